// round 1
// baseline (speedup 1.0000x reference)
#include <cuda_runtime.h>

#define BN_  2
#define HH   64
#define WW   64
#define CC   128
#define HP   66
#define AREA 4356          // HP*HP
#define LL   4096          // HH*WW
#define TCOLS 4224         // 64*66
#define KS   8             // split-K factor for final GEMM

// ---------------- scratch (static device globals; no allocation) ----------------
__device__ float g_Xp1[BN_ * AREA * CC];              // x1 zero-padded  [b, a, c]
__device__ float g_Xp2[BN_ * AREA * CC];              // x2 zero-padded
__device__ float g_r  [BN_ * AREA];                   // per-pixel sum of squares of x2pad
__device__ float g_nm [BN_ * LL];                     // max(patch L2 norm, 1e-4)
__device__ float g_D  [(size_t)BN_ * AREA * AREA];    // D = Xp2 @ Xp2^T
__device__ float g_S  [(size_t)BN_ * LL * LL];        // scores, later reused for att
__device__ float g_P  [(size_t)BN_ * LL * LL];        // horizontal pool sums
__device__ float g_T  [(size_t)BN_ * LL * TCOLS];     // horizontal diag filter of att
__device__ float g_W2 [(size_t)BN_ * LL * AREA];      // full diag filter of att
__device__ float g_part[BN_ * KS * LL * CC];          // split-K partials

// ---------------- pad x1 and x2 into [b, 66*66, 128] with zero border ----------------
__global__ void k_pad(const float* __restrict__ x1, const float* __restrict__ x2) {
    int idx = blockIdx.x * blockDim.x + threadIdx.x;     // over BN_*AREA*32 float4s
    if (idx >= BN_ * AREA * 32) return;
    int v = idx & 31;
    int a = (idx >> 5) % AREA;
    int b = idx / (AREA * 32);
    int ai = a / HP, aj = a % HP;
    float4 z1 = make_float4(0.f, 0.f, 0.f, 0.f), z2 = z1;
    if (ai >= 1 && ai <= HH && aj >= 1 && aj <= WW) {
        int src = ((b * HH + (ai - 1)) * WW + (aj - 1)) * 32 + v;
        z1 = ((const float4*)x1)[src];
        z2 = ((const float4*)x2)[src];
    }
    ((float4*)g_Xp1)[idx] = z1;
    ((float4*)g_Xp2)[idx] = z2;
}

// ---------------- per-pixel squared norms of x2pad (one warp per pixel) ----------------
__global__ void k_rnorm() {
    int gw = (blockIdx.x * blockDim.x + threadIdx.x) >> 5;
    int lane = threadIdx.x & 31;
    if (gw >= BN_ * AREA) return;
    const float4* p = ((const float4*)g_Xp2) + (size_t)gw * 32;
    float4 v = p[lane];
    float s = v.x * v.x + v.y * v.y + v.z * v.z + v.w * v.w;
    #pragma unroll
    for (int o = 16; o; o >>= 1) s += __shfl_xor_sync(0xffffffffu, s, o);
    if (!lane) g_r[gw] = s;
}

// ---------------- patch norms: nm[l] = max(sqrt(sum of 3x3 r), 1e-4) ----------------
__global__ void k_nm() {
    int idx = blockIdx.x * blockDim.x + threadIdx.x;
    if (idx >= BN_ * LL) return;
    int l = idx & (LL - 1), b = idx / LL;
    int li = l >> 6, lj = l & 63;
    const float* rb = g_r + b * AREA;
    float s = 0.f;
    #pragma unroll
    for (int dy = 0; dy < 3; dy++)
        #pragma unroll
        for (int dx = 0; dx < 3; dx++)
            s += rb[(li + dy) * HP + lj + dx];
    g_nm[idx] = fmaxf(sqrtf(s), 1e-4f);
}

// ---------------- D = Xp2 @ Xp2^T  (M=N=4356, K=128), 128x128 tile SGEMM ----------------
__global__ __launch_bounds__(256) void k_dgemm() {
    int b = blockIdx.z;
    const float* __restrict__ X = g_Xp2 + (size_t)b * AREA * CC;
    float* __restrict__ Dp = g_D + (size_t)b * AREA * AREA;
    __shared__ float As[16][132];
    __shared__ float Bs[16][132];
    int tid = threadIdx.x;
    int m0 = blockIdx.x * 128, n0 = blockIdx.y * 128;
    int tx = tid & 15, ty = tid >> 4;
    float acc[8][8];
    #pragma unroll
    for (int i = 0; i < 8; i++)
        #pragma unroll
        for (int j = 0; j < 8; j++) acc[i][j] = 0.f;

    #pragma unroll
    for (int k0 = 0; k0 < CC; k0 += 16) {
        #pragma unroll
        for (int i = 0; i < 2; i++) {
            int li = tid + i * 256;            // 0..511
            int row = li >> 2, c4 = li & 3;
            float4 va = make_float4(0.f, 0.f, 0.f, 0.f), vb = va;
            if (m0 + row < AREA) va = *(const float4*)&X[(size_t)(m0 + row) * CC + k0 + c4 * 4];
            if (n0 + row < AREA) vb = *(const float4*)&X[(size_t)(n0 + row) * CC + k0 + c4 * 4];
            As[c4 * 4 + 0][row] = va.x; As[c4 * 4 + 1][row] = va.y;
            As[c4 * 4 + 2][row] = va.z; As[c4 * 4 + 3][row] = va.w;
            Bs[c4 * 4 + 0][row] = vb.x; Bs[c4 * 4 + 1][row] = vb.y;
            Bs[c4 * 4 + 2][row] = vb.z; Bs[c4 * 4 + 3][row] = vb.w;
        }
        __syncthreads();
        #pragma unroll
        for (int kk = 0; kk < 16; kk++) {
            float a[8], bv[8];
            #pragma unroll
            for (int i = 0; i < 4; i++) { a[i] = As[kk][ty * 4 + i]; a[4 + i] = As[kk][64 + ty * 4 + i]; }
            #pragma unroll
            for (int j = 0; j < 4; j++) { bv[j] = Bs[kk][tx * 4 + j]; bv[4 + j] = Bs[kk][64 + tx * 4 + j]; }
            #pragma unroll
            for (int i = 0; i < 8; i++)
                #pragma unroll
                for (int j = 0; j < 8; j++) acc[i][j] += a[i] * bv[j];
        }
        __syncthreads();
    }
    #pragma unroll
    for (int i = 0; i < 8; i++) {
        int gm = m0 + ((i < 4) ? (ty * 4 + i) : (64 + ty * 4 + i - 4));
        if (gm >= AREA) continue;
        #pragma unroll
        for (int jh = 0; jh < 2; jh++) {
            int gn = n0 + ((jh == 0) ? (tx * 4) : (64 + tx * 4));
            if (gn >= AREA) continue;   // AREA % 4 == 0 so float4 all-or-none
            float4 v = make_float4(acc[i][jh * 4 + 0], acc[i][jh * 4 + 1],
                                   acc[i][jh * 4 + 2], acc[i][jh * 4 + 3]);
            *(float4*)&Dp[(size_t)gm * AREA + gn] = v;
        }
    }
}

// ---------------- scores[x,l] = (sum of 9 diagonal D entries) / nm[l] ----------------
__global__ void k_scores() {
    int b = blockIdx.y;
    int lin = blockIdx.x * blockDim.x + threadIdx.x;   // over LL*LL
    int x = lin >> 12, l = lin & 4095;
    int xp = (x >> 6) * HP + (x & 63);
    int lp = (l >> 6) * HP + (l & 63);
    const float* __restrict__ Db = g_D + (size_t)b * AREA * AREA;
    float s = 0.f;
    #pragma unroll
    for (int dy = 0; dy < 3; dy++)
        #pragma unroll
        for (int dx = 0; dx < 3; dx++) {
            int d = dy * HP + dx;
            s += __ldg(&Db[(size_t)(xp + d) * AREA + lp + d]);
        }
    g_S[(size_t)b * LL * LL + lin] = s / g_nm[b * LL + l];
}

// ---------------- horizontal 3-tap pool over query xj ----------------
__global__ void k_hpool() {
    int b = blockIdx.y;
    size_t base = (size_t)b * LL * LL;
    int lin = blockIdx.x * blockDim.x + threadIdx.x;
    int x = lin >> 12;
    int xj = x & 63;
    float s = g_S[base + lin];
    if (xj > 0)  s += g_S[base + lin - LL];
    if (xj < 63) s += g_S[base + lin + LL];
    g_P[base + lin] = s;
}

// ---------------- vertical pool + TF count-scale + x10 + row softmax → att (into g_S) ----------------
__global__ __launch_bounds__(256) void k_softmax() {
    __shared__ float row[LL];
    __shared__ float red[32];
    int b = blockIdx.y, x = blockIdx.x;
    int xi = x >> 6, xj = x & 63;
    float cy = (xi == 0 || xi == 63) ? 2.f : 3.f;
    float cx = (xj == 0 || xj == 63) ? 2.f : 3.f;
    float sc = 90.f / (cy * cx);                    // (9/cnt) * softmax_scale(10)
    size_t base = (size_t)b * LL * LL;
    const float* P0 = g_P + base + (size_t)x * LL;
    int t = threadIdx.x;
    float lmax = -1e30f;
    for (int l = t; l < LL; l += 256) {
        float s = P0[l];
        if (xi > 0)  s += P0[l - 64 * LL];
        if (xi < 63) s += P0[l + 64 * LL];
        s *= sc;
        row[l] = s;
        lmax = fmaxf(lmax, s);
    }
    #pragma unroll
    for (int o = 16; o; o >>= 1) lmax = fmaxf(lmax, __shfl_xor_sync(0xffffffffu, lmax, o));
    if ((t & 31) == 0) red[t >> 5] = lmax;
    __syncthreads();
    if (t < 32) {
        float v = (t < 8) ? red[t] : -1e30f;
        #pragma unroll
        for (int o = 4; o; o >>= 1) v = fmaxf(v, __shfl_xor_sync(0xffffffffu, v, o));
        if (!t) red[0] = v;
    }
    __syncthreads();
    float m = red[0];
    __syncthreads();
    float lsum = 0.f;
    for (int l = t; l < LL; l += 256) {
        float e = __expf(row[l] - m);
        row[l] = e;
        lsum += e;
    }
    #pragma unroll
    for (int o = 16; o; o >>= 1) lsum += __shfl_xor_sync(0xffffffffu, lsum, o);
    if ((t & 31) == 0) red[t >> 5] = lsum;
    __syncthreads();
    if (t < 32) {
        float v = (t < 8) ? red[t] : 0.f;
        #pragma unroll
        for (int o = 4; o; o >>= 1) v += __shfl_xor_sync(0xffffffffu, v, o);
        if (!t) red[0] = v;
    }
    __syncthreads();
    float inv = 1.f / red[0];
    float* A0 = g_S + base + (size_t)x * LL;       // att overwrites scores buffer
    for (int l = t; l < LL; l += 256) A0[l] = row[l] * inv;
}

// ---------------- horizontal diagonal filter: att → T [4096 x 4224] ----------------
__global__ void k_T() {
    int b = blockIdx.y;
    int lin = blockIdx.x * blockDim.x + threadIdx.x;
    if (lin >= LL * TCOLS) return;
    int x = lin / TCOLS, col = lin % TCOLS;
    int w = x & 63;
    int ai = col / HP, ajp = col % HP;
    const float* __restrict__ att = g_S + (size_t)b * LL * LL;
    int lc = ai * 64 + ajp;
    float s = 0.f;
    if (w < 63 && ajp < 64)    s += att[(size_t)(x + 1) * LL + lc];       // dx=0
    if (ajp >= 1 && ajp <= 64) s += att[(size_t)x * LL + lc - 1];         // dx=1
    if (w >= 1 && ajp >= 2)    s += att[(size_t)(x - 1) * LL + lc - 2];   // dx=2
    g_T[(size_t)b * LL * TCOLS + lin] = s;
}

// ---------------- vertical diagonal filter: T → W2 [4096 x 4356] ----------------
__global__ void k_W2() {
    int b = blockIdx.y;
    int lin = blockIdx.x * blockDim.x + threadIdx.x;
    if (lin >= LL * AREA) return;
    int x = lin / AREA, col = lin % AREA;
    int h = x >> 6;
    int aip = col / HP, ajp = col % HP;
    const float* __restrict__ T = g_T + (size_t)b * LL * TCOLS;
    float s = 0.f;
    if (h < 63 && aip < 64)    s += T[(size_t)(x + 64) * TCOLS + aip * HP + ajp];       // dy=0
    if (aip >= 1 && aip <= 64) s += T[(size_t)x * TCOLS + (aip - 1) * HP + ajp];        // dy=1
    if (h >= 1 && aip >= 2)    s += T[(size_t)(x - 64) * TCOLS + (aip - 2) * HP + ajp]; // dy=2
    g_W2[(size_t)b * LL * AREA + lin] = s;
}

// ---------------- y = W2 @ Xp1   (M=4096, K=4356, N=128), split-K ----------------
#define G3_BM 64
#define G3_BK 16
#define KSPAN 545   // ceil(4356/8)
__global__ __launch_bounds__(256) void k_gemm3() {
    int b = blockIdx.z;
    int ks = blockIdx.y;
    int m0 = blockIdx.x * G3_BM;
    const float* __restrict__ Wm = g_W2 + (size_t)b * LL * AREA;
    const float* __restrict__ V  = g_Xp1 + (size_t)b * AREA * CC;
    int kbeg = ks * KSPAN;
    int kend = kbeg + KSPAN; if (kend > AREA) kend = AREA;
    __shared__ float As[G3_BK][G3_BM + 4];
    __shared__ float Bs[G3_BK][CC];
    int tid = threadIdx.x;
    int tx = tid & 15;   // 16 col groups of 8
    int ty = tid >> 4;   // 16 row groups of 4
    float acc[4][8];
    #pragma unroll
    for (int i = 0; i < 4; i++)
        #pragma unroll
        for (int j = 0; j < 8; j++) acc[i][j] = 0.f;

    for (int k0 = kbeg; k0 < kend; k0 += G3_BK) {
        int klen = kend - k0; if (klen > G3_BK) klen = G3_BK;
        #pragma unroll
        for (int i = 0; i < 4; i++) {
            int li = tid + i * 256;           // 0..1023
            int r = li >> 4, c = li & 15;
            float v = 0.f;
            if (c < klen) v = Wm[(size_t)(m0 + r) * AREA + k0 + c];
            As[c][r] = v;
        }
        #pragma unroll
        for (int i = 0; i < 2; i++) {
            int li = tid + i * 256;           // 0..511
            int r = li >> 5, c4 = li & 31;
            float4 v = make_float4(0.f, 0.f, 0.f, 0.f);
            if (r < klen) v = *(const float4*)&V[(size_t)(k0 + r) * CC + c4 * 4];
            *(float4*)&Bs[r][c4 * 4] = v;
        }
        __syncthreads();
        #pragma unroll
        for (int kk = 0; kk < G3_BK; kk++) {
            float a[4], bv[8];
            #pragma unroll
            for (int i = 0; i < 4; i++) a[i] = As[kk][ty * 4 + i];
            #pragma unroll
            for (int j = 0; j < 8; j++) bv[j] = Bs[kk][tx * 8 + j];
            #pragma unroll
            for (int i = 0; i < 4; i++)
                #pragma unroll
                for (int j = 0; j < 8; j++) acc[i][j] += a[i] * bv[j];
        }
        __syncthreads();
    }
    #pragma unroll
    for (int i = 0; i < 4; i++) {
        float* outp = g_part + ((size_t)(b * KS + ks) * LL + m0 + ty * 4 + i) * CC + tx * 8;
        *(float4*)outp       = make_float4(acc[i][0], acc[i][1], acc[i][2], acc[i][3]);
        *(float4*)(outp + 4) = make_float4(acc[i][4], acc[i][5], acc[i][6], acc[i][7]);
    }
}

// ---------------- reduce split-K partials → output ----------------
__global__ void k_reduce(float* __restrict__ out) {
    int idx = blockIdx.x * blockDim.x + threadIdx.x;
    if (idx >= BN_ * LL * CC) return;
    int b = idx / (LL * CC);
    int mc = idx % (LL * CC);
    float s = 0.f;
    #pragma unroll
    for (int ks = 0; ks < KS; ks++)
        s += g_part[(size_t)(b * KS + ks) * LL * CC + mc];
    out[idx] = s;
}

// ---------------- launcher ----------------
extern "C" void kernel_launch(void* const* d_in, const int* in_sizes, int n_in,
                              void* d_out, int out_size) {
    const float* x1 = (const float*)d_in[0];
    const float* x2 = (const float*)d_in[1];
    float* out = (float*)d_out;

    k_pad  <<<(BN_ * AREA * 32 + 255) / 256, 256>>>(x1, x2);
    k_rnorm<<<(BN_ * AREA * 32 + 255) / 256, 256>>>();
    k_nm   <<<(BN_ * LL + 255) / 256, 256>>>();

    dim3 gd((AREA + 127) / 128, (AREA + 127) / 128, BN_);
    k_dgemm<<<gd, 256>>>();

    dim3 gs((LL * LL) / 256, BN_);
    k_scores<<<gs, 256>>>();
    k_hpool <<<gs, 256>>>();

    dim3 gsm(LL, BN_);
    k_softmax<<<gsm, 256>>>();

    dim3 gt((LL * TCOLS) / 256, BN_);
    k_T<<<gt, 256>>>();

    dim3 gw((LL * AREA) / 256, BN_);
    k_W2<<<gw, 256>>>();

    dim3 gg(LL / G3_BM, KS, BN_);
    k_gemm3<<<gg, 256>>>();

    k_reduce<<<(BN_ * LL * CC + 255) / 256, 256>>>(out);
}

// round 2
// speedup vs baseline: 1.3390x; 1.3390x over previous
#include <cuda_runtime.h>

#define BN_  2
#define HH   64
#define WW   64
#define CC   128
#define HP   66
#define AREA 4356          // HP*HP
#define LL   4096          // HH*WW
#define NBLK 35            // ceil(AREA/128)
#define KS   8             // split-K factor for final GEMM

// ---------------- scratch (static device globals; no allocation) ----------------
__device__ float g_Xp1[BN_ * AREA * CC];              // x1 zero-padded  [b, a, c]
__device__ float g_Xp2[BN_ * AREA * CC];              // x2 zero-padded
__device__ float g_r  [BN_ * AREA];                   // per-pixel sum of squares of x2pad
__device__ float g_nm [BN_ * LL];                     // max(patch L2 norm, 1e-4)
__device__ float g_D  [(size_t)BN_ * AREA * AREA];    // D = Xp2 @ Xp2^T
__device__ float g_S  [(size_t)BN_ * LL * LL];        // raw scores
__device__ float g_A  [(size_t)BN_ * LL * LL];        // att (softmax output)
__device__ float g_W2 [(size_t)BN_ * LL * AREA];      // diag-filtered att
__device__ float g_part[BN_ * KS * LL * CC];          // split-K partials

// ---------------- pad x1 and x2 into [b, 66*66, 128] with zero border ----------------
__global__ void k_pad(const float* __restrict__ x1, const float* __restrict__ x2) {
    int idx = blockIdx.x * blockDim.x + threadIdx.x;     // over BN_*AREA*32 float4s
    if (idx >= BN_ * AREA * 32) return;
    int v = idx & 31;
    int a = (idx >> 5) % AREA;
    int b = idx / (AREA * 32);
    int ai = a / HP, aj = a % HP;
    float4 z1 = make_float4(0.f, 0.f, 0.f, 0.f), z2 = z1;
    if (ai >= 1 && ai <= HH && aj >= 1 && aj <= WW) {
        int src = ((b * HH + (ai - 1)) * WW + (aj - 1)) * 32 + v;
        z1 = ((const float4*)x1)[src];
        z2 = ((const float4*)x2)[src];
    }
    ((float4*)g_Xp1)[idx] = z1;
    ((float4*)g_Xp2)[idx] = z2;
}

// ---------------- per-pixel squared norms of x2pad (one warp per pixel) ----------------
__global__ void k_rnorm() {
    int gw = (blockIdx.x * blockDim.x + threadIdx.x) >> 5;
    int lane = threadIdx.x & 31;
    if (gw >= BN_ * AREA) return;
    const float4* p = ((const float4*)g_Xp2) + (size_t)gw * 32;
    float4 v = p[lane];
    float s = v.x * v.x + v.y * v.y + v.z * v.z + v.w * v.w;
    #pragma unroll
    for (int o = 16; o; o >>= 1) s += __shfl_xor_sync(0xffffffffu, s, o);
    if (!lane) g_r[gw] = s;
}

// ---------------- patch norms: nm[l] = max(sqrt(sum of 3x3 r), 1e-4) ----------------
__global__ void k_nm() {
    int idx = blockIdx.x * blockDim.x + threadIdx.x;
    if (idx >= BN_ * LL) return;
    int l = idx & (LL - 1), b = idx / LL;
    int li = l >> 6, lj = l & 63;
    const float* rb = g_r + b * AREA;
    float s = 0.f;
    #pragma unroll
    for (int dy = 0; dy < 3; dy++)
        #pragma unroll
        for (int dx = 0; dx < 3; dx++)
            s += rb[(li + dy) * HP + lj + dx];
    g_nm[idx] = fmaxf(sqrtf(s), 1e-4f);
}

// ---------------- D = Xp2 @ Xp2^T, symmetric: upper-triangle blocks only ----------------
__global__ __launch_bounds__(256, 2) void k_dgemm() {
    // decode triangular block index -> (bm, bn), bm <= bn
    int rem = blockIdx.x;
    int bm = 0;
    while (rem >= NBLK - bm) { rem -= NBLK - bm; bm++; }
    int bn = bm + rem;
    int b = blockIdx.z;

    const float* __restrict__ X = g_Xp2 + (size_t)b * AREA * CC;
    float* __restrict__ Dp = g_D + (size_t)b * AREA * AREA;

    __shared__ float sm[128 * 129];                 // 66 KB; reused for transpose
    float (*As)[132] = (float(*)[132])sm;           // 16*132 = 2112 floats
    float (*Bs)[132] = (float(*)[132])(sm + 2112);  // 16*132 = 2112 floats

    int tid = threadIdx.x;
    int m0 = bm * 128, n0 = bn * 128;
    int tx = tid & 15, ty = tid >> 4;
    float acc[8][8];
    #pragma unroll
    for (int i = 0; i < 8; i++)
        #pragma unroll
        for (int j = 0; j < 8; j++) acc[i][j] = 0.f;

    #pragma unroll 1
    for (int k0 = 0; k0 < CC; k0 += 16) {
        #pragma unroll
        for (int i = 0; i < 2; i++) {
            int li = tid + i * 256;            // 0..511
            int row = li >> 2, c4 = li & 3;
            float4 va = make_float4(0.f, 0.f, 0.f, 0.f), vb = va;
            if (m0 + row < AREA) va = *(const float4*)&X[(size_t)(m0 + row) * CC + k0 + c4 * 4];
            if (n0 + row < AREA) vb = *(const float4*)&X[(size_t)(n0 + row) * CC + k0 + c4 * 4];
            As[c4 * 4 + 0][row] = va.x; As[c4 * 4 + 1][row] = va.y;
            As[c4 * 4 + 2][row] = va.z; As[c4 * 4 + 3][row] = va.w;
            Bs[c4 * 4 + 0][row] = vb.x; Bs[c4 * 4 + 1][row] = vb.y;
            Bs[c4 * 4 + 2][row] = vb.z; Bs[c4 * 4 + 3][row] = vb.w;
        }
        __syncthreads();
        #pragma unroll
        for (int kk = 0; kk < 16; kk++) {
            float a[8], bv[8];
            #pragma unroll
            for (int i = 0; i < 4; i++) { a[i] = As[kk][ty * 4 + i]; a[4 + i] = As[kk][64 + ty * 4 + i]; }
            #pragma unroll
            for (int j = 0; j < 4; j++) { bv[j] = Bs[kk][tx * 4 + j]; bv[4 + j] = Bs[kk][64 + tx * 4 + j]; }
            #pragma unroll
            for (int i = 0; i < 8; i++)
                #pragma unroll
                for (int j = 0; j < 8; j++) acc[i][j] += a[i] * bv[j];
        }
        __syncthreads();
    }

    // normal (coalesced) store to (m0, n0)
    #pragma unroll
    for (int i = 0; i < 8; i++) {
        int ml = (i < 4) ? (ty * 4 + i) : (64 + ty * 4 + i - 4);
        int gm = m0 + ml;
        if (gm < AREA) {
            #pragma unroll
            for (int jh = 0; jh < 2; jh++) {
                int gn = n0 + ((jh == 0) ? (tx * 4) : (64 + tx * 4));
                if (gn < AREA) {
                    float4 v = make_float4(acc[i][jh * 4 + 0], acc[i][jh * 4 + 1],
                                           acc[i][jh * 4 + 2], acc[i][jh * 4 + 3]);
                    *(float4*)&Dp[(size_t)gm * AREA + gn] = v;
                }
            }
        }
    }

    if (bm == bn) return;

    // transposed store to (n0, m0) via smem staging
    __syncthreads();   // As/Bs dead now
    #pragma unroll
    for (int i = 0; i < 8; i++) {
        int ml = (i < 4) ? (ty * 4 + i) : (64 + ty * 4 + i - 4);
        #pragma unroll
        for (int j = 0; j < 8; j++) {
            int nl = (j < 4) ? (tx * 4 + j) : (64 + tx * 4 + j - 4);
            sm[nl * 129 + ml] = acc[i][j];
        }
    }
    __syncthreads();
    #pragma unroll
    for (int q = 0; q < 16; q++) {
        int pos = q * 256 + tid;          // 0..4095 float4 slots
        int r = pos >> 5, c4 = pos & 31;
        int gn = n0 + r, gm = m0 + c4 * 4;
        if (gn < AREA && gm < AREA) {
            float4 v = make_float4(sm[r * 129 + c4 * 4 + 0], sm[r * 129 + c4 * 4 + 1],
                                   sm[r * 129 + c4 * 4 + 2], sm[r * 129 + c4 * 4 + 3]);
            *(float4*)&Dp[(size_t)gn * AREA + gm] = v;
        }
    }
}

// ---------------- scores[x,l] = (sum of 9 diagonal D entries) / nm[l] ----------------
__global__ void k_scores() {
    int b = blockIdx.y;
    int lin = blockIdx.x * blockDim.x + threadIdx.x;   // over LL*LL
    int x = lin >> 12, l = lin & 4095;
    int xp = (x >> 6) * HP + (x & 63);
    int lp = (l >> 6) * HP + (l & 63);
    const float* __restrict__ Db = g_D + (size_t)b * AREA * AREA;
    float s = 0.f;
    #pragma unroll
    for (int dy = 0; dy < 3; dy++)
        #pragma unroll
        for (int dx = 0; dx < 3; dx++) {
            int d = dy * HP + dx;
            s += __ldg(&Db[(size_t)(xp + d) * AREA + lp + d]);
        }
    g_S[(size_t)b * LL * LL + lin] = s / g_nm[b * LL + l];
}

// ---------------- 3x3 query pool (9 direct row reads) + scale + row softmax → g_A ----------------
__global__ __launch_bounds__(256) void k_softmax() {
    __shared__ float row[LL];
    __shared__ float red[32];
    int b = blockIdx.y, x = blockIdx.x;
    int xi = x >> 6, xj = x & 63;
    float cy = (xi == 0 || xi == 63) ? 2.f : 3.f;
    float cx = (xj == 0 || xj == 63) ? 2.f : 3.f;
    float sc = 90.f / (cy * cx);                    // (9/cnt) * softmax_scale(10)
    size_t base = (size_t)b * LL * LL;
    const float* __restrict__ S0 = g_S + base;
    int t = threadIdx.x;

    // which of the 9 neighbor rows exist
    int offs[9]; int no = 0;
    #pragma unroll
    for (int dy = -1; dy <= 1; dy++)
        #pragma unroll
        for (int dx = -1; dx <= 1; dx++) {
            if (xi + dy >= 0 && xi + dy < HH && xj + dx >= 0 && xj + dx < WW)
                offs[no++] = (x + dy * 64 + dx) * LL;
        }

    float lmax = -1e30f;
    for (int l = t; l < LL; l += 256) {
        float s = 0.f;
        for (int o = 0; o < no; o++) s += __ldg(&S0[offs[o] + l]);
        s *= sc;
        row[l] = s;
        lmax = fmaxf(lmax, s);
    }
    #pragma unroll
    for (int o = 16; o; o >>= 1) lmax = fmaxf(lmax, __shfl_xor_sync(0xffffffffu, lmax, o));
    if ((t & 31) == 0) red[t >> 5] = lmax;
    __syncthreads();
    if (t < 32) {
        float v = (t < 8) ? red[t] : -1e30f;
        #pragma unroll
        for (int o = 4; o; o >>= 1) v = fmaxf(v, __shfl_xor_sync(0xffffffffu, v, o));
        if (!t) red[0] = v;
    }
    __syncthreads();
    float m = red[0];
    __syncthreads();
    float lsum = 0.f;
    for (int l = t; l < LL; l += 256) {
        float e = __expf(row[l] - m);
        row[l] = e;
        lsum += e;
    }
    #pragma unroll
    for (int o = 16; o; o >>= 1) lsum += __shfl_xor_sync(0xffffffffu, lsum, o);
    if ((t & 31) == 0) red[t >> 5] = lsum;
    __syncthreads();
    if (t < 32) {
        float v = (t < 8) ? red[t] : 0.f;
        #pragma unroll
        for (int o = 4; o; o >>= 1) v += __shfl_xor_sync(0xffffffffu, v, o);
        if (!t) red[0] = v;
    }
    __syncthreads();
    float inv = 1.f / red[0];
    float* A0 = g_A + base + (size_t)x * LL;
    for (int l = t; l < LL; l += 256) A0[l] = row[l] * inv;
}

// ---------------- fused 9-tap diagonal filter: att → W2 [4096 x 4356] ----------------
__global__ void k_W2f() {
    int b = blockIdx.y;
    int lin = blockIdx.x * blockDim.x + threadIdx.x;
    if (lin >= LL * AREA) return;
    int x = lin / AREA, col = lin % AREA;
    int h = x >> 6, w = x & 63;
    int aip = col / HP, ajp = col % HP;
    const float* __restrict__ att = g_A + (size_t)b * LL * LL;

    // vert cond per dy, horz cond per dx (independent)
    bool vy[3] = { (h < 63) && (aip < 64),
                   (aip >= 1) && (aip <= 64),
                   (h >= 1) && (aip >= 2) };
    bool vx[3] = { (w < 63) && (ajp < 64),
                   (ajp >= 1) && (ajp <= 64),
                   (w >= 1) && (ajp >= 2) };
    float s = 0.f;
    #pragma unroll
    for (int dy = 0; dy < 3; dy++) {
        if (!vy[dy]) continue;
        int ai = aip - dy;
        int xr = x + (1 - dy) * 64;
        #pragma unroll
        for (int dx = 0; dx < 3; dx++) {
            if (!vx[dx]) continue;
            s += __ldg(&att[(size_t)(xr + 1 - dx) * LL + ai * 64 + ajp - dx]);
        }
    }
    g_W2[(size_t)b * LL * AREA + lin] = s;
}

// ---------------- y = W2 @ Xp1   (M=4096, K=4356, N=128), split-K ----------------
#define G3_BM 64
#define G3_BK 16
#define KSPAN 545   // ceil(4356/8)
__global__ __launch_bounds__(256) void k_gemm3() {
    int b = blockIdx.z;
    int ks = blockIdx.y;
    int m0 = blockIdx.x * G3_BM;
    const float* __restrict__ Wm = g_W2 + (size_t)b * LL * AREA;
    const float* __restrict__ V  = g_Xp1 + (size_t)b * AREA * CC;
    int kbeg = ks * KSPAN;
    int kend = kbeg + KSPAN; if (kend > AREA) kend = AREA;
    __shared__ float As[G3_BK][G3_BM + 4];
    __shared__ float Bs[G3_BK][CC];
    int tid = threadIdx.x;
    int tx = tid & 15;   // 16 col groups of 8
    int ty = tid >> 4;   // 16 row groups of 4
    float acc[4][8];
    #pragma unroll
    for (int i = 0; i < 4; i++)
        #pragma unroll
        for (int j = 0; j < 8; j++) acc[i][j] = 0.f;

    for (int k0 = kbeg; k0 < kend; k0 += G3_BK) {
        int klen = kend - k0; if (klen > G3_BK) klen = G3_BK;
        #pragma unroll
        for (int i = 0; i < 4; i++) {
            int li = tid + i * 256;           // 0..1023
            int r = li >> 4, c = li & 15;
            float v = 0.f;
            if (c < klen) v = Wm[(size_t)(m0 + r) * AREA + k0 + c];
            As[c][r] = v;
        }
        #pragma unroll
        for (int i = 0; i < 2; i++) {
            int li = tid + i * 256;           // 0..511
            int r = li >> 5, c4 = li & 31;
            float4 v = make_float4(0.f, 0.f, 0.f, 0.f);
            if (r < klen) v = *(const float4*)&V[(size_t)(k0 + r) * CC + c4 * 4];
            *(float4*)&Bs[r][c4 * 4] = v;
        }
        __syncthreads();
        #pragma unroll
        for (int kk = 0; kk < G3_BK; kk++) {
            float a[4], bv[8];
            #pragma unroll
            for (int i = 0; i < 4; i++) a[i] = As[kk][ty * 4 + i];
            #pragma unroll
            for (int j = 0; j < 8; j++) bv[j] = Bs[kk][tx * 8 + j];
            #pragma unroll
            for (int i = 0; i < 4; i++)
                #pragma unroll
                for (int j = 0; j < 8; j++) acc[i][j] += a[i] * bv[j];
        }
        __syncthreads();
    }
    #pragma unroll
    for (int i = 0; i < 4; i++) {
        float* outp = g_part + ((size_t)(b * KS + ks) * LL + m0 + ty * 4 + i) * CC + tx * 8;
        *(float4*)outp       = make_float4(acc[i][0], acc[i][1], acc[i][2], acc[i][3]);
        *(float4*)(outp + 4) = make_float4(acc[i][4], acc[i][5], acc[i][6], acc[i][7]);
    }
}

// ---------------- reduce split-K partials → output ----------------
__global__ void k_reduce(float* __restrict__ out) {
    int idx = blockIdx.x * blockDim.x + threadIdx.x;
    if (idx >= BN_ * LL * CC) return;
    int b = idx / (LL * CC);
    int mc = idx % (LL * CC);
    float s = 0.f;
    #pragma unroll
    for (int ks = 0; ks < KS; ks++)
        s += g_part[(size_t)(b * KS + ks) * LL * CC + mc];
    out[idx] = s;
}

// ---------------- launcher ----------------
extern "C" void kernel_launch(void* const* d_in, const int* in_sizes, int n_in,
                              void* d_out, int out_size) {
    const float* x1 = (const float*)d_in[0];
    const float* x2 = (const float*)d_in[1];
    float* out = (float*)d_out;

    k_pad  <<<(BN_ * AREA * 32 + 255) / 256, 256>>>(x1, x2);
    k_rnorm<<<(BN_ * AREA * 32 + 255) / 256, 256>>>();
    k_nm   <<<(BN_ * LL + 255) / 256, 256>>>();

    dim3 gd(NBLK * (NBLK + 1) / 2, 1, BN_);
    k_dgemm<<<gd, 256>>>();

    dim3 gs((LL * LL) / 256, BN_);
    k_scores<<<gs, 256>>>();

    dim3 gsm(LL, BN_);
    k_softmax<<<gsm, 256>>>();

    dim3 gw((LL * AREA + 255) / 256, BN_);
    k_W2f<<<gw, 256>>>();

    dim3 gg(LL / G3_BM, KS, BN_);
    k_gemm3<<<gg, 256>>>();

    k_reduce<<<(BN_ * LL * CC + 255) / 256, 256>>>(out);
}

// round 3
// speedup vs baseline: 1.6658x; 1.2441x over previous
#include <cuda_runtime.h>

#define BN_  2
#define HH   64
#define WW   64
#define CC   128
#define HP   66
#define AREA 4356          // HP*HP
#define LL   4096          // HH*WW
#define NBLK 35            // ceil(AREA/128)
#define G3_KS 4            // split-K factor for final GEMM

// ---------------- scratch (static device globals; no allocation) ----------------
__device__ float g_Xp2[BN_ * AREA * CC];              // x2 zero-padded
__device__ float g_r  [BN_ * AREA];                   // per-pixel sum of squares of x2pad
__device__ float g_nm [BN_ * LL];                     // 1 / max(patch L2 norm, 1e-4)
__device__ float g_D  [(size_t)BN_ * AREA * AREA];    // D = Xp2 @ Xp2^T
__device__ float g_S  [(size_t)BN_ * LL * LL];        // raw scores
__device__ float g_A  [(size_t)BN_ * LL * LL];        // att (softmax output)
__device__ float g_W2 [(size_t)BN_ * LL * LL];        // diag-filtered att (interior cols)
__device__ float g_part[BN_ * G3_KS * LL * CC];       // split-K partials

// ---------------- pad x2 into [b, 66*66, 128] with zero border ----------------
__global__ void k_pad(const float* __restrict__ x2) {
    int idx = blockIdx.x * blockDim.x + threadIdx.x;     // over BN_*AREA*32 float4s
    if (idx >= BN_ * AREA * 32) return;
    int v = idx & 31;
    int a = (idx >> 5) % AREA;
    int b = idx / (AREA * 32);
    int ai = a / HP, aj = a % HP;
    float4 z2 = make_float4(0.f, 0.f, 0.f, 0.f);
    if (ai >= 1 && ai <= HH && aj >= 1 && aj <= WW) {
        int src = ((b * HH + (ai - 1)) * WW + (aj - 1)) * 32 + v;
        z2 = ((const float4*)x2)[src];
    }
    ((float4*)g_Xp2)[idx] = z2;
}

// ---------------- per-pixel squared norms of x2pad (one warp per pixel) ----------------
__global__ void k_rnorm() {
    int gw = (blockIdx.x * blockDim.x + threadIdx.x) >> 5;
    int lane = threadIdx.x & 31;
    if (gw >= BN_ * AREA) return;
    const float4* p = ((const float4*)g_Xp2) + (size_t)gw * 32;
    float4 v = p[lane];
    float s = v.x * v.x + v.y * v.y + v.z * v.z + v.w * v.w;
    #pragma unroll
    for (int o = 16; o; o >>= 1) s += __shfl_xor_sync(0xffffffffu, s, o);
    if (!lane) g_r[gw] = s;
}

// ---------------- patch norms: nm[l] = 1/max(sqrt(sum of 3x3 r), 1e-4) ----------------
__global__ void k_nm() {
    int idx = blockIdx.x * blockDim.x + threadIdx.x;
    if (idx >= BN_ * LL) return;
    int l = idx & (LL - 1), b = idx / LL;
    int li = l >> 6, lj = l & 63;
    const float* rb = g_r + b * AREA;
    float s = 0.f;
    #pragma unroll
    for (int dy = 0; dy < 3; dy++)
        #pragma unroll
        for (int dx = 0; dx < 3; dx++)
            s += rb[(li + dy) * HP + lj + dx];
    g_nm[idx] = 1.f / fmaxf(sqrtf(s), 1e-4f);
}

// ---------------- D = Xp2 @ Xp2^T, symmetric: upper-triangle blocks only ----------------
__global__ __launch_bounds__(256, 2) void k_dgemm() {
    int rem = blockIdx.x;
    int bm = 0;
    while (rem >= NBLK - bm) { rem -= NBLK - bm; bm++; }
    int bn = bm + rem;
    int b = blockIdx.z;

    const float* __restrict__ X = g_Xp2 + (size_t)b * AREA * CC;
    float* __restrict__ Dp = g_D + (size_t)b * AREA * AREA;

    __shared__ float sm[128 * 129];                 // reused for transpose
    float (*As)[132] = (float(*)[132])sm;
    float (*Bs)[132] = (float(*)[132])(sm + 2112);

    int tid = threadIdx.x;
    int m0 = bm * 128, n0 = bn * 128;
    int tx = tid & 15, ty = tid >> 4;
    float acc[8][8];
    #pragma unroll
    for (int i = 0; i < 8; i++)
        #pragma unroll
        for (int j = 0; j < 8; j++) acc[i][j] = 0.f;

    #pragma unroll 1
    for (int k0 = 0; k0 < CC; k0 += 16) {
        #pragma unroll
        for (int i = 0; i < 2; i++) {
            int li = tid + i * 256;
            int row = li >> 2, c4 = li & 3;
            float4 va = make_float4(0.f, 0.f, 0.f, 0.f), vb = va;
            if (m0 + row < AREA) va = *(const float4*)&X[(size_t)(m0 + row) * CC + k0 + c4 * 4];
            if (n0 + row < AREA) vb = *(const float4*)&X[(size_t)(n0 + row) * CC + k0 + c4 * 4];
            As[c4 * 4 + 0][row] = va.x; As[c4 * 4 + 1][row] = va.y;
            As[c4 * 4 + 2][row] = va.z; As[c4 * 4 + 3][row] = va.w;
            Bs[c4 * 4 + 0][row] = vb.x; Bs[c4 * 4 + 1][row] = vb.y;
            Bs[c4 * 4 + 2][row] = vb.z; Bs[c4 * 4 + 3][row] = vb.w;
        }
        __syncthreads();
        #pragma unroll
        for (int kk = 0; kk < 16; kk++) {
            float a[8], bv[8];
            #pragma unroll
            for (int i = 0; i < 4; i++) { a[i] = As[kk][ty * 4 + i]; a[4 + i] = As[kk][64 + ty * 4 + i]; }
            #pragma unroll
            for (int j = 0; j < 4; j++) { bv[j] = Bs[kk][tx * 4 + j]; bv[4 + j] = Bs[kk][64 + tx * 4 + j]; }
            #pragma unroll
            for (int i = 0; i < 8; i++)
                #pragma unroll
                for (int j = 0; j < 8; j++) acc[i][j] += a[i] * bv[j];
        }
        __syncthreads();
    }

    #pragma unroll
    for (int i = 0; i < 8; i++) {
        int ml = (i < 4) ? (ty * 4 + i) : (64 + ty * 4 + i - 4);
        int gm = m0 + ml;
        if (gm < AREA) {
            #pragma unroll
            for (int jh = 0; jh < 2; jh++) {
                int gn = n0 + ((jh == 0) ? (tx * 4) : (64 + tx * 4));
                if (gn < AREA) {
                    float4 v = make_float4(acc[i][jh * 4 + 0], acc[i][jh * 4 + 1],
                                           acc[i][jh * 4 + 2], acc[i][jh * 4 + 3]);
                    *(float4*)&Dp[(size_t)gm * AREA + gn] = v;
                }
            }
        }
    }

    if (bm == bn) return;

    __syncthreads();
    #pragma unroll
    for (int i = 0; i < 8; i++) {
        int ml = (i < 4) ? (ty * 4 + i) : (64 + ty * 4 + i - 4);
        #pragma unroll
        for (int j = 0; j < 8; j++) {
            int nl = (j < 4) ? (tx * 4 + j) : (64 + tx * 4 + j - 4);
            sm[nl * 129 + ml] = acc[i][j];
        }
    }
    __syncthreads();
    #pragma unroll
    for (int q = 0; q < 16; q++) {
        int pos = q * 256 + tid;
        int r = pos >> 5, c4 = pos & 31;
        int gn = n0 + r, gm = m0 + c4 * 4;
        if (gn < AREA && gm < AREA) {
            float4 v = make_float4(sm[r * 129 + c4 * 4 + 0], sm[r * 129 + c4 * 4 + 1],
                                   sm[r * 129 + c4 * 4 + 2], sm[r * 129 + c4 * 4 + 3]);
            *(float4*)&Dp[(size_t)gn * AREA + gm] = v;
        }
    }
}

// ---------------- scores[x,l] = (sum of 9 diagonal D entries) * invnm[l] ----------------
__global__ void k_scores() {
    int b = blockIdx.y;
    int lin = blockIdx.x * blockDim.x + threadIdx.x;   // over LL*LL
    int x = lin >> 12, l = lin & 4095;
    int xp = (x >> 6) * HP + (x & 63);
    int lp = (l >> 6) * HP + (l & 63);
    const float* __restrict__ Db = g_D + (size_t)b * AREA * AREA;
    float s = 0.f;
    #pragma unroll
    for (int dy = 0; dy < 3; dy++)
        #pragma unroll
        for (int dx = 0; dx < 3; dx++) {
            int d = dy * HP + dx;
            s += __ldg(&Db[(size_t)(xp + d) * AREA + lp + d]);
        }
    g_S[(size_t)b * LL * LL + lin] = s * g_nm[b * LL + l];
}

// ---------------- 3x3 query pool (9 direct row reads) + scale + row softmax → g_A ----------------
__global__ __launch_bounds__(256) void k_softmax() {
    __shared__ float row[LL];
    __shared__ float red[32];
    int b = blockIdx.y, x = blockIdx.x;
    int xi = x >> 6, xj = x & 63;
    float cy = (xi == 0 || xi == 63) ? 2.f : 3.f;
    float cx = (xj == 0 || xj == 63) ? 2.f : 3.f;
    float sc = 90.f / (cy * cx);                    // (9/cnt) * softmax_scale(10)
    size_t base = (size_t)b * LL * LL;
    const float* __restrict__ S0 = g_S + base;
    int t = threadIdx.x;

    int offs[9]; int no = 0;
    #pragma unroll
    for (int dy = -1; dy <= 1; dy++)
        #pragma unroll
        for (int dx = -1; dx <= 1; dx++) {
            if (xi + dy >= 0 && xi + dy < HH && xj + dx >= 0 && xj + dx < WW)
                offs[no++] = (x + dy * 64 + dx) * LL;
        }

    float lmax = -1e30f;
    for (int l = t; l < LL; l += 256) {
        float s = 0.f;
        for (int o = 0; o < no; o++) s += __ldg(&S0[offs[o] + l]);
        s *= sc;
        row[l] = s;
        lmax = fmaxf(lmax, s);
    }
    #pragma unroll
    for (int o = 16; o; o >>= 1) lmax = fmaxf(lmax, __shfl_xor_sync(0xffffffffu, lmax, o));
    if ((t & 31) == 0) red[t >> 5] = lmax;
    __syncthreads();
    if (t < 32) {
        float v = (t < 8) ? red[t] : -1e30f;
        #pragma unroll
        for (int o = 4; o; o >>= 1) v = fmaxf(v, __shfl_xor_sync(0xffffffffu, v, o));
        if (!t) red[0] = v;
    }
    __syncthreads();
    float m = red[0];
    __syncthreads();
    float lsum = 0.f;
    for (int l = t; l < LL; l += 256) {
        float e = __expf(row[l] - m);
        row[l] = e;
        lsum += e;
    }
    #pragma unroll
    for (int o = 16; o; o >>= 1) lsum += __shfl_xor_sync(0xffffffffu, lsum, o);
    if ((t & 31) == 0) red[t >> 5] = lsum;
    __syncthreads();
    if (t < 32) {
        float v = (t < 8) ? red[t] : 0.f;
        #pragma unroll
        for (int o = 4; o; o >>= 1) v += __shfl_xor_sync(0xffffffffu, v, o);
        if (!t) red[0] = v;
    }
    __syncthreads();
    float inv = 1.f / red[0];
    float* A0 = g_A + base + (size_t)x * LL;
    for (int l = t; l < LL; l += 256) A0[l] = row[l] * inv;
}

// ---------------- diagonal 3x3 box filter: W2c[x,l] = sum_u att[x+u, l+u] ----------------
__global__ void k_W2f() {
    int b = blockIdx.y;
    int lin = blockIdx.x * blockDim.x + threadIdx.x;   // over LL*LL
    int x = lin >> 12, l = lin & 4095;
    int h = x >> 6, w = x & 63;
    int li = l >> 6, lj = l & 63;
    const float* __restrict__ att = g_A + (size_t)b * LL * LL;
    float s = 0.f;
    #pragma unroll
    for (int sy = 1; sy >= -1; sy--) {
        if ((unsigned)(h + sy) >= 64u || (unsigned)(li + sy) >= 64u) continue;
        #pragma unroll
        for (int sx = 1; sx >= -1; sx--) {
            if ((unsigned)(w + sx) >= 64u || (unsigned)(lj + sx) >= 64u) continue;
            long u = sy * 64 + sx;
            s += __ldg(&att[(long)lin + u * (LL + 1)]);
        }
    }
    g_W2[(size_t)b * LL * LL + lin] = s;
}

// ---------------- y = W2c @ x1   (M=4096, K=4096, N=128), split-K, 128x128 tiles ----------------
__global__ __launch_bounds__(256, 2) void k_gemm3(const float* __restrict__ x1) {
    int b = blockIdx.z;
    int ks = blockIdx.y;
    int m0 = blockIdx.x * 128;
    const float* __restrict__ Wm = g_W2 + (size_t)b * LL * LL;
    const float* __restrict__ V  = x1 + (size_t)b * LL * CC;
    int kbeg = ks * (LL / G3_KS);

    __shared__ float As[32][132];
    __shared__ float Bs[32][128];
    int tid = threadIdx.x;
    int tx = tid & 15, ty = tid >> 4;
    float acc[8][8];
    #pragma unroll
    for (int i = 0; i < 8; i++)
        #pragma unroll
        for (int j = 0; j < 8; j++) acc[i][j] = 0.f;

    #pragma unroll 1
    for (int k0 = kbeg; k0 < kbeg + LL / G3_KS; k0 += 32) {
        #pragma unroll
        for (int i = 0; i < 4; i++) {
            int li = i * 256 + tid;           // 0..1023
            int r = li >> 3, c4 = li & 7;     // 128 rows x 8 float4
            float4 v = *(const float4*)&Wm[(size_t)(m0 + r) * LL + k0 + c4 * 4];
            As[c4 * 4 + 0][r] = v.x; As[c4 * 4 + 1][r] = v.y;
            As[c4 * 4 + 2][r] = v.z; As[c4 * 4 + 3][r] = v.w;
        }
        #pragma unroll
        for (int i = 0; i < 4; i++) {
            int li = i * 256 + tid;           // 0..1023
            int r = li >> 5, c4 = li & 31;    // 32 rows x 32 float4
            *(float4*)&Bs[r][c4 * 4] = *(const float4*)&V[(size_t)(k0 + r) * CC + c4 * 4];
        }
        __syncthreads();
        #pragma unroll
        for (int kk = 0; kk < 32; kk++) {
            float a[8], bv[8];
            #pragma unroll
            for (int i = 0; i < 4; i++) { a[i] = As[kk][ty * 4 + i]; a[4 + i] = As[kk][64 + ty * 4 + i]; }
            #pragma unroll
            for (int j = 0; j < 4; j++) { bv[j] = Bs[kk][tx * 4 + j]; bv[4 + j] = Bs[kk][64 + tx * 4 + j]; }
            #pragma unroll
            for (int i = 0; i < 8; i++)
                #pragma unroll
                for (int j = 0; j < 8; j++) acc[i][j] += a[i] * bv[j];
        }
        __syncthreads();
    }

    float* Pp = g_part + (size_t)(b * G3_KS + ks) * LL * CC;
    #pragma unroll
    for (int i = 0; i < 8; i++) {
        int ml = (i < 4) ? (ty * 4 + i) : (64 + ty * 4 + i - 4);
        int gm = m0 + ml;
        #pragma unroll
        for (int jh = 0; jh < 2; jh++) {
            int gn = (jh == 0) ? (tx * 4) : (64 + tx * 4);
            float4 v = make_float4(acc[i][jh * 4 + 0], acc[i][jh * 4 + 1],
                                   acc[i][jh * 4 + 2], acc[i][jh * 4 + 3]);
            *(float4*)&Pp[(size_t)gm * CC + gn] = v;
        }
    }
}

// ---------------- reduce split-K partials → output ----------------
__global__ void k_reduce(float* __restrict__ out) {
    int idx = blockIdx.x * blockDim.x + threadIdx.x;
    if (idx >= BN_ * LL * CC) return;
    int b = idx / (LL * CC);
    int mc = idx % (LL * CC);
    float s = 0.f;
    #pragma unroll
    for (int ks = 0; ks < G3_KS; ks++)
        s += g_part[(size_t)(b * G3_KS + ks) * LL * CC + mc];
    out[idx] = s;
}

// ---------------- launcher ----------------
extern "C" void kernel_launch(void* const* d_in, const int* in_sizes, int n_in,
                              void* d_out, int out_size) {
    const float* x1 = (const float*)d_in[0];
    const float* x2 = (const float*)d_in[1];
    float* out = (float*)d_out;

    k_pad  <<<(BN_ * AREA * 32 + 255) / 256, 256>>>(x2);
    k_rnorm<<<(BN_ * AREA * 32 + 255) / 256, 256>>>();
    k_nm   <<<(BN_ * LL + 255) / 256, 256>>>();

    dim3 gd(NBLK * (NBLK + 1) / 2, 1, BN_);
    k_dgemm<<<gd, 256>>>();

    dim3 gs((LL * LL) / 256, BN_);
    k_scores<<<gs, 256>>>();

    dim3 gsm(LL, BN_);
    k_softmax<<<gsm, 256>>>();

    k_W2f<<<gs, 256>>>();

    dim3 gg(LL / 128, G3_KS, BN_);
    k_gemm3<<<gg, 256>>>(x1);

    k_reduce<<<(BN_ * LL * CC + 255) / 256, 256>>>(out);
}

// round 5
// speedup vs baseline: 1.8864x; 1.1324x over previous
#include <cuda_runtime.h>
#include <cuda_bf16.h>
#include <cstdint>

#define BN_  2
#define HH   64
#define WW   64
#define CC   128
#define HP   66
#define AREA 4356          // HP*HP
#define LL   4096          // HH*WW
#define NBLK 35            // ceil(AREA/128)

// ---------------- scratch (static device globals; no allocation) ----------------
__device__ float g_Xp2[BN_ * AREA * CC];              // x2 zero-padded
__device__ float g_r  [BN_ * AREA];                   // per-pixel sum of squares of x2pad
__device__ float g_nm [BN_ * LL];                     // 1 / max(patch L2 norm, 1e-4)
__device__ float g_D  [(size_t)BN_ * AREA * AREA];    // D = Xp2 @ Xp2^T
__device__ float g_S  [(size_t)BN_ * LL * LL];        // raw scores
__device__ float g_A  [(size_t)BN_ * LL * LL];        // att (softmax output)
__device__ __nv_bfloat16 g_W2h[(size_t)BN_ * LL * LL];   // diag-filtered att, hi
__device__ __nv_bfloat16 g_W2l[(size_t)BN_ * LL * LL];   // diag-filtered att, lo
__device__ __nv_bfloat16 g_V1h[BN_ * LL * CC];           // x1 hi  [b][k][c]
__device__ __nv_bfloat16 g_V1l[BN_ * LL * CC];           // x1 lo

// ================= portable PTX helpers (no arch-specific instructions) =================
__device__ __forceinline__ uint32_t smem_u32(const void* p) {
    uint32_t a;
    asm("{ .reg .u64 t; cvta.to.shared.u64 t, %1; cvt.u32.u64 %0, t; }" : "=r"(a) : "l"(p));
    return a;
}

#define LDM_X4(r0, r1, r2, r3, addr) \
    asm volatile("ldmatrix.sync.aligned.m8n8.x4.shared.b16 {%0,%1,%2,%3}, [%4];" \
        : "=r"(r0), "=r"(r1), "=r"(r2), "=r"(r3) : "r"(addr))

#define LDM_X4T(r0, r1, r2, r3, addr) \
    asm volatile("ldmatrix.sync.aligned.m8n8.x4.trans.shared.b16 {%0,%1,%2,%3}, [%4];" \
        : "=r"(r0), "=r"(r1), "=r"(r2), "=r"(r3) : "r"(addr))

#define MMA16816(d, a, b0v, b1v) \
    asm volatile("mma.sync.aligned.m16n8k16.row.col.f32.bf16.bf16.f32 " \
        "{%0,%1,%2,%3}, {%4,%5,%6,%7}, {%8,%9}, {%0,%1,%2,%3};" \
        : "+f"((d)[0]), "+f"((d)[1]), "+f"((d)[2]), "+f"((d)[3]) \
        : "r"((a)[0]), "r"((a)[1]), "r"((a)[2]), "r"((a)[3]), "r"(b0v), "r"(b1v))

// ---------------- pad x2 into [b, 66*66, 128] with zero border ----------------
__global__ void k_pad(const float* __restrict__ x2) {
    int idx = blockIdx.x * blockDim.x + threadIdx.x;
    if (idx >= BN_ * AREA * 32) return;
    int v = idx & 31;
    int a = (idx >> 5) % AREA;
    int b = idx / (AREA * 32);
    int ai = a / HP, aj = a % HP;
    float4 z2 = make_float4(0.f, 0.f, 0.f, 0.f);
    if (ai >= 1 && ai <= HH && aj >= 1 && aj <= WW) {
        int src = ((b * HH + (ai - 1)) * WW + (aj - 1)) * 32 + v;
        z2 = ((const float4*)x2)[src];
    }
    ((float4*)g_Xp2)[idx] = z2;
}

// ---------------- split x1 into bf16 hi/lo (same layout) + zero output ----------------
__global__ void k_split(const float* __restrict__ x1, float* __restrict__ out) {
    int idx = blockIdx.x * blockDim.x + threadIdx.x;
    if (idx >= BN_ * LL * CC) return;
    float v = x1[idx];
    __nv_bfloat16 h = __float2bfloat16(v);
    float lo = v - __bfloat162float(h);
    g_V1h[idx] = h;
    g_V1l[idx] = __float2bfloat16(lo);
    out[idx] = 0.f;
}

// ---------------- per-pixel squared norms of x2pad ----------------
__global__ void k_rnorm() {
    int gw = (blockIdx.x * blockDim.x + threadIdx.x) >> 5;
    int lane = threadIdx.x & 31;
    if (gw >= BN_ * AREA) return;
    const float4* p = ((const float4*)g_Xp2) + (size_t)gw * 32;
    float4 v = p[lane];
    float s = v.x * v.x + v.y * v.y + v.z * v.z + v.w * v.w;
    #pragma unroll
    for (int o = 16; o; o >>= 1) s += __shfl_xor_sync(0xffffffffu, s, o);
    if (!lane) g_r[gw] = s;
}

// ---------------- patch norms ----------------
__global__ void k_nm() {
    int idx = blockIdx.x * blockDim.x + threadIdx.x;
    if (idx >= BN_ * LL) return;
    int l = idx & (LL - 1), b = idx / LL;
    int li = l >> 6, lj = l & 63;
    const float* rb = g_r + b * AREA;
    float s = 0.f;
    #pragma unroll
    for (int dy = 0; dy < 3; dy++)
        #pragma unroll
        for (int dx = 0; dx < 3; dx++)
            s += rb[(li + dy) * HP + lj + dx];
    g_nm[idx] = 1.f / fmaxf(sqrtf(s), 1e-4f);
}

// ---------------- D = Xp2 @ Xp2^T, symmetric ----------------
__global__ __launch_bounds__(256, 2) void k_dgemm() {
    int rem = blockIdx.x;
    int bm = 0;
    while (rem >= NBLK - bm) { rem -= NBLK - bm; bm++; }
    int bn = bm + rem;
    int b = blockIdx.z;

    const float* __restrict__ X = g_Xp2 + (size_t)b * AREA * CC;
    float* __restrict__ Dp = g_D + (size_t)b * AREA * AREA;

    __shared__ float sm[128 * 129];
    float (*As)[132] = (float(*)[132])sm;
    float (*Bs)[132] = (float(*)[132])(sm + 2112);

    int tid = threadIdx.x;
    int m0 = bm * 128, n0 = bn * 128;
    int tx = tid & 15, ty = tid >> 4;
    float acc[8][8];
    #pragma unroll
    for (int i = 0; i < 8; i++)
        #pragma unroll
        for (int j = 0; j < 8; j++) acc[i][j] = 0.f;

    #pragma unroll 1
    for (int k0 = 0; k0 < CC; k0 += 16) {
        #pragma unroll
        for (int i = 0; i < 2; i++) {
            int li = tid + i * 256;
            int row = li >> 2, c4 = li & 3;
            float4 va = make_float4(0.f, 0.f, 0.f, 0.f), vb = va;
            if (m0 + row < AREA) va = *(const float4*)&X[(size_t)(m0 + row) * CC + k0 + c4 * 4];
            if (n0 + row < AREA) vb = *(const float4*)&X[(size_t)(n0 + row) * CC + k0 + c4 * 4];
            As[c4 * 4 + 0][row] = va.x; As[c4 * 4 + 1][row] = va.y;
            As[c4 * 4 + 2][row] = va.z; As[c4 * 4 + 3][row] = va.w;
            Bs[c4 * 4 + 0][row] = vb.x; Bs[c4 * 4 + 1][row] = vb.y;
            Bs[c4 * 4 + 2][row] = vb.z; Bs[c4 * 4 + 3][row] = vb.w;
        }
        __syncthreads();
        #pragma unroll
        for (int kk = 0; kk < 16; kk++) {
            float a[8], bv[8];
            #pragma unroll
            for (int i = 0; i < 4; i++) { a[i] = As[kk][ty * 4 + i]; a[4 + i] = As[kk][64 + ty * 4 + i]; }
            #pragma unroll
            for (int j = 0; j < 4; j++) { bv[j] = Bs[kk][tx * 4 + j]; bv[4 + j] = Bs[kk][64 + tx * 4 + j]; }
            #pragma unroll
            for (int i = 0; i < 8; i++)
                #pragma unroll
                for (int j = 0; j < 8; j++) acc[i][j] += a[i] * bv[j];
        }
        __syncthreads();
    }

    #pragma unroll
    for (int i = 0; i < 8; i++) {
        int ml = (i < 4) ? (ty * 4 + i) : (64 + ty * 4 + i - 4);
        int gm = m0 + ml;
        if (gm < AREA) {
            #pragma unroll
            for (int jh = 0; jh < 2; jh++) {
                int gn = n0 + ((jh == 0) ? (tx * 4) : (64 + tx * 4));
                if (gn < AREA) {
                    float4 v = make_float4(acc[i][jh * 4 + 0], acc[i][jh * 4 + 1],
                                           acc[i][jh * 4 + 2], acc[i][jh * 4 + 3]);
                    *(float4*)&Dp[(size_t)gm * AREA + gn] = v;
                }
            }
        }
    }

    if (bm == bn) return;

    __syncthreads();
    #pragma unroll
    for (int i = 0; i < 8; i++) {
        int ml = (i < 4) ? (ty * 4 + i) : (64 + ty * 4 + i - 4);
        #pragma unroll
        for (int j = 0; j < 8; j++) {
            int nl = (j < 4) ? (tx * 4 + j) : (64 + tx * 4 + j - 4);
            sm[nl * 129 + ml] = acc[i][j];
        }
    }
    __syncthreads();
    #pragma unroll
    for (int q = 0; q < 16; q++) {
        int pos = q * 256 + tid;
        int r = pos >> 5, c4 = pos & 31;
        int gn = n0 + r, gm = m0 + c4 * 4;
        if (gn < AREA && gm < AREA) {
            float4 v = make_float4(sm[r * 129 + c4 * 4 + 0], sm[r * 129 + c4 * 4 + 1],
                                   sm[r * 129 + c4 * 4 + 2], sm[r * 129 + c4 * 4 + 3]);
            *(float4*)&Dp[(size_t)gn * AREA + gm] = v;
        }
    }
}

// ---------------- scores[x,l] = (sum of 9 diagonal D entries) * invnm[l] ----------------
__global__ void k_scores() {
    int b = blockIdx.y;
    int lin = blockIdx.x * blockDim.x + threadIdx.x;
    int x = lin >> 12, l = lin & 4095;
    int xp = (x >> 6) * HP + (x & 63);
    int lp = (l >> 6) * HP + (l & 63);
    const float* __restrict__ Db = g_D + (size_t)b * AREA * AREA;
    float s = 0.f;
    #pragma unroll
    for (int dy = 0; dy < 3; dy++)
        #pragma unroll
        for (int dx = 0; dx < 3; dx++) {
            int d = dy * HP + dx;
            s += __ldg(&Db[(size_t)(xp + d) * AREA + lp + d]);
        }
    g_S[(size_t)b * LL * LL + lin] = s * g_nm[b * LL + l];
}

// ---------------- 3x3 query pool + scale + row softmax → g_A ----------------
__global__ __launch_bounds__(256) void k_softmax() {
    __shared__ float row[LL];
    __shared__ float red[32];
    int b = blockIdx.y, x = blockIdx.x;
    int xi = x >> 6, xj = x & 63;
    float cy = (xi == 0 || xi == 63) ? 2.f : 3.f;
    float cx = (xj == 0 || xj == 63) ? 2.f : 3.f;
    float sc = 90.f / (cy * cx);
    size_t base = (size_t)b * LL * LL;
    const float* __restrict__ S0 = g_S + base;
    int t = threadIdx.x;

    int offs[9]; int no = 0;
    #pragma unroll
    for (int dy = -1; dy <= 1; dy++)
        #pragma unroll
        for (int dx = -1; dx <= 1; dx++) {
            if (xi + dy >= 0 && xi + dy < HH && xj + dx >= 0 && xj + dx < WW)
                offs[no++] = (x + dy * 64 + dx) * LL;
        }

    float lmax = -1e30f;
    for (int l = t; l < LL; l += 256) {
        float s = 0.f;
        for (int o = 0; o < no; o++) s += __ldg(&S0[offs[o] + l]);
        s *= sc;
        row[l] = s;
        lmax = fmaxf(lmax, s);
    }
    #pragma unroll
    for (int o = 16; o; o >>= 1) lmax = fmaxf(lmax, __shfl_xor_sync(0xffffffffu, lmax, o));
    if ((t & 31) == 0) red[t >> 5] = lmax;
    __syncthreads();
    if (t < 32) {
        float v = (t < 8) ? red[t] : -1e30f;
        #pragma unroll
        for (int o = 4; o; o >>= 1) v = fmaxf(v, __shfl_xor_sync(0xffffffffu, v, o));
        if (!t) red[0] = v;
    }
    __syncthreads();
    float m = red[0];
    __syncthreads();
    float lsum = 0.f;
    for (int l = t; l < LL; l += 256) {
        float e = __expf(row[l] - m);
        row[l] = e;
        lsum += e;
    }
    #pragma unroll
    for (int o = 16; o; o >>= 1) lsum += __shfl_xor_sync(0xffffffffu, lsum, o);
    if ((t & 31) == 0) red[t >> 5] = lsum;
    __syncthreads();
    if (t < 32) {
        float v = (t < 8) ? red[t] : 0.f;
        #pragma unroll
        for (int o = 4; o; o >>= 1) v += __shfl_xor_sync(0xffffffffu, v, o);
        if (!t) red[0] = v;
    }
    __syncthreads();
    float inv = 1.f / red[0];
    float* A0 = g_A + base + (size_t)x * LL;
    for (int l = t; l < LL; l += 256) A0[l] = row[l] * inv;
}

// ---------------- diagonal 3x3 box filter → W2 hi/lo bf16 ----------------
__global__ void k_W2f() {
    int b = blockIdx.y;
    int lin = blockIdx.x * blockDim.x + threadIdx.x;
    int x = lin >> 12, l = lin & 4095;
    int h = x >> 6, w = x & 63;
    int li = l >> 6, lj = l & 63;
    const float* __restrict__ att = g_A + (size_t)b * LL * LL;
    float s = 0.f;
    #pragma unroll
    for (int sy = 1; sy >= -1; sy--) {
        if ((unsigned)(h + sy) >= 64u || (unsigned)(li + sy) >= 64u) continue;
        #pragma unroll
        for (int sx = 1; sx >= -1; sx--) {
            if ((unsigned)(w + sx) >= 64u || (unsigned)(lj + sx) >= 64u) continue;
            long u = sy * 64 + sx;
            s += __ldg(&att[(long)lin + u * (LL + 1)]);
        }
    }
    __nv_bfloat16 hi = __float2bfloat16(s);
    float lo = s - __bfloat162float(hi);
    size_t dst = (size_t)b * LL * LL + lin;
    g_W2h[dst] = hi;
    g_W2l[dst] = __float2bfloat16(lo);
}

// ---------------- y = W2 @ x1 via mma.sync bf16x3 (M=128, N=128, split-K=2) ----------------
#define GA_STR 72      // bf16 stride for A tiles in smem
#define GB_STR 136     // bf16 stride for B tiles in smem
#define SM_AH  0
#define SM_AL  (128 * GA_STR)                     // 9216
#define SM_BH  (2 * 128 * GA_STR)                 // 18432
#define SM_BL  (2 * 128 * GA_STR + 64 * GB_STR)   // 27136
#define SM_TOTB ((2 * 128 * GA_STR + 2 * 64 * GB_STR) * 2)   // 71680 bytes

__global__ __launch_bounds__(256, 1) void k_gemm3_mma(float* __restrict__ out) {
    extern __shared__ __nv_bfloat16 sm[];
    int tid = threadIdx.x, lane = tid & 31, wid = tid >> 5;
    int wm = wid >> 2, wn = wid & 3;            // warp grid 2 x 4
    int m0 = blockIdx.x * 128;
    int kbeg = blockIdx.y * (LL / 2);
    int b = blockIdx.z;

    const __nv_bfloat16* __restrict__ Ah = g_W2h + (size_t)b * LL * LL;
    const __nv_bfloat16* __restrict__ Al = g_W2l + (size_t)b * LL * LL;
    const __nv_bfloat16* __restrict__ Bh = g_V1h + (size_t)b * LL * CC;
    const __nv_bfloat16* __restrict__ Bl = g_V1l + (size_t)b * LL * CC;

    uint32_t sb = smem_u32(sm);
    float acc[4][4][4];
    #pragma unroll
    for (int i = 0; i < 4; i++)
        #pragma unroll
        for (int j = 0; j < 4; j++)
            #pragma unroll
            for (int q = 0; q < 4; q++) acc[i][j][q] = 0.f;

    // ldmatrix lane address components (same pattern for A and B-trans)
    int frow = (lane & 7) + ((lane >> 3) & 1) * 8;
    int fcol = ((lane >> 4) & 1) * 8;

    #pragma unroll 1
    for (int ci = 0; ci < 32; ci++) {
        int k0 = kbeg + ci * 64;
        // ---- global -> smem : A tiles 128x64, B tiles 64x128 (hi & lo) ----
        #pragma unroll
        for (int q = 0; q < 4; q++) {
            int e = q * 256 + tid;              // 0..1023
            int r = e >> 3, c = e & 7;
            const size_t so = (size_t)(m0 + r) * LL + k0 + c * 8;
            *(uint4*)(sm + SM_AH + r * GA_STR + c * 8) = *(const uint4*)(Ah + so);
            *(uint4*)(sm + SM_AL + r * GA_STR + c * 8) = *(const uint4*)(Al + so);
        }
        #pragma unroll
        for (int q = 0; q < 4; q++) {
            int e = q * 256 + tid;              // 0..1023
            int r = e >> 4, c = e & 15;
            const size_t so = (size_t)(k0 + r) * CC + c * 8;
            *(uint4*)(sm + SM_BH + r * GB_STR + c * 8) = *(const uint4*)(Bh + so);
            *(uint4*)(sm + SM_BL + r * GB_STR + c * 8) = *(const uint4*)(Bl + so);
        }
        __syncthreads();

        #pragma unroll
        for (int ks = 0; ks < 4; ks++) {
            uint32_t ah[4][4], al[4][4], bh[2][4], bl[2][4];
            #pragma unroll
            for (int tm = 0; tm < 4; tm++) {
                uint32_t off = (wm * 64 + tm * 16 + frow) * GA_STR + ks * 16 + fcol;
                LDM_X4(ah[tm][0], ah[tm][1], ah[tm][2], ah[tm][3], sb + (SM_AH + off) * 2);
                LDM_X4(al[tm][0], al[tm][1], al[tm][2], al[tm][3], sb + (SM_AL + off) * 2);
            }
            #pragma unroll
            for (int p = 0; p < 2; p++) {
                uint32_t off = (ks * 16 + frow) * GB_STR + wn * 32 + p * 16 + fcol;
                LDM_X4T(bh[p][0], bh[p][1], bh[p][2], bh[p][3], sb + (SM_BH + off) * 2);
                LDM_X4T(bl[p][0], bl[p][1], bl[p][2], bl[p][3], sb + (SM_BL + off) * 2);
            }
            #pragma unroll
            for (int tm = 0; tm < 4; tm++) {
                #pragma unroll
                for (int tn = 0; tn < 4; tn++) {
                    int p = tn >> 1, h2 = (tn & 1) * 2;
                    MMA16816(acc[tm][tn], ah[tm], bh[p][h2], bh[p][h2 + 1]);
                    MMA16816(acc[tm][tn], ah[tm], bl[p][h2], bl[p][h2 + 1]);
                    MMA16816(acc[tm][tn], al[tm], bh[p][h2], bh[p][h2 + 1]);
                }
            }
        }
        __syncthreads();
    }

    // ---- split-K reduction into pre-zeroed out via RED ----
    float* ob = out + (size_t)b * LL * CC;
    #pragma unroll
    for (int tm = 0; tm < 4; tm++) {
        int row = m0 + wm * 64 + tm * 16 + (lane >> 2);
        #pragma unroll
        for (int tn = 0; tn < 4; tn++) {
            int col = wn * 32 + tn * 8 + (lane & 3) * 2;
            atomicAdd(&ob[(size_t)row * CC + col],           acc[tm][tn][0]);
            atomicAdd(&ob[(size_t)row * CC + col + 1],       acc[tm][tn][1]);
            atomicAdd(&ob[(size_t)(row + 8) * CC + col],     acc[tm][tn][2]);
            atomicAdd(&ob[(size_t)(row + 8) * CC + col + 1], acc[tm][tn][3]);
        }
    }
}

// ---------------- launcher ----------------
extern "C" void kernel_launch(void* const* d_in, const int* in_sizes, int n_in,
                              void* d_out, int out_size) {
    const float* x1 = (const float*)d_in[0];
    const float* x2 = (const float*)d_in[1];
    float* out = (float*)d_out;

    cudaFuncSetAttribute(k_gemm3_mma, cudaFuncAttributeMaxDynamicSharedMemorySize, SM_TOTB);

    k_pad  <<<(BN_ * AREA * 32 + 255) / 256, 256>>>(x2);
    k_split<<<(BN_ * LL * CC + 255) / 256, 256>>>(x1, out);
    k_rnorm<<<(BN_ * AREA * 32 + 255) / 256, 256>>>();
    k_nm   <<<(BN_ * LL + 255) / 256, 256>>>();

    dim3 gd(NBLK * (NBLK + 1) / 2, 1, BN_);
    k_dgemm<<<gd, 256>>>();

    dim3 gs((LL * LL) / 256, BN_);
    k_scores<<<gs, 256>>>();

    dim3 gsm(LL, BN_);
    k_softmax<<<gsm, 256>>>();

    k_W2f<<<gs, 256>>>();

    dim3 gg(LL / 128, 2, BN_);
    k_gemm3_mma<<<gg, 256, SM_TOTB>>>(out);
}

// round 6
// speedup vs baseline: 2.2890x; 1.2134x over previous
#include <cuda_runtime.h>
#include <cuda_bf16.h>
#include <cstdint>

#define BN_  2
#define HH   64
#define WW   64
#define CC   128
#define HP   66
#define AREA 4356          // HP*HP
#define LL   4096          // HH*WW
#define NBLK 35            // ceil(AREA/128)

// ---------------- scratch (static device globals; no allocation) ----------------
__device__ float g_Xp2[BN_ * AREA * CC];              // x2 zero-padded
__device__ float g_r  [BN_ * AREA];                   // per-pixel sum of squares of x2pad
__device__ float g_nm [BN_ * LL];                     // 1 / max(patch L2 norm, 1e-4)
__device__ float g_D  [(size_t)BN_ * AREA * AREA];    // D = Xp2 @ Xp2^T
__device__ float g_S  [(size_t)BN_ * LL * LL];        // raw scores
__device__ float g_A  [(size_t)BN_ * LL * LL];        // att (softmax output)
__device__ __nv_bfloat16 g_W2h[(size_t)BN_ * LL * LL];   // diag-filtered att, hi
__device__ __nv_bfloat16 g_W2l[(size_t)BN_ * LL * LL];   // diag-filtered att, lo
__device__ __nv_bfloat16 g_V1h[BN_ * LL * CC];           // x1 hi  [b][k][c]
__device__ __nv_bfloat16 g_V1l[BN_ * LL * CC];           // x1 lo

// ================= portable PTX helpers =================
__device__ __forceinline__ uint32_t smem_u32(const void* p) {
    uint32_t a;
    asm("{ .reg .u64 t; cvta.to.shared.u64 t, %1; cvt.u32.u64 %0, t; }" : "=r"(a) : "l"(p));
    return a;
}

#define LDM_X4(r0, r1, r2, r3, addr) \
    asm volatile("ldmatrix.sync.aligned.m8n8.x4.shared.b16 {%0,%1,%2,%3}, [%4];" \
        : "=r"(r0), "=r"(r1), "=r"(r2), "=r"(r3) : "r"(addr))

#define LDM_X4T(r0, r1, r2, r3, addr) \
    asm volatile("ldmatrix.sync.aligned.m8n8.x4.trans.shared.b16 {%0,%1,%2,%3}, [%4];" \
        : "=r"(r0), "=r"(r1), "=r"(r2), "=r"(r3) : "r"(addr))

#define MMA16816(d, a, b0v, b1v) \
    asm volatile("mma.sync.aligned.m16n8k16.row.col.f32.bf16.bf16.f32 " \
        "{%0,%1,%2,%3}, {%4,%5,%6,%7}, {%8,%9}, {%0,%1,%2,%3};" \
        : "+f"((d)[0]), "+f"((d)[1]), "+f"((d)[2]), "+f"((d)[3]) \
        : "r"((a)[0]), "r"((a)[1]), "r"((a)[2]), "r"((a)[3]), "r"(b0v), "r"(b1v))

// ---------------- pad x2 into [b, 66*66, 128] with zero border ----------------
__global__ void k_pad(const float* __restrict__ x2) {
    int idx = blockIdx.x * blockDim.x + threadIdx.x;
    if (idx >= BN_ * AREA * 32) return;
    int v = idx & 31;
    int a = (idx >> 5) % AREA;
    int b = idx / (AREA * 32);
    int ai = a / HP, aj = a % HP;
    float4 z2 = make_float4(0.f, 0.f, 0.f, 0.f);
    if (ai >= 1 && ai <= HH && aj >= 1 && aj <= WW) {
        int src = ((b * HH + (ai - 1)) * WW + (aj - 1)) * 32 + v;
        z2 = ((const float4*)x2)[src];
    }
    ((float4*)g_Xp2)[idx] = z2;
}

// ---------------- split x1 into bf16 hi/lo + zero output ----------------
__global__ void k_split(const float* __restrict__ x1, float* __restrict__ out) {
    int idx = blockIdx.x * blockDim.x + threadIdx.x;
    if (idx >= BN_ * LL * CC) return;
    float v = x1[idx];
    __nv_bfloat16 h = __float2bfloat16(v);
    float lo = v - __bfloat162float(h);
    g_V1h[idx] = h;
    g_V1l[idx] = __float2bfloat16(lo);
    out[idx] = 0.f;
}

// ---------------- per-pixel squared norms of x2pad ----------------
__global__ void k_rnorm() {
    int gw = (blockIdx.x * blockDim.x + threadIdx.x) >> 5;
    int lane = threadIdx.x & 31;
    if (gw >= BN_ * AREA) return;
    const float4* p = ((const float4*)g_Xp2) + (size_t)gw * 32;
    float4 v = p[lane];
    float s = v.x * v.x + v.y * v.y + v.z * v.z + v.w * v.w;
    #pragma unroll
    for (int o = 16; o; o >>= 1) s += __shfl_xor_sync(0xffffffffu, s, o);
    if (!lane) g_r[gw] = s;
}

// ---------------- patch norms ----------------
__global__ void k_nm() {
    int idx = blockIdx.x * blockDim.x + threadIdx.x;
    if (idx >= BN_ * LL) return;
    int l = idx & (LL - 1), b = idx / LL;
    int li = l >> 6, lj = l & 63;
    const float* rb = g_r + b * AREA;
    float s = 0.f;
    #pragma unroll
    for (int dy = 0; dy < 3; dy++)
        #pragma unroll
        for (int dx = 0; dx < 3; dx++)
            s += rb[(li + dy) * HP + lj + dx];
    g_nm[idx] = 1.f / fmaxf(sqrtf(s), 1e-4f);
}

// ---------------- D = Xp2 @ Xp2^T, symmetric ----------------
__global__ __launch_bounds__(256, 2) void k_dgemm() {
    int rem = blockIdx.x;
    int bm = 0;
    while (rem >= NBLK - bm) { rem -= NBLK - bm; bm++; }
    int bn = bm + rem;
    int b = blockIdx.z;

    const float* __restrict__ X = g_Xp2 + (size_t)b * AREA * CC;
    float* __restrict__ Dp = g_D + (size_t)b * AREA * AREA;

    __shared__ float sm[128 * 129];
    float (*As)[132] = (float(*)[132])sm;
    float (*Bs)[132] = (float(*)[132])(sm + 2112);

    int tid = threadIdx.x;
    int m0 = bm * 128, n0 = bn * 128;
    int tx = tid & 15, ty = tid >> 4;
    float acc[8][8];
    #pragma unroll
    for (int i = 0; i < 8; i++)
        #pragma unroll
        for (int j = 0; j < 8; j++) acc[i][j] = 0.f;

    #pragma unroll 1
    for (int k0 = 0; k0 < CC; k0 += 16) {
        #pragma unroll
        for (int i = 0; i < 2; i++) {
            int li = tid + i * 256;
            int row = li >> 2, c4 = li & 3;
            float4 va = make_float4(0.f, 0.f, 0.f, 0.f), vb = va;
            if (m0 + row < AREA) va = *(const float4*)&X[(size_t)(m0 + row) * CC + k0 + c4 * 4];
            if (n0 + row < AREA) vb = *(const float4*)&X[(size_t)(n0 + row) * CC + k0 + c4 * 4];
            As[c4 * 4 + 0][row] = va.x; As[c4 * 4 + 1][row] = va.y;
            As[c4 * 4 + 2][row] = va.z; As[c4 * 4 + 3][row] = va.w;
            Bs[c4 * 4 + 0][row] = vb.x; Bs[c4 * 4 + 1][row] = vb.y;
            Bs[c4 * 4 + 2][row] = vb.z; Bs[c4 * 4 + 3][row] = vb.w;
        }
        __syncthreads();
        #pragma unroll
        for (int kk = 0; kk < 16; kk++) {
            float a[8], bv[8];
            #pragma unroll
            for (int i = 0; i < 4; i++) { a[i] = As[kk][ty * 4 + i]; a[4 + i] = As[kk][64 + ty * 4 + i]; }
            #pragma unroll
            for (int j = 0; j < 4; j++) { bv[j] = Bs[kk][tx * 4 + j]; bv[4 + j] = Bs[kk][64 + tx * 4 + j]; }
            #pragma unroll
            for (int i = 0; i < 8; i++)
                #pragma unroll
                for (int j = 0; j < 8; j++) acc[i][j] += a[i] * bv[j];
        }
        __syncthreads();
    }

    #pragma unroll
    for (int i = 0; i < 8; i++) {
        int ml = (i < 4) ? (ty * 4 + i) : (64 + ty * 4 + i - 4);
        int gm = m0 + ml;
        if (gm < AREA) {
            #pragma unroll
            for (int jh = 0; jh < 2; jh++) {
                int gn = n0 + ((jh == 0) ? (tx * 4) : (64 + tx * 4));
                if (gn < AREA) {
                    float4 v = make_float4(acc[i][jh * 4 + 0], acc[i][jh * 4 + 1],
                                           acc[i][jh * 4 + 2], acc[i][jh * 4 + 3]);
                    *(float4*)&Dp[(size_t)gm * AREA + gn] = v;
                }
            }
        }
    }

    if (bm == bn) return;

    __syncthreads();
    #pragma unroll
    for (int i = 0; i < 8; i++) {
        int ml = (i < 4) ? (ty * 4 + i) : (64 + ty * 4 + i - 4);
        #pragma unroll
        for (int j = 0; j < 8; j++) {
            int nl = (j < 4) ? (tx * 4 + j) : (64 + tx * 4 + j - 4);
            sm[nl * 129 + ml] = acc[i][j];
        }
    }
    __syncthreads();
    #pragma unroll
    for (int q = 0; q < 16; q++) {
        int pos = q * 256 + tid;
        int r = pos >> 5, c4 = pos & 31;
        int gn = n0 + r, gm = m0 + c4 * 4;
        if (gn < AREA && gm < AREA) {
            float4 v = make_float4(sm[r * 129 + c4 * 4 + 0], sm[r * 129 + c4 * 4 + 1],
                                   sm[r * 129 + c4 * 4 + 2], sm[r * 129 + c4 * 4 + 3]);
            *(float4*)&Dp[(size_t)gn * AREA + gm] = v;
        }
    }
}

// ---------------- scores, smem-tiled: block = (xi, li) image-row pair ----------------
// slab[s] = D[(xi+s)*HP + 0..65, (li+s)*HP + 0..65]; out[xj,lj] = sum_{dy,dx} slab[dy][xj+dx][lj+dx]
#define SC_SMEM ((3 * AREA + 64) * 4)
__global__ __launch_bounds__(256) void k_scores() {
    extern __shared__ float dsm[];
    float* slab = dsm;            // 3 * 4356
    float* inm  = dsm + 3 * AREA; // 64
    int xi = blockIdx.x, li = blockIdx.y, b = blockIdx.z;
    int tid = threadIdx.x;
    const float* __restrict__ Db = g_D + (size_t)b * AREA * AREA;

    if (tid < 64) inm[tid] = g_nm[b * LL + li * 64 + tid];
    #pragma unroll
    for (int s = 0; s < 3; s++) {
        const float* src = Db + (size_t)((xi + s) * HP) * AREA + (li + s) * HP;
        float* dst = slab + s * AREA;
        for (int e = tid; e < AREA; e += 256) {
            int r = e / HP, c = e - r * HP;
            dst[e] = src[(size_t)r * AREA + c];
        }
    }
    __syncthreads();

    int lj = tid & 63;
    int xb = tid >> 6;            // 0..3
    float* So = g_S + (size_t)b * LL * LL + (size_t)(xi * 64) * LL + li * 64 + lj;
    float iv = inm[lj];
    #pragma unroll
    for (int q = 0; q < 16; q++) {
        int xj = xb + (q << 2);
        float s = 0.f;
        #pragma unroll
        for (int dy = 0; dy < 3; dy++) {
            const float* sl = slab + dy * AREA;
            #pragma unroll
            for (int dx = 0; dx < 3; dx++)
                s += sl[(xj + dx) * HP + lj + dx];
        }
        So[(size_t)xj * LL] = s * iv;
    }
}

// ---------------- 3x3 query pool (float4) + scale + row softmax → g_A ----------------
__global__ __launch_bounds__(256) void k_softmax() {
    __shared__ __align__(16) float row[LL];
    __shared__ float red[32];
    int b = blockIdx.y, x = blockIdx.x;
    int xi = x >> 6, xj = x & 63;
    float cy = (xi == 0 || xi == 63) ? 2.f : 3.f;
    float cx = (xj == 0 || xj == 63) ? 2.f : 3.f;
    float sc = 90.f / (cy * cx);
    size_t base = (size_t)b * LL * LL;
    const float4* __restrict__ S4 = (const float4*)(g_S + base);
    int t = threadIdx.x;

    int offs4[9]; int no = 0;
    #pragma unroll
    for (int dy = -1; dy <= 1; dy++)
        #pragma unroll
        for (int dx = -1; dx <= 1; dx++) {
            if (xi + dy >= 0 && xi + dy < HH && xj + dx >= 0 && xj + dx < WW)
                offs4[no++] = (x + dy * 64 + dx) * (LL / 4);
        }

    float lmax = -1e30f;
    for (int l4 = t; l4 < LL / 4; l4 += 256) {
        float4 s = make_float4(0.f, 0.f, 0.f, 0.f);
        for (int o = 0; o < no; o++) {
            float4 v = __ldg(&S4[offs4[o] + l4]);
            s.x += v.x; s.y += v.y; s.z += v.z; s.w += v.w;
        }
        s.x *= sc; s.y *= sc; s.z *= sc; s.w *= sc;
        ((float4*)row)[l4] = s;
        lmax = fmaxf(fmaxf(fmaxf(lmax, s.x), fmaxf(s.y, s.z)), s.w);
    }
    #pragma unroll
    for (int o = 16; o; o >>= 1) lmax = fmaxf(lmax, __shfl_xor_sync(0xffffffffu, lmax, o));
    if ((t & 31) == 0) red[t >> 5] = lmax;
    __syncthreads();
    if (t < 32) {
        float v = (t < 8) ? red[t] : -1e30f;
        #pragma unroll
        for (int o = 4; o; o >>= 1) v = fmaxf(v, __shfl_xor_sync(0xffffffffu, v, o));
        if (!t) red[0] = v;
    }
    __syncthreads();
    float m = red[0];
    __syncthreads();
    float lsum = 0.f;
    for (int l4 = t; l4 < LL / 4; l4 += 256) {
        float4 s = ((float4*)row)[l4];
        s.x = __expf(s.x - m); s.y = __expf(s.y - m);
        s.z = __expf(s.z - m); s.w = __expf(s.w - m);
        ((float4*)row)[l4] = s;
        lsum += s.x + s.y + s.z + s.w;
    }
    #pragma unroll
    for (int o = 16; o; o >>= 1) lsum += __shfl_xor_sync(0xffffffffu, lsum, o);
    if ((t & 31) == 0) red[t >> 5] = lsum;
    __syncthreads();
    if (t < 32) {
        float v = (t < 8) ? red[t] : 0.f;
        #pragma unroll
        for (int o = 4; o; o >>= 1) v += __shfl_xor_sync(0xffffffffu, v, o);
        if (!t) red[0] = v;
    }
    __syncthreads();
    float inv = 1.f / red[0];
    float4* A4 = (float4*)(g_A + base + (size_t)x * LL);
    for (int l4 = t; l4 < LL / 4; l4 += 256) {
        float4 s = ((float4*)row)[l4];
        s.x *= inv; s.y *= inv; s.z *= inv; s.w *= inv;
        A4[l4] = s;
    }
}

// ---------------- diagonal 3x3 box filter → W2 hi/lo bf16, 4 outputs/thread ----------------
__global__ void k_W2f() {
    int b = blockIdx.y;
    int lin4 = blockIdx.x * blockDim.x + threadIdx.x;   // over LL*LL/4
    int x = lin4 >> 10, l0 = (lin4 & 1023) << 2;
    int h = x >> 6, w = x & 63;
    int lj0 = l0 & 63;
    const float* __restrict__ att = g_A + (size_t)b * LL * LL;
    float s[4] = {0.f, 0.f, 0.f, 0.f};
    #pragma unroll
    for (int sy = 1; sy >= -1; sy--) {
        if ((unsigned)(h + sy) >= 64u) continue;
        #pragma unroll
        for (int sx = 1; sx >= -1; sx--) {
            if ((unsigned)(w + sx) >= 64u) continue;
            long u = sy * 64 + sx;
            const float* p = att + (size_t)(x + u) * LL + l0 + u;
            int li0 = (l0 >> 6) + sy;
            if ((unsigned)li0 >= 64u) continue;
            #pragma unroll
            for (int j = 0; j < 4; j++) {
                if ((unsigned)(lj0 + j + sx) < 64u)
                    s[j] += __ldg(p + j);
            }
        }
    }
    size_t dst = (size_t)b * LL * LL + (size_t)x * LL + l0;
    __nv_bfloat162 h01, h23, l01, l23;
    float r0 = s[0] - __bfloat162float(__float2bfloat16(s[0]));
    float r1 = s[1] - __bfloat162float(__float2bfloat16(s[1]));
    float r2 = s[2] - __bfloat162float(__float2bfloat16(s[2]));
    float r3 = s[3] - __bfloat162float(__float2bfloat16(s[3]));
    h01 = __nv_bfloat162(__float2bfloat16(s[0]), __float2bfloat16(s[1]));
    h23 = __nv_bfloat162(__float2bfloat16(s[2]), __float2bfloat16(s[3]));
    l01 = __nv_bfloat162(__float2bfloat16(r0), __float2bfloat16(r1));
    l23 = __nv_bfloat162(__float2bfloat16(r2), __float2bfloat16(r3));
    *(__nv_bfloat162*)(g_W2h + dst)     = h01;
    *(__nv_bfloat162*)(g_W2h + dst + 2) = h23;
    *(__nv_bfloat162*)(g_W2l + dst)     = l01;
    *(__nv_bfloat162*)(g_W2l + dst + 2) = l23;
}

// ---------------- y = W2 @ x1 via mma.sync bf16x3 (M=128, N=128, split-K=2) ----------------
#define GA_STR 72
#define GB_STR 136
#define SM_AH  0
#define SM_AL  (128 * GA_STR)
#define SM_BH  (2 * 128 * GA_STR)
#define SM_BL  (2 * 128 * GA_STR + 64 * GB_STR)
#define SM_TOTB ((2 * 128 * GA_STR + 2 * 64 * GB_STR) * 2)

__global__ __launch_bounds__(256, 1) void k_gemm3_mma(float* __restrict__ out) {
    extern __shared__ __nv_bfloat16 sm[];
    int tid = threadIdx.x, lane = tid & 31, wid = tid >> 5;
    int wm = wid >> 2, wn = wid & 3;
    int m0 = blockIdx.x * 128;
    int kbeg = blockIdx.y * (LL / 2);
    int b = blockIdx.z;

    const __nv_bfloat16* __restrict__ Ah = g_W2h + (size_t)b * LL * LL;
    const __nv_bfloat16* __restrict__ Al = g_W2l + (size_t)b * LL * LL;
    const __nv_bfloat16* __restrict__ Bh = g_V1h + (size_t)b * LL * CC;
    const __nv_bfloat16* __restrict__ Bl = g_V1l + (size_t)b * LL * CC;

    uint32_t sb = smem_u32(sm);
    float acc[4][4][4];
    #pragma unroll
    for (int i = 0; i < 4; i++)
        #pragma unroll
        for (int j = 0; j < 4; j++)
            #pragma unroll
            for (int q = 0; q < 4; q++) acc[i][j][q] = 0.f;

    int frow = (lane & 7) + ((lane >> 3) & 1) * 8;
    int fcol = ((lane >> 4) & 1) * 8;

    #pragma unroll 1
    for (int ci = 0; ci < 32; ci++) {
        int k0 = kbeg + ci * 64;
        #pragma unroll
        for (int q = 0; q < 4; q++) {
            int e = q * 256 + tid;
            int r = e >> 3, c = e & 7;
            const size_t so = (size_t)(m0 + r) * LL + k0 + c * 8;
            *(uint4*)(sm + SM_AH + r * GA_STR + c * 8) = *(const uint4*)(Ah + so);
            *(uint4*)(sm + SM_AL + r * GA_STR + c * 8) = *(const uint4*)(Al + so);
        }
        #pragma unroll
        for (int q = 0; q < 4; q++) {
            int e = q * 256 + tid;
            int r = e >> 4, c = e & 15;
            const size_t so = (size_t)(k0 + r) * CC + c * 8;
            *(uint4*)(sm + SM_BH + r * GB_STR + c * 8) = *(const uint4*)(Bh + so);
            *(uint4*)(sm + SM_BL + r * GB_STR + c * 8) = *(const uint4*)(Bl + so);
        }
        __syncthreads();

        #pragma unroll
        for (int ks = 0; ks < 4; ks++) {
            uint32_t ah[4][4], al[4][4], bh[2][4], bl[2][4];
            #pragma unroll
            for (int tm = 0; tm < 4; tm++) {
                uint32_t off = (wm * 64 + tm * 16 + frow) * GA_STR + ks * 16 + fcol;
                LDM_X4(ah[tm][0], ah[tm][1], ah[tm][2], ah[tm][3], sb + (SM_AH + off) * 2);
                LDM_X4(al[tm][0], al[tm][1], al[tm][2], al[tm][3], sb + (SM_AL + off) * 2);
            }
            #pragma unroll
            for (int p = 0; p < 2; p++) {
                uint32_t off = (ks * 16 + frow) * GB_STR + wn * 32 + p * 16 + fcol;
                LDM_X4T(bh[p][0], bh[p][1], bh[p][2], bh[p][3], sb + (SM_BH + off) * 2);
                LDM_X4T(bl[p][0], bl[p][1], bl[p][2], bl[p][3], sb + (SM_BL + off) * 2);
            }
            #pragma unroll
            for (int tm = 0; tm < 4; tm++) {
                #pragma unroll
                for (int tn = 0; tn < 4; tn++) {
                    int p = tn >> 1, h2 = (tn & 1) * 2;
                    MMA16816(acc[tm][tn], ah[tm], bh[p][h2], bh[p][h2 + 1]);
                    MMA16816(acc[tm][tn], ah[tm], bl[p][h2], bl[p][h2 + 1]);
                    MMA16816(acc[tm][tn], al[tm], bh[p][h2], bh[p][h2 + 1]);
                }
            }
        }
        __syncthreads();
    }

    float* ob = out + (size_t)b * LL * CC;
    #pragma unroll
    for (int tm = 0; tm < 4; tm++) {
        int row = m0 + wm * 64 + tm * 16 + (lane >> 2);
        #pragma unroll
        for (int tn = 0; tn < 4; tn++) {
            int col = wn * 32 + tn * 8 + (lane & 3) * 2;
            atomicAdd(&ob[(size_t)row * CC + col],           acc[tm][tn][0]);
            atomicAdd(&ob[(size_t)row * CC + col + 1],       acc[tm][tn][1]);
            atomicAdd(&ob[(size_t)(row + 8) * CC + col],     acc[tm][tn][2]);
            atomicAdd(&ob[(size_t)(row + 8) * CC + col + 1], acc[tm][tn][3]);
        }
    }
}

// ---------------- launcher ----------------
extern "C" void kernel_launch(void* const* d_in, const int* in_sizes, int n_in,
                              void* d_out, int out_size) {
    const float* x1 = (const float*)d_in[0];
    const float* x2 = (const float*)d_in[1];
    float* out = (float*)d_out;

    cudaFuncSetAttribute(k_gemm3_mma, cudaFuncAttributeMaxDynamicSharedMemorySize, SM_TOTB);
    cudaFuncSetAttribute(k_scores, cudaFuncAttributeMaxDynamicSharedMemorySize, SC_SMEM);

    k_pad  <<<(BN_ * AREA * 32 + 255) / 256, 256>>>(x2);
    k_split<<<(BN_ * LL * CC + 255) / 256, 256>>>(x1, out);
    k_rnorm<<<(BN_ * AREA * 32 + 255) / 256, 256>>>();
    k_nm   <<<(BN_ * LL + 255) / 256, 256>>>();

    dim3 gd(NBLK * (NBLK + 1) / 2, 1, BN_);
    k_dgemm<<<gd, 256>>>();

    dim3 gsc(64, 64, BN_);
    k_scores<<<gsc, 256, SC_SMEM>>>();

    dim3 gsm(LL, BN_);
    k_softmax<<<gsm, 256>>>();

    dim3 gw((LL * LL / 4) / 256, BN_);
    k_W2f<<<gw, 256>>>();

    dim3 gg(LL / 128, 2, BN_);
    k_gemm3_mma<<<gg, 256, SM_TOTB>>>(out);
}

// round 7
// speedup vs baseline: 2.4385x; 1.0653x over previous
#include <cuda_runtime.h>
#include <cuda_bf16.h>
#include <cstdint>

#define BN_  2
#define HH   64
#define WW   64
#define CC   128
#define HP   66
#define AREA 4356          // HP*HP
#define LL   4096          // HH*WW
#define NBLK 35            // ceil(AREA/128)

// ---------------- scratch (static device globals; no allocation) ----------------
__device__ float g_Xp2[BN_ * AREA * CC];              // x2 zero-padded [b][a][c]
__device__ float g_XT [BN_ * CC * AREA + 128];        // x2 padded, transposed [b][c][a] (+pad)
__device__ float g_r  [BN_ * AREA];                   // per-pixel sum of squares
__device__ float g_nm [BN_ * LL];                     // 1 / max(patch L2 norm, 1e-4)
__device__ float g_D  [(size_t)BN_ * AREA * AREA];    // D = Xp2 @ Xp2^T
__device__ float g_S  [(size_t)BN_ * LL * LL];        // raw scores
__device__ float g_A  [(size_t)BN_ * LL * LL];        // att
__device__ __nv_bfloat16 g_W2h[(size_t)BN_ * LL * LL];
__device__ __nv_bfloat16 g_W2l[(size_t)BN_ * LL * LL];
__device__ __nv_bfloat16 g_V1h[BN_ * LL * CC];
__device__ __nv_bfloat16 g_V1l[BN_ * LL * CC];

// ================= portable PTX helpers =================
__device__ __forceinline__ uint32_t smem_u32(const void* p) {
    uint32_t a;
    asm("{ .reg .u64 t; cvta.to.shared.u64 t, %1; cvt.u32.u64 %0, t; }" : "=r"(a) : "l"(p));
    return a;
}
#define CP_A16(dst, src) asm volatile("cp.async.cg.shared.global [%0], [%1], 16;" :: "r"(dst), "l"(src))
#define CP_COMMIT()      asm volatile("cp.async.commit_group;" ::: "memory")
#define CP_WAIT(n)       asm volatile("cp.async.wait_group %0;" :: "n"(n) : "memory")

#define LDM_X4(r0, r1, r2, r3, addr) \
    asm volatile("ldmatrix.sync.aligned.m8n8.x4.shared.b16 {%0,%1,%2,%3}, [%4];" \
        : "=r"(r0), "=r"(r1), "=r"(r2), "=r"(r3) : "r"(addr))
#define LDM_X4T(r0, r1, r2, r3, addr) \
    asm volatile("ldmatrix.sync.aligned.m8n8.x4.trans.shared.b16 {%0,%1,%2,%3}, [%4];" \
        : "=r"(r0), "=r"(r1), "=r"(r2), "=r"(r3) : "r"(addr))
#define MMA16816(d, a, b0v, b1v) \
    asm volatile("mma.sync.aligned.m16n8k16.row.col.f32.bf16.bf16.f32 " \
        "{%0,%1,%2,%3}, {%4,%5,%6,%7}, {%8,%9}, {%0,%1,%2,%3};" \
        : "+f"((d)[0]), "+f"((d)[1]), "+f"((d)[2]), "+f"((d)[3]) \
        : "r"((a)[0]), "r"((a)[1]), "r"((a)[2]), "r"((a)[3]), "r"(b0v), "r"(b1v))

// ---------------- pad x2 into [b, 66*66, 128] with zero border ----------------
__global__ void k_pad(const float* __restrict__ x2) {
    int idx = blockIdx.x * blockDim.x + threadIdx.x;
    if (idx >= BN_ * AREA * 32) return;
    int v = idx & 31;
    int a = (idx >> 5) % AREA;
    int b = idx / (AREA * 32);
    int ai = a / HP, aj = a % HP;
    float4 z2 = make_float4(0.f, 0.f, 0.f, 0.f);
    if (ai >= 1 && ai <= HH && aj >= 1 && aj <= WW) {
        int src = ((b * HH + (ai - 1)) * WW + (aj - 1)) * 32 + v;
        z2 = ((const float4*)x2)[src];
    }
    ((float4*)g_Xp2)[idx] = z2;
}

// ---------------- transpose Xp2 -> XT [b][c][a] ----------------
__global__ void k_xt() {
    __shared__ float t[32][33];
    int b = blockIdx.z;
    int a0 = blockIdx.x * 32, c0 = blockIdx.y * 32;
    int tx = threadIdx.x, ty = threadIdx.y;
    #pragma unroll
    for (int i = 0; i < 4; i++) {
        int r = ty + i * 8;
        if (a0 + r < AREA)
            t[r][tx] = g_Xp2[((size_t)b * AREA + a0 + r) * CC + c0 + tx];
    }
    __syncthreads();
    #pragma unroll
    for (int i = 0; i < 4; i++) {
        int r = ty + i * 8;
        if (a0 + tx < AREA)
            g_XT[((size_t)b * CC + c0 + r) * AREA + a0 + tx] = t[tx][r];
    }
}

// ---------------- split x1 into bf16 hi/lo + zero output ----------------
__global__ void k_split(const float* __restrict__ x1, float* __restrict__ out) {
    int idx = blockIdx.x * blockDim.x + threadIdx.x;
    if (idx >= BN_ * LL * CC) return;
    float v = x1[idx];
    __nv_bfloat16 h = __float2bfloat16(v);
    float lo = v - __bfloat162float(h);
    g_V1h[idx] = h;
    g_V1l[idx] = __float2bfloat16(lo);
    out[idx] = 0.f;
}

// ---------------- per-pixel squared norms of x2pad ----------------
__global__ void k_rnorm() {
    int gw = (blockIdx.x * blockDim.x + threadIdx.x) >> 5;
    int lane = threadIdx.x & 31;
    if (gw >= BN_ * AREA) return;
    const float4* p = ((const float4*)g_Xp2) + (size_t)gw * 32;
    float4 v = p[lane];
    float s = v.x * v.x + v.y * v.y + v.z * v.z + v.w * v.w;
    #pragma unroll
    for (int o = 16; o; o >>= 1) s += __shfl_xor_sync(0xffffffffu, s, o);
    if (!lane) g_r[gw] = s;
}

// ---------------- patch norms ----------------
__global__ void k_nm() {
    int idx = blockIdx.x * blockDim.x + threadIdx.x;
    if (idx >= BN_ * LL) return;
    int l = idx & (LL - 1), b = idx / LL;
    int li = l >> 6, lj = l & 63;
    const float* rb = g_r + b * AREA;
    float s = 0.f;
    #pragma unroll
    for (int dy = 0; dy < 3; dy++)
        #pragma unroll
        for (int dx = 0; dx < 3; dx++)
            s += rb[(li + dy) * HP + lj + dx];
    g_nm[idx] = 1.f / fmaxf(sqrtf(s), 1e-4f);
}

// ---------------- D = XT^T @ XT, symmetric, cp.async double-buffered ----------------
// stage: As[32][132] + Bs[32][132]; 2 stages = 16896 floats = 67584 B
#define DG_STG 4224
#define DG_SMEM (2 * 2 * DG_STG * 4)
__global__ __launch_bounds__(256, 2) void k_dgemm() {
    extern __shared__ float dsm[];
    int rem = blockIdx.x;
    int bm = 0;
    while (rem >= NBLK - bm) { rem -= NBLK - bm; bm++; }
    int bn = bm + rem;
    int b = blockIdx.z;

    const float* __restrict__ XT = g_XT + (size_t)b * CC * AREA;
    float* __restrict__ Dp = g_D + (size_t)b * AREA * AREA;

    int tid = threadIdx.x;
    int m0 = bm * 128, n0 = bn * 128;
    int tx = tid & 15, ty = tid >> 4;
    float acc[8][8];
    #pragma unroll
    for (int i = 0; i < 8; i++)
        #pragma unroll
        for (int j = 0; j < 8; j++) acc[i][j] = 0.f;

    uint32_t sbase = smem_u32(dsm);

    // loader: stage s, k-chunk start kc
    auto load_stage = [&](int s, int kc) {
        uint32_t stA = sbase + (uint32_t)(2 * s) * DG_STG * 4;
        uint32_t stB = stA + DG_STG * 4;
        #pragma unroll
        for (int q = 0; q < 4; q++) {
            int e = q * 256 + tid;           // 0..1023 = 32 rows x 32 16B-chunks
            int r = e >> 5, c16 = e & 31;
            const float* srcA = XT + (size_t)(kc + r) * AREA + m0 + c16 * 4;
            const float* srcB = XT + (size_t)(kc + r) * AREA + n0 + c16 * 4;
            CP_A16(stA + (r * 132 + c16 * 4) * 4, srcA);
            CP_A16(stB + (r * 132 + c16 * 4) * 4, srcB);
        }
    };

    load_stage(0, 0);
    CP_COMMIT();

    #pragma unroll 1
    for (int ch = 0; ch < 4; ch++) {
        if (ch < 3) { load_stage((ch + 1) & 1, (ch + 1) * 32); CP_COMMIT(); }
        if (ch < 3) CP_WAIT(1); else CP_WAIT(0);
        __syncthreads();
        float (*As)[132] = (float(*)[132])(dsm + (size_t)(2 * (ch & 1)) * DG_STG);
        float (*Bs)[132] = (float(*)[132])(dsm + (size_t)(2 * (ch & 1)) * DG_STG + DG_STG);
        #pragma unroll 8
        for (int kk = 0; kk < 32; kk++) {
            float a[8], bv[8];
            #pragma unroll
            for (int i = 0; i < 4; i++) { a[i] = As[kk][ty * 4 + i]; a[4 + i] = As[kk][64 + ty * 4 + i]; }
            #pragma unroll
            for (int j = 0; j < 4; j++) { bv[j] = Bs[kk][tx * 4 + j]; bv[4 + j] = Bs[kk][64 + tx * 4 + j]; }
            #pragma unroll
            for (int i = 0; i < 8; i++)
                #pragma unroll
                for (int j = 0; j < 8; j++) acc[i][j] += a[i] * bv[j];
        }
        __syncthreads();
    }

    #pragma unroll
    for (int i = 0; i < 8; i++) {
        int ml = (i < 4) ? (ty * 4 + i) : (64 + ty * 4 + i - 4);
        int gm = m0 + ml;
        if (gm < AREA) {
            #pragma unroll
            for (int jh = 0; jh < 2; jh++) {
                int gn = n0 + ((jh == 0) ? (tx * 4) : (64 + tx * 4));
                if (gn < AREA) {
                    float4 v = make_float4(acc[i][jh * 4 + 0], acc[i][jh * 4 + 1],
                                           acc[i][jh * 4 + 2], acc[i][jh * 4 + 3]);
                    *(float4*)&Dp[(size_t)gm * AREA + gn] = v;
                }
            }
        }
    }

    if (bm == bn) return;

    // transposed store via smem staging (reuse pipeline smem: 128*129*4 = 66048 <= 67584)
    __syncthreads();
    #pragma unroll
    for (int i = 0; i < 8; i++) {
        int ml = (i < 4) ? (ty * 4 + i) : (64 + ty * 4 + i - 4);
        #pragma unroll
        for (int j = 0; j < 8; j++) {
            int nl = (j < 4) ? (tx * 4 + j) : (64 + tx * 4 + j - 4);
            dsm[nl * 129 + ml] = acc[i][j];
        }
    }
    __syncthreads();
    #pragma unroll
    for (int q = 0; q < 16; q++) {
        int pos = q * 256 + tid;
        int r = pos >> 5, c4 = pos & 31;
        int gn = n0 + r, gm = m0 + c4 * 4;
        if (gn < AREA && gm < AREA) {
            float4 v = make_float4(dsm[r * 129 + c4 * 4 + 0], dsm[r * 129 + c4 * 4 + 1],
                                   dsm[r * 129 + c4 * 4 + 2], dsm[r * 129 + c4 * 4 + 3]);
            *(float4*)&Dp[(size_t)gn * AREA + gm] = v;
        }
    }
}

// ---------------- scores, smem-tiled ----------------
#define SC_SMEM ((3 * AREA + 64) * 4)
__global__ __launch_bounds__(256) void k_scores() {
    extern __shared__ float dsm[];
    float* slab = dsm;
    float* inm  = dsm + 3 * AREA;
    int xi = blockIdx.x, li = blockIdx.y, b = blockIdx.z;
    int tid = threadIdx.x;
    const float* __restrict__ Db = g_D + (size_t)b * AREA * AREA;

    if (tid < 64) inm[tid] = g_nm[b * LL + li * 64 + tid];
    #pragma unroll
    for (int s = 0; s < 3; s++) {
        const float* src = Db + (size_t)((xi + s) * HP) * AREA + (li + s) * HP;
        float* dst = slab + s * AREA;
        for (int e = tid; e < AREA; e += 256) {
            int r = e / HP, c = e - r * HP;
            dst[e] = src[(size_t)r * AREA + c];
        }
    }
    __syncthreads();

    int lj = tid & 63;
    int xb = tid >> 6;
    float* So = g_S + (size_t)b * LL * LL + (size_t)(xi * 64) * LL + li * 64 + lj;
    float iv = inm[lj];
    #pragma unroll
    for (int q = 0; q < 16; q++) {
        int xj = xb + (q << 2);
        float s = 0.f;
        #pragma unroll
        for (int dy = 0; dy < 3; dy++) {
            const float* sl = slab + dy * AREA;
            #pragma unroll
            for (int dx = 0; dx < 3; dx++)
                s += sl[(xj + dx) * HP + lj + dx];
        }
        So[(size_t)xj * LL] = s * iv;
    }
}

// ---------------- 3x3 query pool (float4) + scale + row softmax → g_A ----------------
__global__ __launch_bounds__(256) void k_softmax() {
    __shared__ __align__(16) float row[LL];
    __shared__ float red[32];
    int b = blockIdx.y, x = blockIdx.x;
    int xi = x >> 6, xj = x & 63;
    float cy = (xi == 0 || xi == 63) ? 2.f : 3.f;
    float cx = (xj == 0 || xj == 63) ? 2.f : 3.f;
    float sc = 90.f / (cy * cx);
    size_t base = (size_t)b * LL * LL;
    const float4* __restrict__ S4 = (const float4*)(g_S + base);
    int t = threadIdx.x;

    int offs4[9]; int no = 0;
    #pragma unroll
    for (int dy = -1; dy <= 1; dy++)
        #pragma unroll
        for (int dx = -1; dx <= 1; dx++) {
            if (xi + dy >= 0 && xi + dy < HH && xj + dx >= 0 && xj + dx < WW)
                offs4[no++] = (x + dy * 64 + dx) * (LL / 4);
        }

    float lmax = -1e30f;
    for (int l4 = t; l4 < LL / 4; l4 += 256) {
        float4 s = make_float4(0.f, 0.f, 0.f, 0.f);
        for (int o = 0; o < no; o++) {
            float4 v = __ldg(&S4[offs4[o] + l4]);
            s.x += v.x; s.y += v.y; s.z += v.z; s.w += v.w;
        }
        s.x *= sc; s.y *= sc; s.z *= sc; s.w *= sc;
        ((float4*)row)[l4] = s;
        lmax = fmaxf(fmaxf(fmaxf(lmax, s.x), fmaxf(s.y, s.z)), s.w);
    }
    #pragma unroll
    for (int o = 16; o; o >>= 1) lmax = fmaxf(lmax, __shfl_xor_sync(0xffffffffu, lmax, o));
    if ((t & 31) == 0) red[t >> 5] = lmax;
    __syncthreads();
    if (t < 32) {
        float v = (t < 8) ? red[t] : -1e30f;
        #pragma unroll
        for (int o = 4; o; o >>= 1) v = fmaxf(v, __shfl_xor_sync(0xffffffffu, v, o));
        if (!t) red[0] = v;
    }
    __syncthreads();
    float m = red[0];
    __syncthreads();
    float lsum = 0.f;
    for (int l4 = t; l4 < LL / 4; l4 += 256) {
        float4 s = ((float4*)row)[l4];
        s.x = __expf(s.x - m); s.y = __expf(s.y - m);
        s.z = __expf(s.z - m); s.w = __expf(s.w - m);
        ((float4*)row)[l4] = s;
        lsum += s.x + s.y + s.z + s.w;
    }
    #pragma unroll
    for (int o = 16; o; o >>= 1) lsum += __shfl_xor_sync(0xffffffffu, lsum, o);
    if ((t & 31) == 0) red[t >> 5] = lsum;
    __syncthreads();
    if (t < 32) {
        float v = (t < 8) ? red[t] : 0.f;
        #pragma unroll
        for (int o = 4; o; o >>= 1) v += __shfl_xor_sync(0xffffffffu, v, o);
        if (!t) red[0] = v;
    }
    __syncthreads();
    float inv = 1.f / red[0];
    float4* A4 = (float4*)(g_A + base + (size_t)x * LL);
    for (int l4 = t; l4 < LL / 4; l4 += 256) {
        float4 s = ((float4*)row)[l4];
        s.x *= inv; s.y *= inv; s.z *= inv; s.w *= inv;
        A4[l4] = s;
    }
}

// ---------------- diagonal 3x3 box filter → W2 hi/lo bf16 ----------------
__global__ void k_W2f() {
    int b = blockIdx.y;
    int lin4 = blockIdx.x * blockDim.x + threadIdx.x;
    int x = lin4 >> 10, l0 = (lin4 & 1023) << 2;
    int h = x >> 6, w = x & 63;
    int lj0 = l0 & 63;
    const float* __restrict__ att = g_A + (size_t)b * LL * LL;
    float s[4] = {0.f, 0.f, 0.f, 0.f};
    #pragma unroll
    for (int sy = 1; sy >= -1; sy--) {
        if ((unsigned)(h + sy) >= 64u) continue;
        #pragma unroll
        for (int sx = 1; sx >= -1; sx--) {
            if ((unsigned)(w + sx) >= 64u) continue;
            long u = sy * 64 + sx;
            const float* p = att + (size_t)(x + u) * LL + l0 + u;
            int li0 = (l0 >> 6) + sy;
            if ((unsigned)li0 >= 64u) continue;
            #pragma unroll
            for (int j = 0; j < 4; j++) {
                if ((unsigned)(lj0 + j + sx) < 64u)
                    s[j] += __ldg(p + j);
            }
        }
    }
    size_t dst = (size_t)b * LL * LL + (size_t)x * LL + l0;
    float r0 = s[0] - __bfloat162float(__float2bfloat16(s[0]));
    float r1 = s[1] - __bfloat162float(__float2bfloat16(s[1]));
    float r2 = s[2] - __bfloat162float(__float2bfloat16(s[2]));
    float r3 = s[3] - __bfloat162float(__float2bfloat16(s[3]));
    __nv_bfloat162 h01(__float2bfloat16(s[0]), __float2bfloat16(s[1]));
    __nv_bfloat162 h23(__float2bfloat16(s[2]), __float2bfloat16(s[3]));
    __nv_bfloat162 l01(__float2bfloat16(r0), __float2bfloat16(r1));
    __nv_bfloat162 l23(__float2bfloat16(r2), __float2bfloat16(r3));
    *(__nv_bfloat162*)(g_W2h + dst)     = h01;
    *(__nv_bfloat162*)(g_W2h + dst + 2) = h23;
    *(__nv_bfloat162*)(g_W2l + dst)     = l01;
    *(__nv_bfloat162*)(g_W2l + dst + 2) = l23;
}

// ---------------- y = W2 @ x1 via mma.sync bf16x3, cp.async double-buffered ----------------
#define GA_STR 72
#define GB_STR 136
#define G3_AH  0
#define G3_AL  (128 * GA_STR * 2)                          // 18432 B
#define G3_BH  (2 * 128 * GA_STR * 2)                      // 36864 B
#define G3_BL  (2 * 128 * GA_STR * 2 + 64 * GB_STR * 2)    // 54272 B
#define G3_STG (2 * 128 * GA_STR * 2 + 2 * 64 * GB_STR * 2)  // 71680 B
#define G3_SMEM (2 * G3_STG)                               // 143360 B

__global__ __launch_bounds__(256, 1) void k_gemm3_mma(float* __restrict__ out) {
    extern __shared__ __nv_bfloat16 sm[];
    int tid = threadIdx.x, lane = tid & 31, wid = tid >> 5;
    int wm = wid >> 2, wn = wid & 3;
    int m0 = blockIdx.x * 128;
    int kbeg = blockIdx.y * (LL / 2);
    int b = blockIdx.z;

    const __nv_bfloat16* __restrict__ Ah = g_W2h + (size_t)b * LL * LL;
    const __nv_bfloat16* __restrict__ Al = g_W2l + (size_t)b * LL * LL;
    const __nv_bfloat16* __restrict__ Bh = g_V1h + (size_t)b * LL * CC;
    const __nv_bfloat16* __restrict__ Bl = g_V1l + (size_t)b * LL * CC;

    uint32_t sb = smem_u32(sm);
    float acc[4][4][4];
    #pragma unroll
    for (int i = 0; i < 4; i++)
        #pragma unroll
        for (int j = 0; j < 4; j++)
            #pragma unroll
            for (int q = 0; q < 4; q++) acc[i][j][q] = 0.f;

    int frow = (lane & 7) + ((lane >> 3) & 1) * 8;
    int fcol = ((lane >> 4) & 1) * 8;

    auto load_stage = [&](int s, int k0) {
        uint32_t st = sb + (uint32_t)s * G3_STG;
        #pragma unroll
        for (int q = 0; q < 4; q++) {
            int e = q * 256 + tid;
            int r = e >> 3, c = e & 7;
            const size_t so = (size_t)(m0 + r) * LL + k0 + c * 8;
            uint32_t doff = (r * GA_STR + c * 8) * 2;
            CP_A16(st + G3_AH + doff, Ah + so);
            CP_A16(st + G3_AL + doff, Al + so);
        }
        #pragma unroll
        for (int q = 0; q < 4; q++) {
            int e = q * 256 + tid;
            int r = e >> 4, c = e & 15;
            const size_t so = (size_t)(k0 + r) * CC + c * 8;
            uint32_t doff = (r * GB_STR + c * 8) * 2;
            CP_A16(st + G3_BH + doff, Bh + so);
            CP_A16(st + G3_BL + doff, Bl + so);
        }
    };

    load_stage(0, kbeg);
    CP_COMMIT();

    #pragma unroll 1
    for (int ci = 0; ci < 32; ci++) {
        if (ci < 31) { load_stage((ci + 1) & 1, kbeg + (ci + 1) * 64); CP_COMMIT(); }
        if (ci < 31) CP_WAIT(1); else CP_WAIT(0);
        __syncthreads();
        uint32_t st = sb + (uint32_t)(ci & 1) * G3_STG;

        #pragma unroll
        for (int ks = 0; ks < 4; ks++) {
            uint32_t ah[4][4], al[4][4], bh[2][4], bl[2][4];
            #pragma unroll
            for (int tm = 0; tm < 4; tm++) {
                uint32_t off = ((wm * 64 + tm * 16 + frow) * GA_STR + ks * 16 + fcol) * 2;
                LDM_X4(ah[tm][0], ah[tm][1], ah[tm][2], ah[tm][3], st + G3_AH + off);
                LDM_X4(al[tm][0], al[tm][1], al[tm][2], al[tm][3], st + G3_AL + off);
            }
            #pragma unroll
            for (int p = 0; p < 2; p++) {
                uint32_t off = ((ks * 16 + frow) * GB_STR + wn * 32 + p * 16 + fcol) * 2;
                LDM_X4T(bh[p][0], bh[p][1], bh[p][2], bh[p][3], st + G3_BH + off);
                LDM_X4T(bl[p][0], bl[p][1], bl[p][2], bl[p][3], st + G3_BL + off);
            }
            #pragma unroll
            for (int tm = 0; tm < 4; tm++) {
                #pragma unroll
                for (int tn = 0; tn < 4; tn++) {
                    int p = tn >> 1, h2 = (tn & 1) * 2;
                    MMA16816(acc[tm][tn], ah[tm], bh[p][h2], bh[p][h2 + 1]);
                    MMA16816(acc[tm][tn], ah[tm], bl[p][h2], bl[p][h2 + 1]);
                    MMA16816(acc[tm][tn], al[tm], bh[p][h2], bh[p][h2 + 1]);
                }
            }
        }
        __syncthreads();
    }

    float* ob = out + (size_t)b * LL * CC;
    #pragma unroll
    for (int tm = 0; tm < 4; tm++) {
        int row = m0 + wm * 64 + tm * 16 + (lane >> 2);
        #pragma unroll
        for (int tn = 0; tn < 4; tn++) {
            int col = wn * 32 + tn * 8 + (lane & 3) * 2;
            atomicAdd(&ob[(size_t)row * CC + col],           acc[tm][tn][0]);
            atomicAdd(&ob[(size_t)row * CC + col + 1],       acc[tm][tn][1]);
            atomicAdd(&ob[(size_t)(row + 8) * CC + col],     acc[tm][tn][2]);
            atomicAdd(&ob[(size_t)(row + 8) * CC + col + 1], acc[tm][tn][3]);
        }
    }
}

// ---------------- launcher ----------------
extern "C" void kernel_launch(void* const* d_in, const int* in_sizes, int n_in,
                              void* d_out, int out_size) {
    const float* x1 = (const float*)d_in[0];
    const float* x2 = (const float*)d_in[1];
    float* out = (float*)d_out;

    cudaFuncSetAttribute(k_gemm3_mma, cudaFuncAttributeMaxDynamicSharedMemorySize, G3_SMEM);
    cudaFuncSetAttribute(k_scores, cudaFuncAttributeMaxDynamicSharedMemorySize, SC_SMEM);
    cudaFuncSetAttribute(k_dgemm, cudaFuncAttributeMaxDynamicSharedMemorySize, DG_SMEM);

    k_pad  <<<(BN_ * AREA * 32 + 255) / 256, 256>>>(x2);
    dim3 gx((AREA + 31) / 32, CC / 32, BN_);
    k_xt   <<<gx, dim3(32, 8)>>>();
    k_split<<<(BN_ * LL * CC + 255) / 256, 256>>>(x1, out);
    k_rnorm<<<(BN_ * AREA * 32 + 255) / 256, 256>>>();
    k_nm   <<<(BN_ * LL + 255) / 256, 256>>>();

    dim3 gd(NBLK * (NBLK + 1) / 2, 1, BN_);
    k_dgemm<<<gd, 256, DG_SMEM>>>();

    dim3 gsc(64, 64, BN_);
    k_scores<<<gsc, 256, SC_SMEM>>>();

    dim3 gsm(LL, BN_);
    k_softmax<<<gsm, 256>>>();

    dim3 gw((LL * LL / 4) / 256, BN_);
    k_W2f<<<gw, 256>>>();

    dim3 gg(LL / 128, 2, BN_);
    k_gemm3_mma<<<gg, 256, G3_SMEM>>>(out);
}

// round 8
// speedup vs baseline: 2.5523x; 1.0467x over previous
#include <cuda_runtime.h>
#include <cuda_bf16.h>
#include <cstdint>

#define BN_  2
#define HH   64
#define WW   64
#define CC   128
#define HP   66
#define AREA 4356          // HP*HP
#define LL   4096          // HH*WW
#define NBLK 35            // ceil(AREA/128)

// ---------------- scratch (static device globals; no allocation) ----------------
__device__ float g_Xp2[BN_ * AREA * CC];              // x2 zero-padded [b][a][c]
__device__ float g_XT [BN_ * CC * AREA + 128];        // x2 padded, transposed [b][c][a]
__device__ float g_r  [BN_ * AREA];
__device__ float g_nm [BN_ * LL];
__device__ float g_D  [(size_t)BN_ * AREA * AREA + 128];
__device__ float g_S  [(size_t)BN_ * LL * LL];
__device__ float g_A  [(size_t)BN_ * LL * LL];
__device__ __nv_bfloat16 g_W2h[(size_t)BN_ * LL * LL];
__device__ __nv_bfloat16 g_W2l[(size_t)BN_ * LL * LL];
__device__ __nv_bfloat16 g_V1h[BN_ * LL * CC];
__device__ __nv_bfloat16 g_V1l[BN_ * LL * CC];

// ================= portable PTX helpers =================
__device__ __forceinline__ uint32_t smem_u32(const void* p) {
    uint32_t a;
    asm("{ .reg .u64 t; cvta.to.shared.u64 t, %1; cvt.u32.u64 %0, t; }" : "=r"(a) : "l"(p));
    return a;
}
#define CP_A16(dst, src) asm volatile("cp.async.cg.shared.global [%0], [%1], 16;" :: "r"(dst), "l"(src))
#define CP_COMMIT()      asm volatile("cp.async.commit_group;" ::: "memory")
#define CP_WAIT(n)       asm volatile("cp.async.wait_group %0;" :: "n"(n) : "memory")

#define LDM_X4(r0, r1, r2, r3, addr) \
    asm volatile("ldmatrix.sync.aligned.m8n8.x4.shared.b16 {%0,%1,%2,%3}, [%4];" \
        : "=r"(r0), "=r"(r1), "=r"(r2), "=r"(r3) : "r"(addr))
#define LDM_X4T(r0, r1, r2, r3, addr) \
    asm volatile("ldmatrix.sync.aligned.m8n8.x4.trans.shared.b16 {%0,%1,%2,%3}, [%4];" \
        : "=r"(r0), "=r"(r1), "=r"(r2), "=r"(r3) : "r"(addr))
#define MMA16816(d, a, b0v, b1v) \
    asm volatile("mma.sync.aligned.m16n8k16.row.col.f32.bf16.bf16.f32 " \
        "{%0,%1,%2,%3}, {%4,%5,%6,%7}, {%8,%9}, {%0,%1,%2,%3};" \
        : "+f"((d)[0]), "+f"((d)[1]), "+f"((d)[2]), "+f"((d)[3]) \
        : "r"((a)[0]), "r"((a)[1]), "r"((a)[2]), "r"((a)[3]), "r"(b0v), "r"(b1v))

// ---------------- pad x2 into [b, 66*66, 128] with zero border ----------------
__global__ void k_pad(const float* __restrict__ x2) {
    int idx = blockIdx.x * blockDim.x + threadIdx.x;
    if (idx >= BN_ * AREA * 32) return;
    int v = idx & 31;
    int a = (idx >> 5) % AREA;
    int b = idx / (AREA * 32);
    int ai = a / HP, aj = a % HP;
    float4 z2 = make_float4(0.f, 0.f, 0.f, 0.f);
    if (ai >= 1 && ai <= HH && aj >= 1 && aj <= WW) {
        int src = ((b * HH + (ai - 1)) * WW + (aj - 1)) * 32 + v;
        z2 = ((const float4*)x2)[src];
    }
    ((float4*)g_Xp2)[idx] = z2;
}

// ---------------- transpose Xp2 -> XT [b][c][a] ----------------
__global__ void k_xt() {
    __shared__ float t[32][33];
    int b = blockIdx.z;
    int a0 = blockIdx.x * 32, c0 = blockIdx.y * 32;
    int tx = threadIdx.x, ty = threadIdx.y;
    #pragma unroll
    for (int i = 0; i < 4; i++) {
        int r = ty + i * 8;
        if (a0 + r < AREA)
            t[r][tx] = g_Xp2[((size_t)b * AREA + a0 + r) * CC + c0 + tx];
    }
    __syncthreads();
    #pragma unroll
    for (int i = 0; i < 4; i++) {
        int r = ty + i * 8;
        if (a0 + tx < AREA)
            g_XT[((size_t)b * CC + c0 + r) * AREA + a0 + tx] = t[tx][r];
    }
}

// ---------------- split x1 into bf16 hi/lo + zero output ----------------
__global__ void k_split(const float* __restrict__ x1, float* __restrict__ out) {
    int idx = blockIdx.x * blockDim.x + threadIdx.x;
    if (idx >= BN_ * LL * CC) return;
    float v = x1[idx];
    __nv_bfloat16 h = __float2bfloat16(v);
    float lo = v - __bfloat162float(h);
    g_V1h[idx] = h;
    g_V1l[idx] = __float2bfloat16(lo);
    out[idx] = 0.f;
}

// ---------------- per-pixel squared norms of x2pad ----------------
__global__ void k_rnorm() {
    int gw = (blockIdx.x * blockDim.x + threadIdx.x) >> 5;
    int lane = threadIdx.x & 31;
    if (gw >= BN_ * AREA) return;
    const float4* p = ((const float4*)g_Xp2) + (size_t)gw * 32;
    float4 v = p[lane];
    float s = v.x * v.x + v.y * v.y + v.z * v.z + v.w * v.w;
    #pragma unroll
    for (int o = 16; o; o >>= 1) s += __shfl_xor_sync(0xffffffffu, s, o);
    if (!lane) g_r[gw] = s;
}

// ---------------- patch norms ----------------
__global__ void k_nm() {
    int idx = blockIdx.x * blockDim.x + threadIdx.x;
    if (idx >= BN_ * LL) return;
    int l = idx & (LL - 1), b = idx / LL;
    int li = l >> 6, lj = l & 63;
    const float* rb = g_r + b * AREA;
    float s = 0.f;
    #pragma unroll
    for (int dy = 0; dy < 3; dy++)
        #pragma unroll
        for (int dx = 0; dx < 3; dx++)
            s += rb[(li + dy) * HP + lj + dx];
    g_nm[idx] = 1.f / fmaxf(sqrtf(s), 1e-4f);
}

// ---------------- D = XT^T @ XT, symmetric, cp.async double-buffered ----------------
#define DG_STG 4224
#define DG_SMEM (2 * 2 * DG_STG * 4)
__global__ __launch_bounds__(256, 2) void k_dgemm() {
    extern __shared__ float dsm[];
    int rem = blockIdx.x;
    int bm = 0;
    while (rem >= NBLK - bm) { rem -= NBLK - bm; bm++; }
    int bn = bm + rem;
    int b = blockIdx.z;

    const float* __restrict__ XT = g_XT + (size_t)b * CC * AREA;
    float* __restrict__ Dp = g_D + (size_t)b * AREA * AREA;

    int tid = threadIdx.x;
    int m0 = bm * 128, n0 = bn * 128;
    int tx = tid & 15, ty = tid >> 4;
    float acc[8][8];
    #pragma unroll
    for (int i = 0; i < 8; i++)
        #pragma unroll
        for (int j = 0; j < 8; j++) acc[i][j] = 0.f;

    uint32_t sbase = smem_u32(dsm);

    auto load_stage = [&](int s, int kc) {
        uint32_t stA = sbase + (uint32_t)(2 * s) * DG_STG * 4;
        uint32_t stB = stA + DG_STG * 4;
        #pragma unroll
        for (int q = 0; q < 4; q++) {
            int e = q * 256 + tid;
            int r = e >> 5, c16 = e & 31;
            const float* srcA = XT + (size_t)(kc + r) * AREA + m0 + c16 * 4;
            const float* srcB = XT + (size_t)(kc + r) * AREA + n0 + c16 * 4;
            CP_A16(stA + (r * 132 + c16 * 4) * 4, srcA);
            CP_A16(stB + (r * 132 + c16 * 4) * 4, srcB);
        }
    };

    load_stage(0, 0);
    CP_COMMIT();

    #pragma unroll 1
    for (int ch = 0; ch < 4; ch++) {
        if (ch < 3) { load_stage((ch + 1) & 1, (ch + 1) * 32); CP_COMMIT(); }
        if (ch < 3) CP_WAIT(1); else CP_WAIT(0);
        __syncthreads();
        float (*As)[132] = (float(*)[132])(dsm + (size_t)(2 * (ch & 1)) * DG_STG);
        float (*Bs)[132] = (float(*)[132])(dsm + (size_t)(2 * (ch & 1)) * DG_STG + DG_STG);
        #pragma unroll 8
        for (int kk = 0; kk < 32; kk++) {
            float a[8], bv[8];
            #pragma unroll
            for (int i = 0; i < 4; i++) { a[i] = As[kk][ty * 4 + i]; a[4 + i] = As[kk][64 + ty * 4 + i]; }
            #pragma unroll
            for (int j = 0; j < 4; j++) { bv[j] = Bs[kk][tx * 4 + j]; bv[4 + j] = Bs[kk][64 + tx * 4 + j]; }
            #pragma unroll
            for (int i = 0; i < 8; i++)
                #pragma unroll
                for (int j = 0; j < 8; j++) acc[i][j] += a[i] * bv[j];
        }
        __syncthreads();
    }

    #pragma unroll
    for (int i = 0; i < 8; i++) {
        int ml = (i < 4) ? (ty * 4 + i) : (64 + ty * 4 + i - 4);
        int gm = m0 + ml;
        if (gm < AREA) {
            #pragma unroll
            for (int jh = 0; jh < 2; jh++) {
                int gn = n0 + ((jh == 0) ? (tx * 4) : (64 + tx * 4));
                if (gn < AREA) {
                    float4 v = make_float4(acc[i][jh * 4 + 0], acc[i][jh * 4 + 1],
                                           acc[i][jh * 4 + 2], acc[i][jh * 4 + 3]);
                    *(float4*)&Dp[(size_t)gm * AREA + gn] = v;
                }
            }
        }
    }

    if (bm == bn) return;

    __syncthreads();
    #pragma unroll
    for (int i = 0; i < 8; i++) {
        int ml = (i < 4) ? (ty * 4 + i) : (64 + ty * 4 + i - 4);
        #pragma unroll
        for (int j = 0; j < 8; j++) {
            int nl = (j < 4) ? (tx * 4 + j) : (64 + tx * 4 + j - 4);
            dsm[nl * 129 + ml] = acc[i][j];
        }
    }
    __syncthreads();
    #pragma unroll
    for (int q = 0; q < 16; q++) {
        int pos = q * 256 + tid;
        int r = pos >> 5, c4 = pos & 31;
        int gn = n0 + r, gm = m0 + c4 * 4;
        if (gn < AREA && gm < AREA) {
            float4 v = make_float4(dsm[r * 129 + c4 * 4 + 0], dsm[r * 129 + c4 * 4 + 1],
                                   dsm[r * 129 + c4 * 4 + 2], dsm[r * 129 + c4 * 4 + 3]);
            *(float4*)&Dp[(size_t)gn * AREA + gm] = v;
        }
    }
}

// ---------------- scores: diagonal-chained, rolling 4-slab ring ----------------
// diagonal d = xi - li; slab(u) = D[u*HP + r, (u-d)*HP - sh + c], sh = 2*((u-d)&1)
#define SD_CH 16
#define SD_RS 68
#define SD_SLAB (66 * SD_RS)         // floats
#define SD_SMEM (4 * SD_SLAB * 4)    // 71808 B
__global__ __launch_bounds__(256, 2) void k_scores() {
    extern __shared__ float dsm[];
    int d = (int)blockIdx.x - 63;     // -63..63
    int chunk = blockIdx.y;
    int b = blockIdx.z;
    int lo = d > 0 ? d : 0;
    int hi = d > 0 ? 63 : 63 + d;
    int xi0 = lo + chunk * SD_CH;
    if (xi0 > hi) return;
    int steps = hi - xi0 + 1; if (steps > SD_CH) steps = SD_CH;
    int tid = threadIdx.x;
    const float* __restrict__ Db = g_D + (size_t)b * AREA * AREA;
    uint32_t sbase = smem_u32(dsm);

    auto load_slab = [&](int u) {
        uint32_t dst = sbase + (uint32_t)(u & 3) * SD_SLAB * 4;
        int col = (u - d) * HP - (((u - d) & 1) ? 2 : 0);
        const float* src = Db + (size_t)(u * HP) * AREA + col;
        #pragma unroll
        for (int q = 0; q < 5; q++) {
            int e = q * 256 + tid;                // 66*17 = 1122 chunks
            if (e < 66 * 17) {
                int r = e / 17, c16 = e - r * 17;
                CP_A16(dst + (r * SD_RS + c16 * 4) * 4, src + (size_t)r * AREA + c16 * 4);
            }
        }
        CP_COMMIT();
    };

    load_slab(xi0); load_slab(xi0 + 1); load_slab(xi0 + 2);

    int lj = tid & 63, xb = tid >> 6;

    #pragma unroll 1
    for (int i = 0; i < steps; i++) {
        int xi = xi0 + i;
        int li = xi - d;
        if (i + 1 < steps) { load_slab(xi + 3); CP_WAIT(1); }
        else CP_WAIT(0);
        __syncthreads();
        int sh0 = (li & 1) ? 2 : 0;          // slabs xi (li), xi+2 (li+2): same parity
        int sh1 = 2 - sh0;                   // slab xi+1 (li+1)
        const float* s0 = dsm + (size_t)((xi + 0) & 3) * SD_SLAB + sh0;
        const float* s1 = dsm + (size_t)((xi + 1) & 3) * SD_SLAB + sh1;
        const float* s2 = dsm + (size_t)((xi + 2) & 3) * SD_SLAB + sh0;
        float iv = g_nm[b * LL + li * 64 + lj];
        float* So = g_S + (size_t)b * LL * LL + (size_t)(xi * 64) * LL + li * 64 + lj;
        #pragma unroll
        for (int q = 0; q < 16; q++) {
            int xj = xb + (q << 2);
            float s = 0.f;
            #pragma unroll
            for (int dx = 0; dx < 3; dx++) {
                int ro = (xj + dx) * SD_RS + lj + dx;
                s += s0[ro] + s1[ro] + s2[ro];
            }
            So[(size_t)xj * LL] = s * iv;
        }
        __syncthreads();
    }
}

// ---------------- 3x3 query pool + scale + row softmax, 8 x-rows per block ----------------
#define SM_XB 8
__global__ __launch_bounds__(256) void k_softmax() {
    __shared__ __align__(16) float row[LL];
    __shared__ float red[32];
    int b = blockIdx.y, xg = blockIdx.x;
    size_t base = (size_t)b * LL * LL;
    const float4* __restrict__ S4 = (const float4*)(g_S + base);
    int t = threadIdx.x;

    #pragma unroll 1
    for (int xs = 0; xs < SM_XB; xs++) {
        int x = xg * SM_XB + xs;
        int xi = x >> 6, xj = x & 63;
        float cy = (xi == 0 || xi == 63) ? 2.f : 3.f;
        float cx = (xj == 0 || xj == 63) ? 2.f : 3.f;
        float sc = 90.f / (cy * cx);

        int offs4[9]; int no = 0;
        #pragma unroll
        for (int dy = -1; dy <= 1; dy++)
            #pragma unroll
            for (int dx = -1; dx <= 1; dx++) {
                if (xi + dy >= 0 && xi + dy < HH && xj + dx >= 0 && xj + dx < WW)
                    offs4[no++] = (x + dy * 64 + dx) * (LL / 4);
            }

        float lmax = -1e30f;
        for (int l4 = t; l4 < LL / 4; l4 += 256) {
            float4 s = make_float4(0.f, 0.f, 0.f, 0.f);
            for (int o = 0; o < no; o++) {
                float4 v = __ldg(&S4[offs4[o] + l4]);
                s.x += v.x; s.y += v.y; s.z += v.z; s.w += v.w;
            }
            s.x *= sc; s.y *= sc; s.z *= sc; s.w *= sc;
            ((float4*)row)[l4] = s;
            lmax = fmaxf(fmaxf(fmaxf(lmax, s.x), fmaxf(s.y, s.z)), s.w);
        }
        #pragma unroll
        for (int o = 16; o; o >>= 1) lmax = fmaxf(lmax, __shfl_xor_sync(0xffffffffu, lmax, o));
        if ((t & 31) == 0) red[t >> 5] = lmax;
        __syncthreads();
        if (t < 32) {
            float v = (t < 8) ? red[t] : -1e30f;
            #pragma unroll
            for (int o = 4; o; o >>= 1) v = fmaxf(v, __shfl_xor_sync(0xffffffffu, v, o));
            if (!t) red[0] = v;
        }
        __syncthreads();
        float m = red[0];
        __syncthreads();
        float lsum = 0.f;
        for (int l4 = t; l4 < LL / 4; l4 += 256) {
            float4 s = ((float4*)row)[l4];
            s.x = __expf(s.x - m); s.y = __expf(s.y - m);
            s.z = __expf(s.z - m); s.w = __expf(s.w - m);
            ((float4*)row)[l4] = s;
            lsum += s.x + s.y + s.z + s.w;
        }
        #pragma unroll
        for (int o = 16; o; o >>= 1) lsum += __shfl_xor_sync(0xffffffffu, lsum, o);
        if ((t & 31) == 0) red[t >> 5] = lsum;
        __syncthreads();
        if (t < 32) {
            float v = (t < 8) ? red[t] : 0.f;
            #pragma unroll
            for (int o = 4; o; o >>= 1) v += __shfl_xor_sync(0xffffffffu, v, o);
            if (!t) red[0] = v;
        }
        __syncthreads();
        float inv = 1.f / red[0];
        float4* A4 = (float4*)(g_A + base + (size_t)x * LL);
        for (int l4 = t; l4 < LL / 4; l4 += 256) {
            float4 s = ((float4*)row)[l4];
            s.x *= inv; s.y *= inv; s.z *= inv; s.w *= inv;
            A4[l4] = s;
        }
        __syncthreads();
    }
}

// ---------------- diagonal 3x3 box filter → W2 hi/lo bf16, 16 x-rows per block ----------------
#define W2_XB 16
__global__ void k_W2f() {
    int b = blockIdx.y;
    int lq = blockIdx.x & 3;
    int xg = blockIdx.x >> 2;
    int l4 = lq * 256 + threadIdx.x;     // 0..1023
    int l0 = l4 << 2;
    int lj0 = l0 & 63;
    int li0b = l0 >> 6;
    const float* __restrict__ att = g_A + (size_t)b * LL * LL;

    #pragma unroll 1
    for (int xs = 0; xs < W2_XB; xs++) {
        int x = xg * W2_XB + xs;
        int h = x >> 6, w = x & 63;
        float s[4] = {0.f, 0.f, 0.f, 0.f};
        #pragma unroll
        for (int sy = 1; sy >= -1; sy--) {
            if ((unsigned)(h + sy) >= 64u || (unsigned)(li0b + sy) >= 64u) continue;
            #pragma unroll
            for (int sx = 1; sx >= -1; sx--) {
                if ((unsigned)(w + sx) >= 64u) continue;
                long u = sy * 64 + sx;
                const float* p = att + (size_t)(x + u) * LL + l0 + u;
                #pragma unroll
                for (int j = 0; j < 4; j++) {
                    if ((unsigned)(lj0 + j + sx) < 64u)
                        s[j] += __ldg(p + j);
                }
            }
        }
        size_t dst = (size_t)b * LL * LL + (size_t)x * LL + l0;
        float r0 = s[0] - __bfloat162float(__float2bfloat16(s[0]));
        float r1 = s[1] - __bfloat162float(__float2bfloat16(s[1]));
        float r2 = s[2] - __bfloat162float(__float2bfloat16(s[2]));
        float r3 = s[3] - __bfloat162float(__float2bfloat16(s[3]));
        __nv_bfloat162 h01(__float2bfloat16(s[0]), __float2bfloat16(s[1]));
        __nv_bfloat162 h23(__float2bfloat16(s[2]), __float2bfloat16(s[3]));
        __nv_bfloat162 l01(__float2bfloat16(r0), __float2bfloat16(r1));
        __nv_bfloat162 l23(__float2bfloat16(r2), __float2bfloat16(r3));
        *(__nv_bfloat162*)(g_W2h + dst)     = h01;
        *(__nv_bfloat162*)(g_W2h + dst + 2) = h23;
        *(__nv_bfloat162*)(g_W2l + dst)     = l01;
        *(__nv_bfloat162*)(g_W2l + dst + 2) = l23;
    }
}

// ---------------- y = W2 @ x1 via mma.sync bf16x3, cp.async double-buffered ----------------
#define GA_STR 72
#define GB_STR 136
#define G3_AH  0
#define G3_AL  (128 * GA_STR * 2)
#define G3_BH  (2 * 128 * GA_STR * 2)
#define G3_BL  (2 * 128 * GA_STR * 2 + 64 * GB_STR * 2)
#define G3_STG (2 * 128 * GA_STR * 2 + 2 * 64 * GB_STR * 2)
#define G3_SMEM (2 * G3_STG)

__global__ __launch_bounds__(256, 1) void k_gemm3_mma(float* __restrict__ out) {
    extern __shared__ __nv_bfloat16 sm[];
    int tid = threadIdx.x, lane = tid & 31, wid = tid >> 5;
    int wm = wid >> 2, wn = wid & 3;
    int m0 = blockIdx.x * 128;
    int kbeg = blockIdx.y * (LL / 2);
    int b = blockIdx.z;

    const __nv_bfloat16* __restrict__ Ah = g_W2h + (size_t)b * LL * LL;
    const __nv_bfloat16* __restrict__ Al = g_W2l + (size_t)b * LL * LL;
    const __nv_bfloat16* __restrict__ Bh = g_V1h + (size_t)b * LL * CC;
    const __nv_bfloat16* __restrict__ Bl = g_V1l + (size_t)b * LL * CC;

    uint32_t sb = smem_u32(sm);
    float acc[4][4][4];
    #pragma unroll
    for (int i = 0; i < 4; i++)
        #pragma unroll
        for (int j = 0; j < 4; j++)
            #pragma unroll
            for (int q = 0; q < 4; q++) acc[i][j][q] = 0.f;

    int frow = (lane & 7) + ((lane >> 3) & 1) * 8;
    int fcol = ((lane >> 4) & 1) * 8;

    auto load_stage = [&](int s, int k0) {
        uint32_t st = sb + (uint32_t)s * G3_STG;
        #pragma unroll
        for (int q = 0; q < 4; q++) {
            int e = q * 256 + tid;
            int r = e >> 3, c = e & 7;
            const size_t so = (size_t)(m0 + r) * LL + k0 + c * 8;
            uint32_t doff = (r * GA_STR + c * 8) * 2;
            CP_A16(st + G3_AH + doff, Ah + so);
            CP_A16(st + G3_AL + doff, Al + so);
        }
        #pragma unroll
        for (int q = 0; q < 4; q++) {
            int e = q * 256 + tid;
            int r = e >> 4, c = e & 15;
            const size_t so = (size_t)(k0 + r) * CC + c * 8;
            uint32_t doff = (r * GB_STR + c * 8) * 2;
            CP_A16(st + G3_BH + doff, Bh + so);
            CP_A16(st + G3_BL + doff, Bl + so);
        }
    };

    load_stage(0, kbeg);
    CP_COMMIT();

    #pragma unroll 1
    for (int ci = 0; ci < 32; ci++) {
        if (ci < 31) { load_stage((ci + 1) & 1, kbeg + (ci + 1) * 64); CP_COMMIT(); }
        if (ci < 31) CP_WAIT(1); else CP_WAIT(0);
        __syncthreads();
        uint32_t st = sb + (uint32_t)(ci & 1) * G3_STG;

        #pragma unroll
        for (int ks = 0; ks < 4; ks++) {
            uint32_t ah[4][4], al[4][4], bh[2][4], bl[2][4];
            #pragma unroll
            for (int tm = 0; tm < 4; tm++) {
                uint32_t off = ((wm * 64 + tm * 16 + frow) * GA_STR + ks * 16 + fcol) * 2;
                LDM_X4(ah[tm][0], ah[tm][1], ah[tm][2], ah[tm][3], st + G3_AH + off);
                LDM_X4(al[tm][0], al[tm][1], al[tm][2], al[tm][3], st + G3_AL + off);
            }
            #pragma unroll
            for (int p = 0; p < 2; p++) {
                uint32_t off = ((ks * 16 + frow) * GB_STR + wn * 32 + p * 16 + fcol) * 2;
                LDM_X4T(bh[p][0], bh[p][1], bh[p][2], bh[p][3], st + G3_BH + off);
                LDM_X4T(bl[p][0], bl[p][1], bl[p][2], bl[p][3], st + G3_BL + off);
            }
            #pragma unroll
            for (int tm = 0; tm < 4; tm++) {
                #pragma unroll
                for (int tn = 0; tn < 4; tn++) {
                    int p = tn >> 1, h2 = (tn & 1) * 2;
                    MMA16816(acc[tm][tn], ah[tm], bh[p][h2], bh[p][h2 + 1]);
                    MMA16816(acc[tm][tn], ah[tm], bl[p][h2], bl[p][h2 + 1]);
                    MMA16816(acc[tm][tn], al[tm], bh[p][h2], bh[p][h2 + 1]);
                }
            }
        }
        __syncthreads();
    }

    float* ob = out + (size_t)b * LL * CC;
    #pragma unroll
    for (int tm = 0; tm < 4; tm++) {
        int row = m0 + wm * 64 + tm * 16 + (lane >> 2);
        #pragma unroll
        for (int tn = 0; tn < 4; tn++) {
            int col = wn * 32 + tn * 8 + (lane & 3) * 2;
            atomicAdd(&ob[(size_t)row * CC + col],           acc[tm][tn][0]);
            atomicAdd(&ob[(size_t)row * CC + col + 1],       acc[tm][tn][1]);
            atomicAdd(&ob[(size_t)(row + 8) * CC + col],     acc[tm][tn][2]);
            atomicAdd(&ob[(size_t)(row + 8) * CC + col + 1], acc[tm][tn][3]);
        }
    }
}

// ---------------- launcher ----------------
extern "C" void kernel_launch(void* const* d_in, const int* in_sizes, int n_in,
                              void* d_out, int out_size) {
    const float* x1 = (const float*)d_in[0];
    const float* x2 = (const float*)d_in[1];
    float* out = (float*)d_out;

    cudaFuncSetAttribute(k_gemm3_mma, cudaFuncAttributeMaxDynamicSharedMemorySize, G3_SMEM);
    cudaFuncSetAttribute(k_scores, cudaFuncAttributeMaxDynamicSharedMemorySize, SD_SMEM);
    cudaFuncSetAttribute(k_dgemm, cudaFuncAttributeMaxDynamicSharedMemorySize, DG_SMEM);

    k_pad  <<<(BN_ * AREA * 32 + 255) / 256, 256>>>(x2);
    dim3 gx((AREA + 31) / 32, CC / 32, BN_);
    k_xt   <<<gx, dim3(32, 8)>>>();
    k_split<<<(BN_ * LL * CC + 255) / 256, 256>>>(x1, out);
    k_rnorm<<<(BN_ * AREA * 32 + 255) / 256, 256>>>();
    k_nm   <<<(BN_ * LL + 255) / 256, 256>>>();

    dim3 gd(NBLK * (NBLK + 1) / 2, 1, BN_);
    k_dgemm<<<gd, 256, DG_SMEM>>>();

    dim3 gsc(127, 4, BN_);
    k_scores<<<gsc, 256, SD_SMEM>>>();

    dim3 gsm(LL / SM_XB, BN_);
    k_softmax<<<gsm, 256>>>();

    dim3 gw((LL / W2_XB) * 4, BN_);
    k_W2f<<<gw, 256>>>();

    dim3 gg(LL / 128, 2, BN_);
    k_gemm3_mma<<<gg, 256, G3_SMEM>>>(out);
}

// round 9
// speedup vs baseline: 2.7914x; 1.0937x over previous
#include <cuda_runtime.h>
#include <cuda_bf16.h>
#include <cstdint>

#define BN_  2
#define HH   64
#define WW   64
#define CC   128
#define HP   66
#define AREA 4356          // HP*HP
#define LL   4096          // HH*WW
#define NBLK 35            // ceil(AREA/128)

// ---------------- scratch ----------------
__device__ float g_XT [BN_ * CC * AREA + 128];        // x2 padded, transposed [b][c][a]
__device__ float g_r  [BN_ * AREA];
__device__ float g_nm [BN_ * LL];
__device__ float g_D  [(size_t)BN_ * AREA * AREA + 128];
__device__ float g_S  [(size_t)BN_ * LL * LL];        // horizontally-pooled scores Sh
__device__ float g_A  [(size_t)BN_ * LL * LL];
__device__ __nv_bfloat16 g_W2h[(size_t)BN_ * LL * LL];
__device__ __nv_bfloat16 g_W2l[(size_t)BN_ * LL * LL];
__device__ __nv_bfloat16 g_V1h[BN_ * LL * CC];
__device__ __nv_bfloat16 g_V1l[BN_ * LL * CC];

// ================= portable PTX helpers =================
__device__ __forceinline__ uint32_t smem_u32(const void* p) {
    uint32_t a;
    asm("{ .reg .u64 t; cvta.to.shared.u64 t, %1; cvt.u32.u64 %0, t; }" : "=r"(a) : "l"(p));
    return a;
}
#define CP_A16(dst, src) asm volatile("cp.async.cg.shared.global [%0], [%1], 16;" :: "r"(dst), "l"(src))
#define CP_COMMIT()      asm volatile("cp.async.commit_group;" ::: "memory")
#define CP_WAIT(n)       asm volatile("cp.async.wait_group %0;" :: "n"(n) : "memory")

#define LDM_X4(r0, r1, r2, r3, addr) \
    asm volatile("ldmatrix.sync.aligned.m8n8.x4.shared.b16 {%0,%1,%2,%3}, [%4];" \
        : "=r"(r0), "=r"(r1), "=r"(r2), "=r"(r3) : "r"(addr))
#define LDM_X4T(r0, r1, r2, r3, addr) \
    asm volatile("ldmatrix.sync.aligned.m8n8.x4.trans.shared.b16 {%0,%1,%2,%3}, [%4];" \
        : "=r"(r0), "=r"(r1), "=r"(r2), "=r"(r3) : "r"(addr))
#define MMA16816(d, a, b0v, b1v) \
    asm volatile("mma.sync.aligned.m16n8k16.row.col.f32.bf16.bf16.f32 " \
        "{%0,%1,%2,%3}, {%4,%5,%6,%7}, {%8,%9}, {%0,%1,%2,%3};" \
        : "+f"((d)[0]), "+f"((d)[1]), "+f"((d)[2]), "+f"((d)[3]) \
        : "r"((a)[0]), "r"((a)[1]), "r"((a)[2]), "r"((a)[3]), "r"(b0v), "r"(b1v))

// ---------------- transpose x2 -> XT [b][c][a] (zero border inline) ----------------
__global__ void k_xt(const float* __restrict__ x2) {
    __shared__ float t[32][33];
    int b = blockIdx.z;
    int a0 = blockIdx.x * 32, c0 = blockIdx.y * 32;
    int tx = threadIdx.x, ty = threadIdx.y;
    #pragma unroll
    for (int i = 0; i < 4; i++) {
        int r = ty + i * 8;
        int a = a0 + r;
        if (a < AREA) {
            int ai = a / HP, aj = a % HP;
            float v = 0.f;
            if (ai >= 1 && ai <= HH && aj >= 1 && aj <= WW)
                v = x2[((size_t)(b * HH + ai - 1) * WW + aj - 1) * CC + c0 + tx];
            t[r][tx] = v;
        }
    }
    __syncthreads();
    #pragma unroll
    for (int i = 0; i < 4; i++) {
        int r = ty + i * 8;
        if (a0 + tx < AREA)
            g_XT[((size_t)b * CC + c0 + r) * AREA + a0 + tx] = t[tx][r];
    }
}

// ---------------- split x1 into bf16 hi/lo + zero output ----------------
__global__ void k_split(const float* __restrict__ x1, float* __restrict__ out) {
    int idx = blockIdx.x * blockDim.x + threadIdx.x;
    if (idx >= BN_ * LL * CC) return;
    float v = x1[idx];
    __nv_bfloat16 h = __float2bfloat16(v);
    float lo = v - __bfloat162float(h);
    g_V1h[idx] = h;
    g_V1l[idx] = __float2bfloat16(lo);
    out[idx] = 0.f;
}

// ---------------- per-pixel squared norms (reads x2 directly) ----------------
__global__ void k_rnorm(const float* __restrict__ x2) {
    int gw = (blockIdx.x * blockDim.x + threadIdx.x) >> 5;
    int lane = threadIdx.x & 31;
    if (gw >= BN_ * AREA) return;
    int a = gw % AREA, b = gw / AREA;
    int ai = a / HP, aj = a % HP;
    float s = 0.f;
    if (ai >= 1 && ai <= HH && aj >= 1 && aj <= WW) {
        const float4* p = (const float4*)(x2 + ((size_t)(b * HH + ai - 1) * WW + aj - 1) * CC);
        float4 v = p[lane];
        s = v.x * v.x + v.y * v.y + v.z * v.z + v.w * v.w;
        #pragma unroll
        for (int o = 16; o; o >>= 1) s += __shfl_xor_sync(0xffffffffu, s, o);
    }
    if (!lane) g_r[gw] = s;
}

// ---------------- patch norms ----------------
__global__ void k_nm() {
    int idx = blockIdx.x * blockDim.x + threadIdx.x;
    if (idx >= BN_ * LL) return;
    int l = idx & (LL - 1), b = idx / LL;
    int li = l >> 6, lj = l & 63;
    const float* rb = g_r + b * AREA;
    float s = 0.f;
    #pragma unroll
    for (int dy = 0; dy < 3; dy++)
        #pragma unroll
        for (int dx = 0; dx < 3; dx++)
            s += rb[(li + dy) * HP + lj + dx];
    g_nm[idx] = 1.f / fmaxf(sqrtf(s), 1e-4f);
}

// ---------------- D = XT^T @ XT, symmetric, cp.async double-buffered ----------------
#define DG_STG 4224
#define DG_SMEM (2 * 2 * DG_STG * 4)
__global__ __launch_bounds__(256, 2) void k_dgemm() {
    extern __shared__ float dsm[];
    int rem = blockIdx.x;
    int bm = 0;
    while (rem >= NBLK - bm) { rem -= NBLK - bm; bm++; }
    int bn = bm + rem;
    int b = blockIdx.z;

    const float* __restrict__ XT = g_XT + (size_t)b * CC * AREA;
    float* __restrict__ Dp = g_D + (size_t)b * AREA * AREA;

    int tid = threadIdx.x;
    int m0 = bm * 128, n0 = bn * 128;
    int tx = tid & 15, ty = tid >> 4;
    float acc[8][8];
    #pragma unroll
    for (int i = 0; i < 8; i++)
        #pragma unroll
        for (int j = 0; j < 8; j++) acc[i][j] = 0.f;

    uint32_t sbase = smem_u32(dsm);

    auto load_stage = [&](int s, int kc) {
        uint32_t stA = sbase + (uint32_t)(2 * s) * DG_STG * 4;
        uint32_t stB = stA + DG_STG * 4;
        #pragma unroll
        for (int q = 0; q < 4; q++) {
            int e = q * 256 + tid;
            int r = e >> 5, c16 = e & 31;
            const float* srcA = XT + (size_t)(kc + r) * AREA + m0 + c16 * 4;
            const float* srcB = XT + (size_t)(kc + r) * AREA + n0 + c16 * 4;
            CP_A16(stA + (r * 132 + c16 * 4) * 4, srcA);
            CP_A16(stB + (r * 132 + c16 * 4) * 4, srcB);
        }
    };

    load_stage(0, 0);
    CP_COMMIT();

    #pragma unroll 1
    for (int ch = 0; ch < 4; ch++) {
        if (ch < 3) { load_stage((ch + 1) & 1, (ch + 1) * 32); CP_COMMIT(); }
        if (ch < 3) CP_WAIT(1); else CP_WAIT(0);
        __syncthreads();
        float (*As)[132] = (float(*)[132])(dsm + (size_t)(2 * (ch & 1)) * DG_STG);
        float (*Bs)[132] = (float(*)[132])(dsm + (size_t)(2 * (ch & 1)) * DG_STG + DG_STG);
        #pragma unroll 8
        for (int kk = 0; kk < 32; kk++) {
            float a[8], bv[8];
            #pragma unroll
            for (int i = 0; i < 4; i++) { a[i] = As[kk][ty * 4 + i]; a[4 + i] = As[kk][64 + ty * 4 + i]; }
            #pragma unroll
            for (int j = 0; j < 4; j++) { bv[j] = Bs[kk][tx * 4 + j]; bv[4 + j] = Bs[kk][64 + tx * 4 + j]; }
            #pragma unroll
            for (int i = 0; i < 8; i++)
                #pragma unroll
                for (int j = 0; j < 8; j++) acc[i][j] += a[i] * bv[j];
        }
        __syncthreads();
    }

    #pragma unroll
    for (int i = 0; i < 8; i++) {
        int ml = (i < 4) ? (ty * 4 + i) : (64 + ty * 4 + i - 4);
        int gm = m0 + ml;
        if (gm < AREA) {
            #pragma unroll
            for (int jh = 0; jh < 2; jh++) {
                int gn = n0 + ((jh == 0) ? (tx * 4) : (64 + tx * 4));
                if (gn < AREA) {
                    float4 v = make_float4(acc[i][jh * 4 + 0], acc[i][jh * 4 + 1],
                                           acc[i][jh * 4 + 2], acc[i][jh * 4 + 3]);
                    *(float4*)&Dp[(size_t)gm * AREA + gn] = v;
                }
            }
        }
    }

    if (bm == bn) return;

    __syncthreads();
    #pragma unroll
    for (int i = 0; i < 8; i++) {
        int ml = (i < 4) ? (ty * 4 + i) : (64 + ty * 4 + i - 4);
        #pragma unroll
        for (int j = 0; j < 8; j++) {
            int nl = (j < 4) ? (tx * 4 + j) : (64 + tx * 4 + j - 4);
            dsm[nl * 129 + ml] = acc[i][j];
        }
    }
    __syncthreads();
    #pragma unroll
    for (int q = 0; q < 16; q++) {
        int pos = q * 256 + tid;
        int r = pos >> 5, c4 = pos & 31;
        int gn = n0 + r, gm = m0 + c4 * 4;
        if (gn < AREA && gm < AREA) {
            float4 v = make_float4(dsm[r * 129 + c4 * 4 + 0], dsm[r * 129 + c4 * 4 + 1],
                                   dsm[r * 129 + c4 * 4 + 2], dsm[r * 129 + c4 * 4 + 3]);
            *(float4*)&Dp[(size_t)gn * AREA + gm] = v;
        }
    }
}

// ---------------- scores: diagonal-chained + horizontal (xj) pooling fused ----------------
#define SD_CH 16
#define SD_RS 68
#define SD_SLAB (66 * SD_RS)
#define SD_POOL (64 * 65)
#define SD_SMEM ((4 * SD_SLAB + SD_POOL) * 4)   // 88448 B
__global__ __launch_bounds__(256, 2) void k_scores() {
    extern __shared__ float dsm[];
    float* pool = dsm + 4 * SD_SLAB;
    int d = (int)blockIdx.x - 63;
    int chunk = blockIdx.y;
    int b = blockIdx.z;
    int lo = d > 0 ? d : 0;
    int hi = d > 0 ? 63 : 63 + d;
    int xi0 = lo + chunk * SD_CH;
    if (xi0 > hi) return;
    int steps = hi - xi0 + 1; if (steps > SD_CH) steps = SD_CH;
    int tid = threadIdx.x;
    const float* __restrict__ Db = g_D + (size_t)b * AREA * AREA;
    uint32_t sbase = smem_u32(dsm);

    auto load_slab = [&](int u) {
        uint32_t dst = sbase + (uint32_t)(u & 3) * SD_SLAB * 4;
        int col = (u - d) * HP - (((u - d) & 1) ? 2 : 0);
        const float* src = Db + (size_t)(u * HP) * AREA + col;
        #pragma unroll
        for (int q = 0; q < 5; q++) {
            int e = q * 256 + tid;
            if (e < 66 * 17) {
                int r = e / 17, c16 = e - r * 17;
                CP_A16(dst + (r * SD_RS + c16 * 4) * 4, src + (size_t)r * AREA + c16 * 4);
            }
        }
        CP_COMMIT();
    };

    load_slab(xi0); load_slab(xi0 + 1); load_slab(xi0 + 2);

    int lj = tid & 63, xb = tid >> 6;

    #pragma unroll 1
    for (int i = 0; i < steps; i++) {
        int xi = xi0 + i;
        int li = xi - d;
        if (i + 1 < steps) { load_slab(xi + 3); CP_WAIT(1); }
        else CP_WAIT(0);
        __syncthreads();
        int sh0 = (li & 1) ? 2 : 0;
        int sh1 = 2 - sh0;
        const float* s0 = dsm + (size_t)((xi + 0) & 3) * SD_SLAB + sh0;
        const float* s1 = dsm + (size_t)((xi + 1) & 3) * SD_SLAB + sh1;
        const float* s2 = dsm + (size_t)((xi + 2) & 3) * SD_SLAB + sh0;
        #pragma unroll
        for (int q = 0; q < 16; q++) {
            int xj = xb + (q << 2);
            float s = 0.f;
            #pragma unroll
            for (int dx = 0; dx < 3; dx++) {
                int ro = (xj + dx) * SD_RS + lj + dx;
                s += s0[ro] + s1[ro] + s2[ro];
            }
            pool[xj * 65 + lj] = s;
        }
        __syncthreads();
        float iv = g_nm[b * LL + li * 64 + lj];
        float* So = g_S + (size_t)b * LL * LL + (size_t)(xi * 64) * LL + li * 64 + lj;
        #pragma unroll
        for (int q = 0; q < 16; q++) {
            int xj = xb + (q << 2);
            float p = pool[xj * 65 + lj];
            if (xj > 0)  p += pool[(xj - 1) * 65 + lj];
            if (xj < 63) p += pool[(xj + 1) * 65 + lj];
            So[(size_t)xj * LL] = p * iv;
        }
        __syncthreads();
    }
}

// ---------------- vertical 3-tap pool + scale + row softmax, 8 x-rows per block ----------------
#define SM_XB 8
__global__ __launch_bounds__(256) void k_softmax() {
    __shared__ __align__(16) float row[LL];
    __shared__ float red[32];
    int b = blockIdx.y, xg = blockIdx.x;
    size_t base = (size_t)b * LL * LL;
    const float4* __restrict__ S4 = (const float4*)(g_S + base);
    int t = threadIdx.x;

    #pragma unroll 1
    for (int xs = 0; xs < SM_XB; xs++) {
        int x = xg * SM_XB + xs;
        int xi = x >> 6, xj = x & 63;
        float cy = (xi == 0 || xi == 63) ? 2.f : 3.f;
        float cx = (xj == 0 || xj == 63) ? 2.f : 3.f;
        float sc = 90.f / (cy * cx);

        int offs4[3]; int no = 0;
        #pragma unroll
        for (int dy = -1; dy <= 1; dy++) {
            if (xi + dy >= 0 && xi + dy < HH)
                offs4[no++] = (x + dy * 64) * (LL / 4);
        }

        float lmax = -1e30f;
        for (int l4 = t; l4 < LL / 4; l4 += 256) {
            float4 s = make_float4(0.f, 0.f, 0.f, 0.f);
            for (int o = 0; o < no; o++) {
                float4 v = __ldg(&S4[offs4[o] + l4]);
                s.x += v.x; s.y += v.y; s.z += v.z; s.w += v.w;
            }
            s.x *= sc; s.y *= sc; s.z *= sc; s.w *= sc;
            ((float4*)row)[l4] = s;
            lmax = fmaxf(fmaxf(fmaxf(lmax, s.x), fmaxf(s.y, s.z)), s.w);
        }
        #pragma unroll
        for (int o = 16; o; o >>= 1) lmax = fmaxf(lmax, __shfl_xor_sync(0xffffffffu, lmax, o));
        if ((t & 31) == 0) red[t >> 5] = lmax;
        __syncthreads();
        if (t < 32) {
            float v = (t < 8) ? red[t] : -1e30f;
            #pragma unroll
            for (int o = 4; o; o >>= 1) v = fmaxf(v, __shfl_xor_sync(0xffffffffu, v, o));
            if (!t) red[0] = v;
        }
        __syncthreads();
        float m = red[0];
        __syncthreads();
        float lsum = 0.f;
        for (int l4 = t; l4 < LL / 4; l4 += 256) {
            float4 s = ((float4*)row)[l4];
            s.x = __expf(s.x - m); s.y = __expf(s.y - m);
            s.z = __expf(s.z - m); s.w = __expf(s.w - m);
            ((float4*)row)[l4] = s;
            lsum += s.x + s.y + s.z + s.w;
        }
        #pragma unroll
        for (int o = 16; o; o >>= 1) lsum += __shfl_xor_sync(0xffffffffu, lsum, o);
        if ((t & 31) == 0) red[t >> 5] = lsum;
        __syncthreads();
        if (t < 32) {
            float v = (t < 8) ? red[t] : 0.f;
            #pragma unroll
            for (int o = 4; o; o >>= 1) v += __shfl_xor_sync(0xffffffffu, v, o);
            if (!t) red[0] = v;
        }
        __syncthreads();
        float inv = 1.f / red[0];
        float4* A4 = (float4*)(g_A + base + (size_t)x * LL);
        for (int l4 = t; l4 < LL / 4; l4 += 256) {
            float4 s = ((float4*)row)[l4];
            s.x *= inv; s.y *= inv; s.z *= inv; s.w *= inv;
            A4[l4] = s;
        }
        __syncthreads();
    }
}

// ---------------- diagonal 3x3 box filter → W2 hi/lo bf16, 16 x-rows per block ----------------
#define W2_XB 16
__global__ void k_W2f() {
    int b = blockIdx.y;
    int lq = blockIdx.x & 3;
    int xg = blockIdx.x >> 2;
    int l4 = lq * 256 + threadIdx.x;
    int l0 = l4 << 2;
    int lj0 = l0 & 63;
    int li0b = l0 >> 6;
    const float* __restrict__ att = g_A + (size_t)b * LL * LL;

    #pragma unroll 1
    for (int xs = 0; xs < W2_XB; xs++) {
        int x = xg * W2_XB + xs;
        int h = x >> 6, w = x & 63;
        float s[4] = {0.f, 0.f, 0.f, 0.f};
        #pragma unroll
        for (int sy = 1; sy >= -1; sy--) {
            if ((unsigned)(h + sy) >= 64u || (unsigned)(li0b + sy) >= 64u) continue;
            #pragma unroll
            for (int sx = 1; sx >= -1; sx--) {
                if ((unsigned)(w + sx) >= 64u) continue;
                long u = sy * 64 + sx;
                const float* p = att + (size_t)(x + u) * LL + l0 + u;
                #pragma unroll
                for (int j = 0; j < 4; j++) {
                    if ((unsigned)(lj0 + j + sx) < 64u)
                        s[j] += __ldg(p + j);
                }
            }
        }
        size_t dst = (size_t)b * LL * LL + (size_t)x * LL + l0;
        float r0 = s[0] - __bfloat162float(__float2bfloat16(s[0]));
        float r1 = s[1] - __bfloat162float(__float2bfloat16(s[1]));
        float r2 = s[2] - __bfloat162float(__float2bfloat16(s[2]));
        float r3 = s[3] - __bfloat162float(__float2bfloat16(s[3]));
        __nv_bfloat162 h01(__float2bfloat16(s[0]), __float2bfloat16(s[1]));
        __nv_bfloat162 h23(__float2bfloat16(s[2]), __float2bfloat16(s[3]));
        __nv_bfloat162 l01(__float2bfloat16(r0), __float2bfloat16(r1));
        __nv_bfloat162 l23(__float2bfloat16(r2), __float2bfloat16(r3));
        *(__nv_bfloat162*)(g_W2h + dst)     = h01;
        *(__nv_bfloat162*)(g_W2h + dst + 2) = h23;
        *(__nv_bfloat162*)(g_W2l + dst)     = l01;
        *(__nv_bfloat162*)(g_W2l + dst + 2) = l23;
    }
}

// ---------------- y = W2 @ x1 via mma.sync bf16x3, cp.async double-buffered ----------------
#define GA_STR 72
#define GB_STR 136
#define G3_AH  0
#define G3_AL  (128 * GA_STR * 2)
#define G3_BH  (2 * 128 * GA_STR * 2)
#define G3_BL  (2 * 128 * GA_STR * 2 + 64 * GB_STR * 2)
#define G3_STG (2 * 128 * GA_STR * 2 + 2 * 64 * GB_STR * 2)
#define G3_SMEM (2 * G3_STG)

__global__ __launch_bounds__(256, 1) void k_gemm3_mma(float* __restrict__ out) {
    extern __shared__ __nv_bfloat16 sm[];
    int tid = threadIdx.x, lane = tid & 31, wid = tid >> 5;
    int wm = wid >> 2, wn = wid & 3;
    int m0 = blockIdx.x * 128;
    int kbeg = blockIdx.y * (LL / 2);
    int b = blockIdx.z;

    const __nv_bfloat16* __restrict__ Ah = g_W2h + (size_t)b * LL * LL;
    const __nv_bfloat16* __restrict__ Al = g_W2l + (size_t)b * LL * LL;
    const __nv_bfloat16* __restrict__ Bh = g_V1h + (size_t)b * LL * CC;
    const __nv_bfloat16* __restrict__ Bl = g_V1l + (size_t)b * LL * CC;

    uint32_t sb = smem_u32(sm);
    float acc[4][4][4];
    #pragma unroll
    for (int i = 0; i < 4; i++)
        #pragma unroll
        for (int j = 0; j < 4; j++)
            #pragma unroll
            for (int q = 0; q < 4; q++) acc[i][j][q] = 0.f;

    int frow = (lane & 7) + ((lane >> 3) & 1) * 8;
    int fcol = ((lane >> 4) & 1) * 8;

    auto load_stage = [&](int s, int k0) {
        uint32_t st = sb + (uint32_t)s * G3_STG;
        #pragma unroll
        for (int q = 0; q < 4; q++) {
            int e = q * 256 + tid;
            int r = e >> 3, c = e & 7;
            const size_t so = (size_t)(m0 + r) * LL + k0 + c * 8;
            uint32_t doff = (r * GA_STR + c * 8) * 2;
            CP_A16(st + G3_AH + doff, Ah + so);
            CP_A16(st + G3_AL + doff, Al + so);
        }
        #pragma unroll
        for (int q = 0; q < 4; q++) {
            int e = q * 256 + tid;
            int r = e >> 4, c = e & 15;
            const size_t so = (size_t)(k0 + r) * CC + c * 8;
            uint32_t doff = (r * GB_STR + c * 8) * 2;
            CP_A16(st + G3_BH + doff, Bh + so);
            CP_A16(st + G3_BL + doff, Bl + so);
        }
    };

    load_stage(0, kbeg);
    CP_COMMIT();

    #pragma unroll 1
    for (int ci = 0; ci < 32; ci++) {
        if (ci < 31) { load_stage((ci + 1) & 1, kbeg + (ci + 1) * 64); CP_COMMIT(); }
        if (ci < 31) CP_WAIT(1); else CP_WAIT(0);
        __syncthreads();
        uint32_t st = sb + (uint32_t)(ci & 1) * G3_STG;

        #pragma unroll
        for (int ks = 0; ks < 4; ks++) {
            uint32_t ah[4][4], al[4][4], bh[2][4], bl[2][4];
            #pragma unroll
            for (int tm = 0; tm < 4; tm++) {
                uint32_t off = ((wm * 64 + tm * 16 + frow) * GA_STR + ks * 16 + fcol) * 2;
                LDM_X4(ah[tm][0], ah[tm][1], ah[tm][2], ah[tm][3], st + G3_AH + off);
                LDM_X4(al[tm][0], al[tm][1], al[tm][2], al[tm][3], st + G3_AL + off);
            }
            #pragma unroll
            for (int p = 0; p < 2; p++) {
                uint32_t off = ((ks * 16 + frow) * GB_STR + wn * 32 + p * 16 + fcol) * 2;
                LDM_X4T(bh[p][0], bh[p][1], bh[p][2], bh[p][3], st + G3_BH + off);
                LDM_X4T(bl[p][0], bl[p][1], bl[p][2], bl[p][3], st + G3_BL + off);
            }
            #pragma unroll
            for (int tm = 0; tm < 4; tm++) {
                #pragma unroll
                for (int tn = 0; tn < 4; tn++) {
                    int p = tn >> 1, h2 = (tn & 1) * 2;
                    MMA16816(acc[tm][tn], ah[tm], bh[p][h2], bh[p][h2 + 1]);
                    MMA16816(acc[tm][tn], ah[tm], bl[p][h2], bl[p][h2 + 1]);
                    MMA16816(acc[tm][tn], al[tm], bh[p][h2], bh[p][h2 + 1]);
                }
            }
        }
        __syncthreads();
    }

    float* ob = out + (size_t)b * LL * CC;
    #pragma unroll
    for (int tm = 0; tm < 4; tm++) {
        int row = m0 + wm * 64 + tm * 16 + (lane >> 2);
        #pragma unroll
        for (int tn = 0; tn < 4; tn++) {
            int col = wn * 32 + tn * 8 + (lane & 3) * 2;
            atomicAdd(&ob[(size_t)row * CC + col],           acc[tm][tn][0]);
            atomicAdd(&ob[(size_t)row * CC + col + 1],       acc[tm][tn][1]);
            atomicAdd(&ob[(size_t)(row + 8) * CC + col],     acc[tm][tn][2]);
            atomicAdd(&ob[(size_t)(row + 8) * CC + col + 1], acc[tm][tn][3]);
        }
    }
}

// ---------------- launcher ----------------
extern "C" void kernel_launch(void* const* d_in, const int* in_sizes, int n_in,
                              void* d_out, int out_size) {
    const float* x1 = (const float*)d_in[0];
    const float* x2 = (const float*)d_in[1];
    float* out = (float*)d_out;

    cudaFuncSetAttribute(k_gemm3_mma, cudaFuncAttributeMaxDynamicSharedMemorySize, G3_SMEM);
    cudaFuncSetAttribute(k_scores, cudaFuncAttributeMaxDynamicSharedMemorySize, SD_SMEM);
    cudaFuncSetAttribute(k_dgemm, cudaFuncAttributeMaxDynamicSharedMemorySize, DG_SMEM);

    dim3 gx((AREA + 31) / 32, CC / 32, BN_);
    k_xt   <<<gx, dim3(32, 8)>>>(x2);
    k_split<<<(BN_ * LL * CC + 255) / 256, 256>>>(x1, out);
    k_rnorm<<<(BN_ * AREA * 32 + 255) / 256, 256>>>(x2);
    k_nm   <<<(BN_ * LL + 255) / 256, 256>>>();

    dim3 gd(NBLK * (NBLK + 1) / 2, 1, BN_);
    k_dgemm<<<gd, 256, DG_SMEM>>>();

    dim3 gsc(127, 4, BN_);
    k_scores<<<gsc, 256, SD_SMEM>>>();

    dim3 gsm(LL / SM_XB, BN_);
    k_softmax<<<gsm, 256>>>();

    dim3 gw((LL / W2_XB) * 4, BN_);
    k_W2f<<<gw, 256>>>();

    dim3 gg(LL / 128, 2, BN_);
    k_gemm3_mma<<<gg, 256, G3_SMEM>>>(out);
}

// round 10
// speedup vs baseline: 3.1315x; 1.1218x over previous
#include <cuda_runtime.h>
#include <cuda_bf16.h>
#include <cstdint>

#define BN_  2
#define HH   64
#define WW   64
#define CC   128
#define HP   66
#define AREA 4356          // HP*HP
#define LL   4096          // HH*WW
#define NBLK 35            // ceil(AREA/128)

// ---------------- scratch ----------------
__device__ float g_XT [BN_ * CC * AREA + 128];        // x2 padded, transposed [b][c][a]
__device__ float g_r  [BN_ * AREA];
__device__ float g_nm [BN_ * LL];
__device__ float g_D  [(size_t)BN_ * AREA * AREA + 128];
__device__ float g_S  [(size_t)BN_ * LL * LL];        // Sh scores; reused as Dh after softmax
__device__ float g_A  [(size_t)BN_ * LL * LL];
__device__ __nv_bfloat16 g_W2h[(size_t)BN_ * LL * LL];
__device__ __nv_bfloat16 g_W2l[(size_t)BN_ * LL * LL];
__device__ __nv_bfloat16 g_V1h[BN_ * LL * CC];
__device__ __nv_bfloat16 g_V1l[BN_ * LL * CC];

// ================= portable PTX helpers =================
__device__ __forceinline__ uint32_t smem_u32(const void* p) {
    uint32_t a;
    asm("{ .reg .u64 t; cvta.to.shared.u64 t, %1; cvt.u32.u64 %0, t; }" : "=r"(a) : "l"(p));
    return a;
}
#define CP_A16(dst, src) asm volatile("cp.async.cg.shared.global [%0], [%1], 16;" :: "r"(dst), "l"(src))
#define CP_COMMIT()      asm volatile("cp.async.commit_group;" ::: "memory")
#define CP_WAIT(n)       asm volatile("cp.async.wait_group %0;" :: "n"(n) : "memory")

#define LDM_X4(r0, r1, r2, r3, addr) \
    asm volatile("ldmatrix.sync.aligned.m8n8.x4.shared.b16 {%0,%1,%2,%3}, [%4];" \
        : "=r"(r0), "=r"(r1), "=r"(r2), "=r"(r3) : "r"(addr))
#define LDM_X4T(r0, r1, r2, r3, addr) \
    asm volatile("ldmatrix.sync.aligned.m8n8.x4.trans.shared.b16 {%0,%1,%2,%3}, [%4];" \
        : "=r"(r0), "=r"(r1), "=r"(r2), "=r"(r3) : "r"(addr))
#define MMA16816(d, a, b0v, b1v) \
    asm volatile("mma.sync.aligned.m16n8k16.row.col.f32.bf16.bf16.f32 " \
        "{%0,%1,%2,%3}, {%4,%5,%6,%7}, {%8,%9}, {%0,%1,%2,%3};" \
        : "+f"((d)[0]), "+f"((d)[1]), "+f"((d)[2]), "+f"((d)[3]) \
        : "r"((a)[0]), "r"((a)[1]), "r"((a)[2]), "r"((a)[3]), "r"(b0v), "r"(b1v))

// ---------------- transpose x2 -> XT [b][c][a] (zero border inline) ----------------
__global__ void k_xt(const float* __restrict__ x2) {
    __shared__ float t[32][33];
    int b = blockIdx.z;
    int a0 = blockIdx.x * 32, c0 = blockIdx.y * 32;
    int tx = threadIdx.x, ty = threadIdx.y;
    #pragma unroll
    for (int i = 0; i < 4; i++) {
        int r = ty + i * 8;
        int a = a0 + r;
        if (a < AREA) {
            int ai = a / HP, aj = a % HP;
            float v = 0.f;
            if (ai >= 1 && ai <= HH && aj >= 1 && aj <= WW)
                v = x2[((size_t)(b * HH + ai - 1) * WW + aj - 1) * CC + c0 + tx];
            t[r][tx] = v;
        }
    }
    __syncthreads();
    #pragma unroll
    for (int i = 0; i < 4; i++) {
        int r = ty + i * 8;
        if (a0 + tx < AREA)
            g_XT[((size_t)b * CC + c0 + r) * AREA + a0 + tx] = t[tx][r];
    }
}

// ---------------- split x1 into bf16 hi/lo + zero output ----------------
__global__ void k_split(const float* __restrict__ x1, float* __restrict__ out) {
    int idx = blockIdx.x * blockDim.x + threadIdx.x;
    if (idx >= BN_ * LL * CC) return;
    float v = x1[idx];
    __nv_bfloat16 h = __float2bfloat16(v);
    float lo = v - __bfloat162float(h);
    g_V1h[idx] = h;
    g_V1l[idx] = __float2bfloat16(lo);
    out[idx] = 0.f;
}

// ---------------- per-pixel squared norms (reads x2 directly) ----------------
__global__ void k_rnorm(const float* __restrict__ x2) {
    int gw = (blockIdx.x * blockDim.x + threadIdx.x) >> 5;
    int lane = threadIdx.x & 31;
    if (gw >= BN_ * AREA) return;
    int a = gw % AREA, b = gw / AREA;
    int ai = a / HP, aj = a % HP;
    float s = 0.f;
    if (ai >= 1 && ai <= HH && aj >= 1 && aj <= WW) {
        const float4* p = (const float4*)(x2 + ((size_t)(b * HH + ai - 1) * WW + aj - 1) * CC);
        float4 v = p[lane];
        s = v.x * v.x + v.y * v.y + v.z * v.z + v.w * v.w;
        #pragma unroll
        for (int o = 16; o; o >>= 1) s += __shfl_xor_sync(0xffffffffu, s, o);
    }
    if (!lane) g_r[gw] = s;
}

// ---------------- patch norms ----------------
__global__ void k_nm() {
    int idx = blockIdx.x * blockDim.x + threadIdx.x;
    if (idx >= BN_ * LL) return;
    int l = idx & (LL - 1), b = idx / LL;
    int li = l >> 6, lj = l & 63;
    const float* rb = g_r + b * AREA;
    float s = 0.f;
    #pragma unroll
    for (int dy = 0; dy < 3; dy++)
        #pragma unroll
        for (int dx = 0; dx < 3; dx++)
            s += rb[(li + dy) * HP + lj + dx];
    g_nm[idx] = 1.f / fmaxf(sqrtf(s), 1e-4f);
}

// ---------------- D = XT^T @ XT, symmetric, cp.async double-buffered ----------------
#define DG_STG 4224
#define DG_SMEM (2 * 2 * DG_STG * 4)
__global__ __launch_bounds__(256, 2) void k_dgemm() {
    extern __shared__ float dsm[];
    int rem = blockIdx.x;
    int bm = 0;
    while (rem >= NBLK - bm) { rem -= NBLK - bm; bm++; }
    int bn = bm + rem;
    int b = blockIdx.z;

    const float* __restrict__ XT = g_XT + (size_t)b * CC * AREA;
    float* __restrict__ Dp = g_D + (size_t)b * AREA * AREA;

    int tid = threadIdx.x;
    int m0 = bm * 128, n0 = bn * 128;
    int tx = tid & 15, ty = tid >> 4;
    float acc[8][8];
    #pragma unroll
    for (int i = 0; i < 8; i++)
        #pragma unroll
        for (int j = 0; j < 8; j++) acc[i][j] = 0.f;

    uint32_t sbase = smem_u32(dsm);

    auto load_stage = [&](int s, int kc) {
        uint32_t stA = sbase + (uint32_t)(2 * s) * DG_STG * 4;
        uint32_t stB = stA + DG_STG * 4;
        #pragma unroll
        for (int q = 0; q < 4; q++) {
            int e = q * 256 + tid;
            int r = e >> 5, c16 = e & 31;
            const float* srcA = XT + (size_t)(kc + r) * AREA + m0 + c16 * 4;
            const float* srcB = XT + (size_t)(kc + r) * AREA + n0 + c16 * 4;
            CP_A16(stA + (r * 132 + c16 * 4) * 4, srcA);
            CP_A16(stB + (r * 132 + c16 * 4) * 4, srcB);
        }
    };

    load_stage(0, 0);
    CP_COMMIT();

    #pragma unroll 1
    for (int ch = 0; ch < 4; ch++) {
        if (ch < 3) { load_stage((ch + 1) & 1, (ch + 1) * 32); CP_COMMIT(); }
        if (ch < 3) CP_WAIT(1); else CP_WAIT(0);
        __syncthreads();
        float (*As)[132] = (float(*)[132])(dsm + (size_t)(2 * (ch & 1)) * DG_STG);
        float (*Bs)[132] = (float(*)[132])(dsm + (size_t)(2 * (ch & 1)) * DG_STG + DG_STG);
        #pragma unroll 8
        for (int kk = 0; kk < 32; kk++) {
            float a[8], bv[8];
            #pragma unroll
            for (int i = 0; i < 4; i++) { a[i] = As[kk][ty * 4 + i]; a[4 + i] = As[kk][64 + ty * 4 + i]; }
            #pragma unroll
            for (int j = 0; j < 4; j++) { bv[j] = Bs[kk][tx * 4 + j]; bv[4 + j] = Bs[kk][64 + tx * 4 + j]; }
            #pragma unroll
            for (int i = 0; i < 8; i++)
                #pragma unroll
                for (int j = 0; j < 8; j++) acc[i][j] += a[i] * bv[j];
        }
        __syncthreads();
    }

    #pragma unroll
    for (int i = 0; i < 8; i++) {
        int ml = (i < 4) ? (ty * 4 + i) : (64 + ty * 4 + i - 4);
        int gm = m0 + ml;
        if (gm < AREA) {
            #pragma unroll
            for (int jh = 0; jh < 2; jh++) {
                int gn = n0 + ((jh == 0) ? (tx * 4) : (64 + tx * 4));
                if (gn < AREA) {
                    float4 v = make_float4(acc[i][jh * 4 + 0], acc[i][jh * 4 + 1],
                                           acc[i][jh * 4 + 2], acc[i][jh * 4 + 3]);
                    *(float4*)&Dp[(size_t)gm * AREA + gn] = v;
                }
            }
        }
    }

    if (bm == bn) return;

    __syncthreads();
    #pragma unroll
    for (int i = 0; i < 8; i++) {
        int ml = (i < 4) ? (ty * 4 + i) : (64 + ty * 4 + i - 4);
        #pragma unroll
        for (int j = 0; j < 8; j++) {
            int nl = (j < 4) ? (tx * 4 + j) : (64 + tx * 4 + j - 4);
            dsm[nl * 129 + ml] = acc[i][j];
        }
    }
    __syncthreads();
    #pragma unroll
    for (int q = 0; q < 16; q++) {
        int pos = q * 256 + tid;
        int r = pos >> 5, c4 = pos & 31;
        int gn = n0 + r, gm = m0 + c4 * 4;
        if (gn < AREA && gm < AREA) {
            float4 v = make_float4(dsm[r * 129 + c4 * 4 + 0], dsm[r * 129 + c4 * 4 + 1],
                                   dsm[r * 129 + c4 * 4 + 2], dsm[r * 129 + c4 * 4 + 3]);
            *(float4*)&Dp[(size_t)gn * AREA + gm] = v;
        }
    }
}

// ---------------- scores: diagonal-chained + horizontal (xj) pooling fused ----------------
#define SD_CH 16
#define SD_RS 68
#define SD_SLAB (66 * SD_RS)
#define SD_POOL (64 * 65)
#define SD_SMEM ((4 * SD_SLAB + SD_POOL) * 4)
__global__ __launch_bounds__(256, 2) void k_scores() {
    extern __shared__ float dsm[];
    float* pool = dsm + 4 * SD_SLAB;
    int d = (int)blockIdx.x - 63;
    int chunk = blockIdx.y;
    int b = blockIdx.z;
    int lo = d > 0 ? d : 0;
    int hi = d > 0 ? 63 : 63 + d;
    int xi0 = lo + chunk * SD_CH;
    if (xi0 > hi) return;
    int steps = hi - xi0 + 1; if (steps > SD_CH) steps = SD_CH;
    int tid = threadIdx.x;
    const float* __restrict__ Db = g_D + (size_t)b * AREA * AREA;
    uint32_t sbase = smem_u32(dsm);

    auto load_slab = [&](int u) {
        uint32_t dst = sbase + (uint32_t)(u & 3) * SD_SLAB * 4;
        int col = (u - d) * HP - (((u - d) & 1) ? 2 : 0);
        const float* src = Db + (size_t)(u * HP) * AREA + col;
        #pragma unroll
        for (int q = 0; q < 5; q++) {
            int e = q * 256 + tid;
            if (e < 66 * 17) {
                int r = e / 17, c16 = e - r * 17;
                CP_A16(dst + (r * SD_RS + c16 * 4) * 4, src + (size_t)r * AREA + c16 * 4);
            }
        }
        CP_COMMIT();
    };

    load_slab(xi0); load_slab(xi0 + 1); load_slab(xi0 + 2);

    int lj = tid & 63, xb = tid >> 6;

    #pragma unroll 1
    for (int i = 0; i < steps; i++) {
        int xi = xi0 + i;
        int li = xi - d;
        if (i + 1 < steps) { load_slab(xi + 3); CP_WAIT(1); }
        else CP_WAIT(0);
        __syncthreads();
        int sh0 = (li & 1) ? 2 : 0;
        int sh1 = 2 - sh0;
        const float* s0 = dsm + (size_t)((xi + 0) & 3) * SD_SLAB + sh0;
        const float* s1 = dsm + (size_t)((xi + 1) & 3) * SD_SLAB + sh1;
        const float* s2 = dsm + (size_t)((xi + 2) & 3) * SD_SLAB + sh0;
        #pragma unroll
        for (int q = 0; q < 16; q++) {
            int xj = xb + (q << 2);
            float s = 0.f;
            #pragma unroll
            for (int dx = 0; dx < 3; dx++) {
                int ro = (xj + dx) * SD_RS + lj + dx;
                s += s0[ro] + s1[ro] + s2[ro];
            }
            pool[xj * 65 + lj] = s;
        }
        __syncthreads();
        float iv = g_nm[b * LL + li * 64 + lj];
        float* So = g_S + (size_t)b * LL * LL + (size_t)(xi * 64) * LL + li * 64 + lj;
        #pragma unroll
        for (int q = 0; q < 16; q++) {
            int xj = xb + (q << 2);
            float p = pool[xj * 65 + lj];
            if (xj > 0)  p += pool[(xj - 1) * 65 + lj];
            if (xj < 63) p += pool[(xj + 1) * 65 + lj];
            So[(size_t)xj * LL] = p * iv;
        }
        __syncthreads();
    }
}

// ---------------- vertical 3-tap pool + scale + row softmax, 8 x-rows per block ----------------
#define SM_XB 8
__global__ __launch_bounds__(256) void k_softmax() {
    __shared__ __align__(16) float row[LL];
    __shared__ float red[32];
    int b = blockIdx.y, xg = blockIdx.x;
    size_t base = (size_t)b * LL * LL;
    const float4* __restrict__ S4 = (const float4*)(g_S + base);
    int t = threadIdx.x;

    #pragma unroll 1
    for (int xs = 0; xs < SM_XB; xs++) {
        int x = xg * SM_XB + xs;
        int xi = x >> 6, xj = x & 63;
        float cy = (xi == 0 || xi == 63) ? 2.f : 3.f;
        float cx = (xj == 0 || xj == 63) ? 2.f : 3.f;
        float sc = 90.f / (cy * cx);

        int offs4[3]; int no = 0;
        #pragma unroll
        for (int dy = -1; dy <= 1; dy++) {
            if (xi + dy >= 0 && xi + dy < HH)
                offs4[no++] = (x + dy * 64) * (LL / 4);
        }

        float lmax = -1e30f;
        for (int l4 = t; l4 < LL / 4; l4 += 256) {
            float4 s = make_float4(0.f, 0.f, 0.f, 0.f);
            for (int o = 0; o < no; o++) {
                float4 v = __ldg(&S4[offs4[o] + l4]);
                s.x += v.x; s.y += v.y; s.z += v.z; s.w += v.w;
            }
            s.x *= sc; s.y *= sc; s.z *= sc; s.w *= sc;
            ((float4*)row)[l4] = s;
            lmax = fmaxf(fmaxf(fmaxf(lmax, s.x), fmaxf(s.y, s.z)), s.w);
        }
        #pragma unroll
        for (int o = 16; o; o >>= 1) lmax = fmaxf(lmax, __shfl_xor_sync(0xffffffffu, lmax, o));
        if ((t & 31) == 0) red[t >> 5] = lmax;
        __syncthreads();
        if (t < 32) {
            float v = (t < 8) ? red[t] : -1e30f;
            #pragma unroll
            for (int o = 4; o; o >>= 1) v = fmaxf(v, __shfl_xor_sync(0xffffffffu, v, o));
            if (!t) red[0] = v;
        }
        __syncthreads();
        float m = red[0];
        __syncthreads();
        float lsum = 0.f;
        for (int l4 = t; l4 < LL / 4; l4 += 256) {
            float4 s = ((float4*)row)[l4];
            s.x = __expf(s.x - m); s.y = __expf(s.y - m);
            s.z = __expf(s.z - m); s.w = __expf(s.w - m);
            ((float4*)row)[l4] = s;
            lsum += s.x + s.y + s.z + s.w;
        }
        #pragma unroll
        for (int o = 16; o; o >>= 1) lsum += __shfl_xor_sync(0xffffffffu, lsum, o);
        if ((t & 31) == 0) red[t >> 5] = lsum;
        __syncthreads();
        if (t < 32) {
            float v = (t < 8) ? red[t] : 0.f;
            #pragma unroll
            for (int o = 4; o; o >>= 1) v += __shfl_xor_sync(0xffffffffu, v, o);
            if (!t) red[0] = v;
        }
        __syncthreads();
        float inv = 1.f / red[0];
        float4* A4 = (float4*)(g_A + base + (size_t)x * LL);
        for (int l4 = t; l4 < LL / 4; l4 += 256) {
            float4 s = ((float4*)row)[l4];
            s.x *= inv; s.y *= inv; s.z *= inv; s.w *= inv;
            A4[l4] = s;
        }
        __syncthreads();
    }
}

// ---------------- W2 pass 1: horizontal diag, Dh[x,l] = sum_sx att[x+sx, l+sx] → g_S ----------------
#define DH_XB 16
__global__ void k_dh() {
    int b = blockIdx.y;
    int lq = blockIdx.x & 3;
    int xg = blockIdx.x >> 2;
    int l0 = (lq * 256 + threadIdx.x) << 2;
    int lj0 = l0 & 63;
    const float* __restrict__ att = g_A + (size_t)b * LL * LL;
    float* __restrict__ Dh = g_S + (size_t)b * LL * LL;

    #pragma unroll 1
    for (int xs = 0; xs < DH_XB; xs++) {
        int x = xg * DH_XB + xs;
        int w = x & 63;
        float s[4] = {0.f, 0.f, 0.f, 0.f};
        #pragma unroll
        for (int sx = -1; sx <= 1; sx++) {
            if ((unsigned)(w + sx) >= 64u) continue;
            const float* p = att + (size_t)(x + sx) * LL + l0 + sx;
            #pragma unroll
            for (int j = 0; j < 4; j++) {
                if ((unsigned)(lj0 + j + sx) < 64u)
                    s[j] += __ldg(p + j);
            }
        }
        *(float4*)(Dh + (size_t)x * LL + l0) = make_float4(s[0], s[1], s[2], s[3]);
    }
}

// ---------------- W2 pass 2: vertical diag, W2 = sum_sy Dh[x+64sy, l+64sy] → bf16 hi/lo ----------------
#define DV_XB 16
__global__ void k_dv() {
    int b = blockIdx.y;
    int lq = blockIdx.x & 3;
    int xg = blockIdx.x >> 2;
    int l0 = (lq * 256 + threadIdx.x) << 2;
    int li0 = l0 >> 6;
    const float* __restrict__ Dh = g_S + (size_t)b * LL * LL;

    #pragma unroll 1
    for (int xs = 0; xs < DV_XB; xs++) {
        int x = xg * DV_XB + xs;
        int h = x >> 6;
        float4 s = make_float4(0.f, 0.f, 0.f, 0.f);
        #pragma unroll
        for (int sy = -1; sy <= 1; sy++) {
            if ((unsigned)(h + sy) >= 64u || (unsigned)(li0 + sy) >= 64u) continue;
            float4 v = *(const float4*)(Dh + (size_t)(x + sy * 64) * LL + l0 + sy * 64);
            s.x += v.x; s.y += v.y; s.z += v.z; s.w += v.w;
        }
        size_t dst = (size_t)b * LL * LL + (size_t)x * LL + l0;
        float r0 = s.x - __bfloat162float(__float2bfloat16(s.x));
        float r1 = s.y - __bfloat162float(__float2bfloat16(s.y));
        float r2 = s.z - __bfloat162float(__float2bfloat16(s.z));
        float r3 = s.w - __bfloat162float(__float2bfloat16(s.w));
        __nv_bfloat162 h01(__float2bfloat16(s.x), __float2bfloat16(s.y));
        __nv_bfloat162 h23(__float2bfloat16(s.z), __float2bfloat16(s.w));
        __nv_bfloat162 l01(__float2bfloat16(r0), __float2bfloat16(r1));
        __nv_bfloat162 l23(__float2bfloat16(r2), __float2bfloat16(r3));
        *(__nv_bfloat162*)(g_W2h + dst)     = h01;
        *(__nv_bfloat162*)(g_W2h + dst + 2) = h23;
        *(__nv_bfloat162*)(g_W2l + dst)     = l01;
        *(__nv_bfloat162*)(g_W2l + dst + 2) = l23;
    }
}

// ---------------- y = W2 @ x1 via mma.sync bf16x3, cp.async double-buffered ----------------
#define GA_STR 72
#define GB_STR 136
#define G3_AH  0
#define G3_AL  (128 * GA_STR * 2)
#define G3_BH  (2 * 128 * GA_STR * 2)
#define G3_BL  (2 * 128 * GA_STR * 2 + 64 * GB_STR * 2)
#define G3_STG (2 * 128 * GA_STR * 2 + 2 * 64 * GB_STR * 2)
#define G3_SMEM (2 * G3_STG)

__global__ __launch_bounds__(256, 1) void k_gemm3_mma(float* __restrict__ out) {
    extern __shared__ __nv_bfloat16 sm[];
    int tid = threadIdx.x, lane = tid & 31, wid = tid >> 5;
    int wm = wid >> 2, wn = wid & 3;
    int m0 = blockIdx.x * 128;
    int kbeg = blockIdx.y * (LL / 2);
    int b = blockIdx.z;

    const __nv_bfloat16* __restrict__ Ah = g_W2h + (size_t)b * LL * LL;
    const __nv_bfloat16* __restrict__ Al = g_W2l + (size_t)b * LL * LL;
    const __nv_bfloat16* __restrict__ Bh = g_V1h + (size_t)b * LL * CC;
    const __nv_bfloat16* __restrict__ Bl = g_V1l + (size_t)b * LL * CC;

    uint32_t sb = smem_u32(sm);
    float acc[4][4][4];
    #pragma unroll
    for (int i = 0; i < 4; i++)
        #pragma unroll
        for (int j = 0; j < 4; j++)
            #pragma unroll
            for (int q = 0; q < 4; q++) acc[i][j][q] = 0.f;

    int frow = (lane & 7) + ((lane >> 3) & 1) * 8;
    int fcol = ((lane >> 4) & 1) * 8;

    auto load_stage = [&](int s, int k0) {
        uint32_t st = sb + (uint32_t)s * G3_STG;
        #pragma unroll
        for (int q = 0; q < 4; q++) {
            int e = q * 256 + tid;
            int r = e >> 3, c = e & 7;
            const size_t so = (size_t)(m0 + r) * LL + k0 + c * 8;
            uint32_t doff = (r * GA_STR + c * 8) * 2;
            CP_A16(st + G3_AH + doff, Ah + so);
            CP_A16(st + G3_AL + doff, Al + so);
        }
        #pragma unroll
        for (int q = 0; q < 4; q++) {
            int e = q * 256 + tid;
            int r = e >> 4, c = e & 15;
            const size_t so = (size_t)(k0 + r) * CC + c * 8;
            uint32_t doff = (r * GB_STR + c * 8) * 2;
            CP_A16(st + G3_BH + doff, Bh + so);
            CP_A16(st + G3_BL + doff, Bl + so);
        }
    };

    load_stage(0, kbeg);
    CP_COMMIT();

    #pragma unroll 1
    for (int ci = 0; ci < 32; ci++) {
        if (ci < 31) { load_stage((ci + 1) & 1, kbeg + (ci + 1) * 64); CP_COMMIT(); }
        if (ci < 31) CP_WAIT(1); else CP_WAIT(0);
        __syncthreads();
        uint32_t st = sb + (uint32_t)(ci & 1) * G3_STG;

        #pragma unroll
        for (int ks = 0; ks < 4; ks++) {
            uint32_t ah[4][4], al[4][4], bh[2][4], bl[2][4];
            #pragma unroll
            for (int tm = 0; tm < 4; tm++) {
                uint32_t off = ((wm * 64 + tm * 16 + frow) * GA_STR + ks * 16 + fcol) * 2;
                LDM_X4(ah[tm][0], ah[tm][1], ah[tm][2], ah[tm][3], st + G3_AH + off);
                LDM_X4(al[tm][0], al[tm][1], al[tm][2], al[tm][3], st + G3_AL + off);
            }
            #pragma unroll
            for (int p = 0; p < 2; p++) {
                uint32_t off = ((ks * 16 + frow) * GB_STR + wn * 32 + p * 16 + fcol) * 2;
                LDM_X4T(bh[p][0], bh[p][1], bh[p][2], bh[p][3], st + G3_BH + off);
                LDM_X4T(bl[p][0], bl[p][1], bl[p][2], bl[p][3], st + G3_BL + off);
            }
            #pragma unroll
            for (int tm = 0; tm < 4; tm++) {
                #pragma unroll
                for (int tn = 0; tn < 4; tn++) {
                    int p = tn >> 1, h2 = (tn & 1) * 2;
                    MMA16816(acc[tm][tn], ah[tm], bh[p][h2], bh[p][h2 + 1]);
                    MMA16816(acc[tm][tn], ah[tm], bl[p][h2], bl[p][h2 + 1]);
                    MMA16816(acc[tm][tn], al[tm], bh[p][h2], bh[p][h2 + 1]);
                }
            }
        }
        __syncthreads();
    }

    float* ob = out + (size_t)b * LL * CC;
    #pragma unroll
    for (int tm = 0; tm < 4; tm++) {
        int row = m0 + wm * 64 + tm * 16 + (lane >> 2);
        #pragma unroll
        for (int tn = 0; tn < 4; tn++) {
            int col = wn * 32 + tn * 8 + (lane & 3) * 2;
            atomicAdd(&ob[(size_t)row * CC + col],           acc[tm][tn][0]);
            atomicAdd(&ob[(size_t)row * CC + col + 1],       acc[tm][tn][1]);
            atomicAdd(&ob[(size_t)(row + 8) * CC + col],     acc[tm][tn][2]);
            atomicAdd(&ob[(size_t)(row + 8) * CC + col + 1], acc[tm][tn][3]);
        }
    }
}

// ---------------- launcher ----------------
extern "C" void kernel_launch(void* const* d_in, const int* in_sizes, int n_in,
                              void* d_out, int out_size) {
    const float* x1 = (const float*)d_in[0];
    const float* x2 = (const float*)d_in[1];
    float* out = (float*)d_out;

    cudaFuncSetAttribute(k_gemm3_mma, cudaFuncAttributeMaxDynamicSharedMemorySize, G3_SMEM);
    cudaFuncSetAttribute(k_scores, cudaFuncAttributeMaxDynamicSharedMemorySize, SD_SMEM);
    cudaFuncSetAttribute(k_dgemm, cudaFuncAttributeMaxDynamicSharedMemorySize, DG_SMEM);

    dim3 gx((AREA + 31) / 32, CC / 32, BN_);
    k_xt   <<<gx, dim3(32, 8)>>>(x2);
    k_split<<<(BN_ * LL * CC + 255) / 256, 256>>>(x1, out);
    k_rnorm<<<(BN_ * AREA * 32 + 255) / 256, 256>>>(x2);
    k_nm   <<<(BN_ * LL + 255) / 256, 256>>>();

    dim3 gd(NBLK * (NBLK + 1) / 2, 1, BN_);
    k_dgemm<<<gd, 256, DG_SMEM>>>();

    dim3 gsc(127, 4, BN_);
    k_scores<<<gsc, 256, SD_SMEM>>>();

    dim3 gsm(LL / SM_XB, BN_);
    k_softmax<<<gsm, 256>>>();

    dim3 gdh((LL / DH_XB) * 4, BN_);
    k_dh<<<gdh, 256>>>();
    k_dv<<<gdh, 256>>>();

    dim3 gg(LL / 128, 2, BN_);
    k_gemm3_mma<<<gg, 256, G3_SMEM>>>(out);
}